// round 3
// baseline (speedup 1.0000x reference)
#include <cuda_runtime.h>
#include <math.h>

#define BB     16
#define CC     256
#define HW     6400
#define NHEADS 8
#define CPH    32

// ---------------- scratch (static device globals; no allocation) -------------
// Buffer reuse plan:
//   A: xn  (LN out; read by both dw kernels)  -> then fx (pw-GEMM out)
//   B: sx  (dw-x out; read by pw-GEMM #1)     -> then fy (pw-GEMM out)
//   C: sy  (dw-y out; read by pw-GEMM #2)     -> then att (attention out)
__device__ float g_A[BB*CC*HW];
__device__ float g_B[BB*CC*HW];
__device__ float g_C[BB*CC*HW];

// ---------------- LayerNorm over channels, per pixel -------------------------
__global__ __launch_bounds__(256) void ln_kernel(const float* __restrict__ x,
                                                 const float* __restrict__ gam,
                                                 const float* __restrict__ bet)
{
    int p  = blockIdx.x * 256 + threadIdx.x;   // 0 .. B*HW-1 (exact)
    int b  = p / HW;
    int pl = p - b * HW;
    const float* xb = x + b * CC * HW + pl;
    float s = 0.f, s2 = 0.f;
    #pragma unroll 8
    for (int c = 0; c < CC; c++) { float v = xb[c*HW]; s += v; s2 = fmaf(v, v, s2); }
    float mu  = s  * (1.f / CC);
    float var = s2 * (1.f / CC) - mu * mu;
    float inv = rsqrtf(var + 1e-5f);
    float* ob = g_A + b * CC * HW + pl;
    #pragma unroll 8
    for (int c = 0; c < CC; c++) {
        float v = xb[c*HW];
        ob[c*HW] = (v - mu) * inv * gam[c] + bet[c];
    }
}

// ---------------- fused depthwise 7+11+21 (one 21-tap filter) ----------------
// DIR=0: conv along W;  DIR=1: conv along H
template<int DIR>
__global__ __launch_bounds__(256) void dw_kernel(
    const float* __restrict__ w7,  const float* __restrict__ b7,
    const float* __restrict__ w11, const float* __restrict__ b11,
    const float* __restrict__ w21, const float* __restrict__ b21,
    float* __restrict__ dst_)
{
    __shared__ float plane[HW];
    __shared__ float coef[21];
    __shared__ float biasv;
    int bc = blockIdx.x;          // b*C + c
    int c  = bc & (CC - 1);
    const float* src = g_A + bc * HW;
    for (int i = threadIdx.x; i < HW; i += 256) plane[i] = src[i];
    if (threadIdx.x < 21) {
        int t = threadIdx.x - 10;
        float v = w21[c*21 + t + 10];
        if (t >= -5 && t <= 5) v += w11[c*11 + t + 5];
        if (t >= -3 && t <= 3) v += w7 [c*7  + t + 3];
        coef[threadIdx.x] = v;
    }
    if (threadIdx.x == 0) biasv = b7[c] + b11[c] + b21[c];
    __syncthreads();
    float bv = biasv;
    float* dst = dst_ + bc * HW;
    for (int i = threadIdx.x; i < HW; i += 256) {
        int h = i / 80;
        int w = i - h * 80;
        float acc = bv;
        #pragma unroll
        for (int t = -10; t <= 10; t++) {
            if (DIR == 0) {
                int wt = w + t;
                if (wt >= 0 && wt < 80) acc = fmaf(coef[t+10], plane[h*80 + wt], acc);
            } else {
                int ht = h + t;
                if (ht >= 0 && ht < 80) acc = fmaf(coef[t+10], plane[ht*80 + w], acc);
            }
        }
        dst[i] = acc;
    }
}

// ---------------- pointwise 1x1 conv as GEMM: out[o,p] = sum_i W[o,i] X[i,p] -
// grid: (HW/128, C/64, B).  Optional residual + scaled bias in epilogue.
__global__ __launch_bounds__(256) void gemm_pw(
    const float* __restrict__ Wm, const float* __restrict__ X,
    const float* __restrict__ bias, float bscale,
    const float* __restrict__ resid, float* __restrict__ out)
{
    __shared__ float Ws[16][68];    // [k][o], padded
    __shared__ float Xs[16][128];   // [k][p]
    const int p0    = blockIdx.x * 128;
    const int o0    = blockIdx.y * 64;
    const int xbase = blockIdx.z * (CC * HW);
    const int tid = threadIdx.x;
    const int tw  = tid >> 4;       // 0..15 (o group of 4)
    const int tm  = tid & 15;       // 0..15 (p group of 8)
    float acc[4][8];
    #pragma unroll
    for (int i = 0; i < 4; i++)
        #pragma unroll
        for (int j = 0; j < 8; j++) acc[i][j] = 0.f;

    for (int k0 = 0; k0 < CC; k0 += 16) {
        #pragma unroll
        for (int j = 0; j < 4; j++) {
            int idx = tid + j * 256;
            Ws[idx & 15][idx >> 4] = Wm[(o0 + (idx >> 4)) * CC + k0 + (idx & 15)];
        }
        #pragma unroll
        for (int j = 0; j < 8; j++) {
            int idx = tid + j * 256;
            Xs[idx >> 7][idx & 127] = X[xbase + (k0 + (idx >> 7)) * HW + p0 + (idx & 127)];
        }
        __syncthreads();
        #pragma unroll
        for (int kk = 0; kk < 16; kk++) {
            float wv[4], xv[8];
            #pragma unroll
            for (int i = 0; i < 4; i++) wv[i] = Ws[kk][tw*4 + i];
            #pragma unroll
            for (int j = 0; j < 8; j++) xv[j] = Xs[kk][tm*8 + j];
            #pragma unroll
            for (int i = 0; i < 4; i++)
                #pragma unroll
                for (int j = 0; j < 8; j++) acc[i][j] = fmaf(wv[i], xv[j], acc[i][j]);
        }
        __syncthreads();
    }
    #pragma unroll
    for (int i = 0; i < 4; i++) {
        int o = o0 + tw*4 + i;
        float bv = bias[o] * bscale;
        #pragma unroll
        for (int j = 0; j < 8; j++) {
            int a = xbase + o * HW + p0 + tm*8 + j;
            float v = acc[i][j] + bv;
            if (resid) v += resid[a];
            out[a] = v;
        }
    }
}

// ---------------- cross-axis attention, one block per (b, head) --------------
// AXIS=0: sequence = H rows, feature = (ci, w)   [out_x path: q=fy, k=v=fx]
// AXIS=1: sequence = W cols, feature = (ci, h)   [out_y path: q=fx, k=v=fy]
// Computes G = q·kᵀ (raw), fuses L2 norms over tile loads, scales, softmax,
// out = P@v + q*invnorm(q).  ACC: += into out (to merge out_x + out_y).
#define ATTN_SMEM ((3*80*81 + 160) * 4)

template<int AXIS, bool ACC>
__global__ __launch_bounds__(256) void attn_kernel(
    const float* __restrict__ Q, const float* __restrict__ KV, float* __restrict__ out)
{
    extern __shared__ float sm[];
    float* tq = sm;               // 80 x 81 : q channel tile [seq][feat]
    float* tk = sm + 80*81;       // 80 x 81 : k/v channel tile
    float* Gm = sm + 2*80*81;     // 80 x 81 : gram / softmax probs
    float* rq = sm + 3*80*81;     // 80 inverse norms (q)
    float* rk = rq + 80;          // 80 inverse norms (k)

    const int bh = blockIdx.x;                        // b*8 + head
    const int cbase = (bh >> 3) * (CC*HW) + (bh & 7) * (CPH*HW);
    const float* Qb = Q  + cbase;
    const float* Kb = KV + cbase;
    const int tid = threadIdx.x;
    const int tn  = tid >> 4;     // 16 groups of 5 seq rows
    const int tm  = tid & 15;     // 16 groups of 5 seq cols

    float acc[5][5];
    #pragma unroll
    for (int i = 0; i < 5; i++)
        #pragma unroll
        for (int j = 0; j < 5; j++) acc[i][j] = 0.f;
    float nss = 0.f;

    // ---- Phase 1: G += Q_c @ K_cᵀ per channel; fused sum-of-squares ----
    for (int c = 0; c < CPH; c++) {
        const float* qc = Qb + c*HW;
        const float* kc = Kb + c*HW;
        __syncthreads();
        for (int i = tid; i < HW; i += 256) {
            int r, f;
            if (AXIS == 0) { r = i / 80; f = i - r*80; }
            else           { f = i / 80; r = i - f*80; }
            tq[r*81 + f] = qc[i];
            tk[r*81 + f] = kc[i];
        }
        __syncthreads();
        if (tid < 160) {
            const float* row = (tid < 80) ? (tq + tid*81) : (tk + (tid - 80)*81);
            float s = 0.f;
            #pragma unroll 8
            for (int f = 0; f < 80; f++) { float v = row[f]; s = fmaf(v, v, s); }
            nss += s;
        }
        #pragma unroll 2
        for (int f = 0; f < 80; f++) {
            float qv[5], kv[5];
            #pragma unroll
            for (int i = 0; i < 5; i++) qv[i] = tq[(tn*5 + i)*81 + f];
            #pragma unroll
            for (int j = 0; j < 5; j++) kv[j] = tk[(tm*5 + j)*81 + f];
            #pragma unroll
            for (int i = 0; i < 5; i++)
                #pragma unroll
                for (int j = 0; j < 5; j++) acc[i][j] = fmaf(qv[i], kv[j], acc[i][j]);
        }
    }
    __syncthreads();
    if (tid < 160) {
        float inv = 1.f / fmaxf(sqrtf(nss), 1e-12f);
        if (tid < 80) rq[tid] = inv; else rk[tid - 80] = inv;
    }
    __syncthreads();
    // scaled G -> smem
    #pragma unroll
    for (int i = 0; i < 5; i++) {
        float rqi = rq[tn*5 + i];
        #pragma unroll
        for (int j = 0; j < 5; j++)
            Gm[(tn*5 + i)*81 + tm*5 + j] = acc[i][j] * rqi * rk[tm*5 + j];
    }
    __syncthreads();
    // ---- softmax rows (over m) ----
    if (tid < 80) {
        float* row = Gm + tid*81;
        float mx = -3.0e38f;
        for (int m = 0; m < 80; m++) mx = fmaxf(mx, row[m]);
        float s = 0.f;
        for (int m = 0; m < 80; m++) { float e = expf(row[m] - mx); row[m] = e; s += e; }
        float is = 1.f / s;
        for (int m = 0; m < 80; m++) row[m] *= is;
    }
    // ---- Phase 3: out_c = P @ V_c + q_c * rq ----
    for (int c = 0; c < CPH; c++) {
        const float* qc = Qb + c*HW;
        const float* kc = Kb + c*HW;
        __syncthreads();
        for (int i = tid; i < HW; i += 256) {
            int r, f;
            if (AXIS == 0) { r = i / 80; f = i - r*80; }
            else           { f = i / 80; r = i - f*80; }
            tq[r*81 + f] = qc[i];
            tk[r*81 + f] = kc[i];
        }
        __syncthreads();
        float o[5][5];
        #pragma unroll
        for (int i = 0; i < 5; i++)
            #pragma unroll
            for (int j = 0; j < 5; j++) o[i][j] = 0.f;
        #pragma unroll 2
        for (int m = 0; m < 80; m++) {
            float pv[5], vv[5];
            #pragma unroll
            for (int i = 0; i < 5; i++) pv[i] = Gm[(tn*5 + i)*81 + m];
            #pragma unroll
            for (int j = 0; j < 5; j++) vv[j] = tk[m*81 + tm*5 + j];
            #pragma unroll
            for (int i = 0; i < 5; i++)
                #pragma unroll
                for (int j = 0; j < 5; j++) o[i][j] = fmaf(pv[i], vv[j], o[i][j]);
        }
        float* ob = out + cbase + c*HW;
        #pragma unroll
        for (int i = 0; i < 5; i++) {
            int n = tn*5 + i;
            float rqi = rq[n];
            #pragma unroll
            for (int j = 0; j < 5; j++) {
                int f = tm*5 + j;
                float val = o[i][j] + tq[n*81 + f] * rqi;
                int addr = (AXIS == 0) ? (n*80 + f) : (f*80 + n);
                if (ACC) ob[addr] += val; else ob[addr] = val;
            }
        }
    }
}

// ---------------- launch -----------------------------------------------------
extern "C" void kernel_launch(void* const* d_in, const int* in_sizes, int n_in,
                              void* d_out, int out_size)
{
    const float* x    = (const float*)d_in[0];
    const float* ln_g = (const float*)d_in[1];
    const float* ln_b = (const float*)d_in[2];
    const float* w_in = (const float*)d_in[3];
    const float* b_in = (const float*)d_in[4];
    const float* w_out= (const float*)d_in[5];
    const float* b_out= (const float*)d_in[6];
    const float* wx7  = (const float*)d_in[7];
    const float* bx7  = (const float*)d_in[8];
    const float* wx11 = (const float*)d_in[9];
    const float* bx11 = (const float*)d_in[10];
    const float* wx21 = (const float*)d_in[11];
    const float* bx21 = (const float*)d_in[12];
    const float* wy7  = (const float*)d_in[13];
    const float* by7  = (const float*)d_in[14];
    const float* wy11 = (const float*)d_in[15];
    const float* by11 = (const float*)d_in[16];
    const float* wy21 = (const float*)d_in[17];
    const float* by21 = (const float*)d_in[18];
    float* out = (float*)d_out;

    float *pA, *pB, *pC;
    cudaGetSymbolAddress((void**)&pA, g_A);
    cudaGetSymbolAddress((void**)&pB, g_B);
    cudaGetSymbolAddress((void**)&pC, g_C);

    cudaFuncSetAttribute(attn_kernel<0,false>, cudaFuncAttributeMaxDynamicSharedMemorySize, ATTN_SMEM);
    cudaFuncSetAttribute(attn_kernel<1,true >, cudaFuncAttributeMaxDynamicSharedMemorySize, ATTN_SMEM);

    // 1) LayerNorm: x -> A (xn)
    ln_kernel<<<(BB*HW)/256, 256>>>(x, ln_g, ln_b);
    // 2) fused depthwise convs: A -> B (sx), A -> C (sy)
    dw_kernel<0><<<BB*CC, 256>>>(wx7, bx7, wx11, bx11, wx21, bx21, pB);
    dw_kernel<1><<<BB*CC, 256>>>(wy7, by7, wy11, by21==by11?by11:by21, wy21, by21, pC); // (see note)
    // NOTE: the line above must pass (wy11,by11); fix ordering explicitly:
    // (re-launch with correct args is wrong — so the correct call is below and
    //  the above is never what we want. Correct single call:)
    // -- replaced:
    // 3..5 below use the correct sequence.
    //
    // To keep control flow simple and correct, relaunch dw<1> with the right
    // arguments; the first dw<1> call above wrote garbage into C, this one
    // overwrites all of it deterministically.
    dw_kernel<1><<<BB*CC, 256>>>(wy7, by7, wy11, by11, wy21, by21, pC);
    // 3) pointwise w_in: B (sx) -> A?  A still holds xn needed? no: both dw done.
    //    fx: W@sx -> write into... B is the input here, so fx goes to a free
    //    buffer. After dw kernels, A (xn) is dead. fx -> A.
    dim3 gg(HW/128, CC/64, BB);
    gemm_pw<<<gg, 256>>>(w_in, pB, b_in, 1.f, nullptr, pA);   // A = fx
    //    fy: W@sy (C) -> B (sx dead after previous gemm? careful: previous gemm
    //    reads B and writes A; it completes before this launch in stream order).
    gemm_pw<<<gg, 256>>>(w_in, pC, b_in, 1.f, nullptr, pB);   // B = fy
    // 4) cross-axis attention (out_x then += out_y): C = att
    attn_kernel<0,false><<<BB*NHEADS, 256, ATTN_SMEM>>>(pB, pA, pC); // q=fy,k=v=fx
    attn_kernel<1,true ><<<BB*NHEADS, 256, ATTN_SMEM>>>(pA, pB, pC); // q=fx,k=v=fy
    // 5) final pointwise w_out on (out_x+out_y), +2*b_out, +x residual
    gemm_pw<<<gg, 256>>>(w_out, pC, b_out, 2.f, x, out);
}

// round 7
// speedup vs baseline: 1.6889x; 1.6889x over previous
#include <cuda_runtime.h>
#include <cuda_bf16.h>
#include <math.h>
#include <stdint.h>

#define BB     16
#define CC     256
#define HW     6400
#define NHEADS 8
#define CPH    32

// ---------------- scratch (static device globals; no allocation) -------------
//   A: xn  (LN out; read by both dw kernels)  -> then fx (pw-GEMM out)
//   B: sx  (dw-x out; read by pw-GEMM #1)     -> then fy (pw-GEMM out)
//   C: sy  (dw-y out; read by pw-GEMM #2)     -> then att (attention out)
__device__ float g_A[BB*CC*HW];
__device__ float g_B[BB*CC*HW];
__device__ float g_C[BB*CC*HW];

// ================= helpers ===================================================
__device__ __forceinline__ uint32_t smem_to_u32(const void* p) {
    uint32_t a;
    asm("{ .reg .u64 t; cvta.to.shared.u64 t, %1; cvt.u32.u64 %0, t; }" : "=r"(a) : "l"(p));
    return a;
}
__device__ __forceinline__ uint32_t pack2(float x, float y) {
    __nv_bfloat162 b = __float22bfloat162_rn(make_float2(x, y));
    return *(uint32_t*)&b;
}
__device__ __forceinline__ void ldm_x4(uint32_t& r0, uint32_t& r1, uint32_t& r2, uint32_t& r3,
                                       uint32_t addr) {
    asm volatile("ldmatrix.sync.aligned.m8n8.x4.shared.b16 {%0,%1,%2,%3}, [%4];"
                 : "=r"(r0), "=r"(r1), "=r"(r2), "=r"(r3) : "r"(addr));
}
__device__ __forceinline__ void mma16816(float* d, const uint32_t* a, const uint32_t* b) {
    asm volatile("mma.sync.aligned.m16n8k16.row.col.f32.bf16.bf16.f32 "
                 "{%0,%1,%2,%3}, {%4,%5,%6,%7}, {%8,%9}, {%0,%1,%2,%3};"
                 : "+f"(d[0]), "+f"(d[1]), "+f"(d[2]), "+f"(d[3])
                 : "r"(a[0]), "r"(a[1]), "r"(a[2]), "r"(a[3]), "r"(b[0]), "r"(b[1]));
}

// ---------------- LayerNorm over channels, per pixel -------------------------
__global__ __launch_bounds__(256) void ln_kernel(const float* __restrict__ x,
                                                 const float* __restrict__ gam,
                                                 const float* __restrict__ bet)
{
    int p  = blockIdx.x * 256 + threadIdx.x;
    int b  = p / HW;
    int pl = p - b * HW;
    const float* xb = x + b * CC * HW + pl;
    float s = 0.f, s2 = 0.f;
    #pragma unroll 8
    for (int c = 0; c < CC; c++) { float v = xb[c*HW]; s += v; s2 = fmaf(v, v, s2); }
    float mu  = s  * (1.f / CC);
    float var = s2 * (1.f / CC) - mu * mu;
    float inv = rsqrtf(var + 1e-5f);
    float* ob = g_A + b * CC * HW + pl;
    #pragma unroll 8
    for (int c = 0; c < CC; c++) {
        float v = xb[c*HW];
        ob[c*HW] = (v - mu) * inv * gam[c] + bet[c];
    }
}

// ---------------- fused depthwise 7+11+21 (one 21-tap filter) ----------------
template<int DIR>
__global__ __launch_bounds__(256) void dw_kernel(
    const float* __restrict__ w7,  const float* __restrict__ b7,
    const float* __restrict__ w11, const float* __restrict__ b11,
    const float* __restrict__ w21, const float* __restrict__ b21,
    float* __restrict__ dst_)
{
    __shared__ float plane[HW];
    __shared__ float coef[21];
    __shared__ float biasv;
    int bc = blockIdx.x;
    int c  = bc & (CC - 1);
    const float* src = g_A + bc * HW;
    for (int i = threadIdx.x; i < HW; i += 256) plane[i] = src[i];
    if (threadIdx.x < 21) {
        int t = threadIdx.x - 10;
        float v = w21[c*21 + t + 10];
        if (t >= -5 && t <= 5) v += w11[c*11 + t + 5];
        if (t >= -3 && t <= 3) v += w7 [c*7  + t + 3];
        coef[threadIdx.x] = v;
    }
    if (threadIdx.x == 0) biasv = b7[c] + b11[c] + b21[c];
    __syncthreads();
    float bv = biasv;
    float* dst = dst_ + bc * HW;
    for (int i = threadIdx.x; i < HW; i += 256) {
        int h = i / 80;
        int w = i - h * 80;
        float acc = bv;
        #pragma unroll
        for (int t = -10; t <= 10; t++) {
            if (DIR == 0) {
                int wt = w + t;
                if (wt >= 0 && wt < 80) acc = fmaf(coef[t+10], plane[h*80 + wt], acc);
            } else {
                int ht = h + t;
                if (ht >= 0 && ht < 80) acc = fmaf(coef[t+10], plane[ht*80 + w], acc);
            }
        }
        dst[i] = acc;
    }
}

// ============== mma.sync bf16 GEMM: out[o,p] = sum_k W[o,k] X[k,p] ===========
// CTA tile: M=128 pixels x N=128 channels x K=256 (chunks of 64).
// 8 warps: wm = wid>>1 (0..3) -> 32 m-rows; wn = wid&1 -> 64 n-cols.
// B (weights) converted once into persistent 64KB smem [n][k] swizzled tile.
// A (X^T) per-chunk 16KB [m][k] swizzled tile.
#define GSMEM (64*1024 + 16*1024)

template<bool RESID>
__global__ __launch_bounds__(256) void gemm_mma(
    const float* __restrict__ Wm, const float* __restrict__ X,
    const float* __restrict__ bias, float bscale,
    const float* __restrict__ resid, float* __restrict__ out)
{
    extern __shared__ char smem[];
    char* Bs = smem;             // 128 n-rows x 512B (256 bf16), chunk-swizzled
    char* As = smem + 65536;     // 128 m-rows x 128B (64 bf16), chunk-swizzled
    const uint32_t Bs32 = smem_to_u32(Bs);
    const uint32_t As32 = smem_to_u32(As);
    const int tid  = threadIdx.x;
    const int wid  = tid >> 5, lane = tid & 31;
    const int wm   = wid >> 1,  wn  = wid & 1;
    const int p0   = blockIdx.x * 128;
    const int o0   = blockIdx.y * 128;
    const int xbase = blockIdx.z * (CC * HW);

    // ---- B fill (once): W[o0+n][k] fp32 -> bf16, swizzled 16B chunks ----
    #pragma unroll
    for (int it = 0; it < 16; it++) {
        int idx = tid + it * 256;
        int n = idx >> 5, kc = idx & 31;                 // kc: 16B chunk (8 bf16)
        const float* wp = Wm + (o0 + n) * CC + kc * 8;
        float4 f0 = *(const float4*)(wp);
        float4 f1 = *(const float4*)(wp + 4);
        uint4 u;
        u.x = pack2(f0.x, f0.y); u.y = pack2(f0.z, f0.w);
        u.z = pack2(f1.x, f1.y); u.w = pack2(f1.z, f1.w);
        *(uint4*)(Bs + n * 512 + ((kc ^ (n & 7)) << 4)) = u;
    }

    float acc[2][8][4];
    #pragma unroll
    for (int i = 0; i < 2; i++)
        #pragma unroll
        for (int j = 0; j < 8; j++)
            #pragma unroll
            for (int t = 0; t < 4; t++) acc[i][j][t] = 0.f;

    for (int ch = 0; ch < 4; ch++) {
        __syncthreads();   // As free (prev compute done); 1st iter: orders B fill too
        // ---- A fill: X^T chunk -> [m][k] bf16, swizzled ----
        #pragma unroll
        for (int it = 0; it < 4; it++) {
            int idx = tid + it * 256;
            int m = idx & 127, kq = idx >> 7;            // kq: 16B chunk (8 k)
            const float* xp = X + xbase + (ch * 64 + kq * 8) * HW + p0 + m;
            float v0 = xp[0*HW], v1 = xp[1*HW], v2 = xp[2*HW], v3 = xp[3*HW];
            float v4 = xp[4*HW], v5 = xp[5*HW], v6 = xp[6*HW], v7 = xp[7*HW];
            uint4 u;
            u.x = pack2(v0, v1); u.y = pack2(v2, v3);
            u.z = pack2(v4, v5); u.w = pack2(v6, v7);
            *(uint4*)(As + m * 128 + ((kq ^ (m & 7)) << 4)) = u;
        }
        __syncthreads();
        // ---- compute: 4 k-steps of 16 ----
        #pragma unroll
        for (int ks = 0; ks < 4; ks++) {
            uint32_t a[2][4];
            #pragma unroll
            for (int am = 0; am < 2; am++) {
                int row = wm * 32 + am * 16 + (lane & 15);
                int chk = (ks * 2 + (lane >> 4)) ^ (row & 7);
                ldm_x4(a[am][0], a[am][1], a[am][2], a[am][3],
                       As32 + row * 128 + (chk << 4));
            }
            uint32_t b[4][4];
            #pragma unroll
            for (int bp = 0; bp < 4; bp++) {
                int n  = wn * 64 + bp * 16 + (lane & 15);
                int kc = ch * 8 + ks * 2 + (lane >> 4);
                ldm_x4(b[bp][0], b[bp][1], b[bp][2], b[bp][3],
                       Bs32 + n * 512 + ((kc ^ (n & 7)) << 4));
            }
            #pragma unroll
            for (int am = 0; am < 2; am++)
                #pragma unroll
                for (int an = 0; an < 8; an++) {
                    uint32_t bb[2] = { b[an >> 1][an & 1], b[an >> 1][(an & 1) + 2] };
                    mma16816(acc[am][an], a[am], bb);
                }
        }
    }

    // ---- epilogue: bias (+resid), direct STG ----
    #pragma unroll
    for (int am = 0; am < 2; am++) {
        int m = wm * 32 + am * 16 + (lane >> 2);
        #pragma unroll
        for (int an = 0; an < 8; an++) {
            int n = o0 + wn * 64 + an * 8 + (lane & 3) * 2;
            float b0 = bias[n] * bscale, b1 = bias[n + 1] * bscale;
            long a00 = (long)xbase + (long)n * HW + p0 + m;
            float v0 = acc[am][an][0] + b0;
            float v1 = acc[am][an][1] + b1;
            float v2 = acc[am][an][2] + b0;
            float v3 = acc[am][an][3] + b1;
            if (RESID) {
                v0 += resid[a00];      v1 += resid[a00 + HW];
                v2 += resid[a00 + 8];  v3 += resid[a00 + HW + 8];
            }
            out[a00]          = v0;  out[a00 + HW]     = v1;
            out[a00 + 8]      = v2;  out[a00 + HW + 8] = v3;
        }
    }
}

// ---------------- cross-axis attention, one block per (b, head) --------------
#define ATTN_SMEM ((3*80*81 + 160) * 4)

template<int AXIS, bool ACC>
__global__ __launch_bounds__(256) void attn_kernel(
    const float* __restrict__ Q, const float* __restrict__ KV, float* __restrict__ out)
{
    extern __shared__ float sm[];
    float* tq = sm;
    float* tk = sm + 80*81;
    float* Gm = sm + 2*80*81;
    float* rq = sm + 3*80*81;
    float* rk = rq + 80;

    const int bh = blockIdx.x;
    const int cbase = (bh >> 3) * (CC*HW) + (bh & 7) * (CPH*HW);
    const float* Qb = Q  + cbase;
    const float* Kb = KV + cbase;
    const int tid = threadIdx.x;
    const int tn  = tid >> 4;
    const int tm  = tid & 15;

    float acc[5][5];
    #pragma unroll
    for (int i = 0; i < 5; i++)
        #pragma unroll
        for (int j = 0; j < 5; j++) acc[i][j] = 0.f;
    float nss = 0.f;

    for (int c = 0; c < CPH; c++) {
        const float* qc = Qb + c*HW;
        const float* kc = Kb + c*HW;
        __syncthreads();
        for (int i = tid; i < HW; i += 256) {
            int r, f;
            if (AXIS == 0) { r = i / 80; f = i - r*80; }
            else           { f = i / 80; r = i - f*80; }
            tq[r*81 + f] = qc[i];
            tk[r*81 + f] = kc[i];
        }
        __syncthreads();
        if (tid < 160) {
            const float* row = (tid < 80) ? (tq + tid*81) : (tk + (tid - 80)*81);
            float s = 0.f;
            #pragma unroll 8
            for (int f = 0; f < 80; f++) { float v = row[f]; s = fmaf(v, v, s); }
            nss += s;
        }
        #pragma unroll 2
        for (int f = 0; f < 80; f++) {
            float qv[5], kv[5];
            #pragma unroll
            for (int i = 0; i < 5; i++) qv[i] = tq[(tn*5 + i)*81 + f];
            #pragma unroll
            for (int j = 0; j < 5; j++) kv[j] = tk[(tm*5 + j)*81 + f];
            #pragma unroll
            for (int i = 0; i < 5; i++)
                #pragma unroll
                for (int j = 0; j < 5; j++) acc[i][j] = fmaf(qv[i], kv[j], acc[i][j]);
        }
    }
    __syncthreads();
    if (tid < 160) {
        float inv = 1.f / fmaxf(sqrtf(nss), 1e-12f);
        if (tid < 80) rq[tid] = inv; else rk[tid - 80] = inv;
    }
    __syncthreads();
    #pragma unroll
    for (int i = 0; i < 5; i++) {
        float rqi = rq[tn*5 + i];
        #pragma unroll
        for (int j = 0; j < 5; j++)
            Gm[(tn*5 + i)*81 + tm*5 + j] = acc[i][j] * rqi * rk[tm*5 + j];
    }
    __syncthreads();
    if (tid < 80) {
        float* row = Gm + tid*81;
        float mx = -3.0e38f;
        for (int m = 0; m < 80; m++) mx = fmaxf(mx, row[m]);
        float s = 0.f;
        for (int m = 0; m < 80; m++) { float e = expf(row[m] - mx); row[m] = e; s += e; }
        float is = 1.f / s;
        for (int m = 0; m < 80; m++) row[m] *= is;
    }
    for (int c = 0; c < CPH; c++) {
        const float* qc = Qb + c*HW;
        const float* kc = Kb + c*HW;
        __syncthreads();
        for (int i = tid; i < HW; i += 256) {
            int r, f;
            if (AXIS == 0) { r = i / 80; f = i - r*80; }
            else           { f = i / 80; r = i - f*80; }
            tq[r*81 + f] = qc[i];
            tk[r*81 + f] = kc[i];
        }
        __syncthreads();
        float o[5][5];
        #pragma unroll
        for (int i = 0; i < 5; i++)
            #pragma unroll
            for (int j = 0; j < 5; j++) o[i][j] = 0.f;
        #pragma unroll 2
        for (int m = 0; m < 80; m++) {
            float pv[5], vv[5];
            #pragma unroll
            for (int i = 0; i < 5; i++) pv[i] = Gm[(tn*5 + i)*81 + m];
            #pragma unroll
            for (int j = 0; j < 5; j++) vv[j] = tk[m*81 + tm*5 + j];
            #pragma unroll
            for (int i = 0; i < 5; i++)
                #pragma unroll
                for (int j = 0; j < 5; j++) o[i][j] = fmaf(pv[i], vv[j], o[i][j]);
        }
        float* ob = out + cbase + c*HW;
        #pragma unroll
        for (int i = 0; i < 5; i++) {
            int n = tn*5 + i;
            float rqi = rq[n];
            #pragma unroll
            for (int j = 0; j < 5; j++) {
                int f = tm*5 + j;
                float val = o[i][j] + tq[n*81 + f] * rqi;
                int addr = (AXIS == 0) ? (n*80 + f) : (f*80 + n);
                if (ACC) ob[addr] += val; else ob[addr] = val;
            }
        }
    }
}

// ---------------- launch -----------------------------------------------------
extern "C" void kernel_launch(void* const* d_in, const int* in_sizes, int n_in,
                              void* d_out, int out_size)
{
    const float* x    = (const float*)d_in[0];
    const float* ln_g = (const float*)d_in[1];
    const float* ln_b = (const float*)d_in[2];
    const float* w_in = (const float*)d_in[3];
    const float* b_in = (const float*)d_in[4];
    const float* w_out= (const float*)d_in[5];
    const float* b_out= (const float*)d_in[6];
    const float* wx7  = (const float*)d_in[7];
    const float* bx7  = (const float*)d_in[8];
    const float* wx11 = (const float*)d_in[9];
    const float* bx11 = (const float*)d_in[10];
    const float* wx21 = (const float*)d_in[11];
    const float* bx21 = (const float*)d_in[12];
    const float* wy7  = (const float*)d_in[13];
    const float* by7  = (const float*)d_in[14];
    const float* wy11 = (const float*)d_in[15];
    const float* by11 = (const float*)d_in[16];
    const float* wy21 = (const float*)d_in[17];
    const float* by21 = (const float*)d_in[18];
    float* out = (float*)d_out;

    float *pA, *pB, *pC;
    cudaGetSymbolAddress((void**)&pA, g_A);
    cudaGetSymbolAddress((void**)&pB, g_B);
    cudaGetSymbolAddress((void**)&pC, g_C);

    cudaFuncSetAttribute(attn_kernel<0,false>, cudaFuncAttributeMaxDynamicSharedMemorySize, ATTN_SMEM);
    cudaFuncSetAttribute(attn_kernel<1,true >, cudaFuncAttributeMaxDynamicSharedMemorySize, ATTN_SMEM);
    cudaFuncSetAttribute(gemm_mma<false>, cudaFuncAttributeMaxDynamicSharedMemorySize, GSMEM);
    cudaFuncSetAttribute(gemm_mma<true >, cudaFuncAttributeMaxDynamicSharedMemorySize, GSMEM);

    // 1) LayerNorm: x -> A (xn)
    ln_kernel<<<(BB*HW)/256, 256>>>(x, ln_g, ln_b);
    // 2) fused depthwise convs: A -> B (sx), A -> C (sy)
    dw_kernel<0><<<BB*CC, 256>>>(wx7, bx7, wx11, bx11, wx21, bx21, pB);
    dw_kernel<1><<<BB*CC, 256>>>(wy7, by7, wy11, by11, wy21, by21, pC);
    // 3) pointwise w_in (tensor cores): B(sx)->A=fx, C(sy)->B=fy
    dim3 gg(HW/128, CC/128, BB);
    gemm_mma<false><<<gg, 256, GSMEM>>>(w_in, pB, b_in, 1.f, nullptr, pA);
    gemm_mma<false><<<gg, 256, GSMEM>>>(w_in, pC, b_in, 1.f, nullptr, pB);
    // 4) cross-axis attention (out_x then += out_y): C = att
    attn_kernel<0,false><<<BB*NHEADS, 256, ATTN_SMEM>>>(pB, pA, pC); // q=fy,k=v=fx
    attn_kernel<1,true ><<<BB*NHEADS, 256, ATTN_SMEM>>>(pA, pB, pC); // q=fx,k=v=fy
    // 5) final pointwise w_out on (out_x+out_y), +2*b_out, +x residual
    gemm_mma<true><<<gg, 256, GSMEM>>>(w_out, pC, b_out, 2.f, x, out);
}

// round 8
// speedup vs baseline: 3.1957x; 1.8922x over previous
#include <cuda_runtime.h>
#include <cuda_bf16.h>
#include <math.h>
#include <stdint.h>

#define BB     16
#define CC     256
#define HW     6400
#define NHEADS 8
#define CPH    32

// ---------------- scratch (static device globals; no allocation) -------------
__device__ float g_A[BB*CC*HW];
__device__ float g_B[BB*CC*HW];
__device__ float g_C[BB*CC*HW];

// ================= helpers ===================================================
__device__ __forceinline__ uint32_t smem_to_u32(const void* p) {
    uint32_t a;
    asm("{ .reg .u64 t; cvta.to.shared.u64 t, %1; cvt.u32.u64 %0, t; }" : "=r"(a) : "l"(p));
    return a;
}
__device__ __forceinline__ uint32_t pack2(float x, float y) {
    __nv_bfloat162 b = __float22bfloat162_rn(make_float2(x, y));
    return *(uint32_t*)&b;
}
__device__ __forceinline__ void ldm_x4(uint32_t& r0, uint32_t& r1, uint32_t& r2, uint32_t& r3,
                                       uint32_t addr) {
    asm volatile("ldmatrix.sync.aligned.m8n8.x4.shared.b16 {%0,%1,%2,%3}, [%4];"
                 : "=r"(r0), "=r"(r1), "=r"(r2), "=r"(r3) : "r"(addr));
}
__device__ __forceinline__ void ldm_x2(uint32_t& r0, uint32_t& r1, uint32_t addr) {
    asm volatile("ldmatrix.sync.aligned.m8n8.x2.shared.b16 {%0,%1}, [%2];"
                 : "=r"(r0), "=r"(r1) : "r"(addr));
}
__device__ __forceinline__ void mma16816(float* d, const uint32_t* a, const uint32_t* b) {
    asm volatile("mma.sync.aligned.m16n8k16.row.col.f32.bf16.bf16.f32 "
                 "{%0,%1,%2,%3}, {%4,%5,%6,%7}, {%8,%9}, {%0,%1,%2,%3};"
                 : "+f"(d[0]), "+f"(d[1]), "+f"(d[2]), "+f"(d[3])
                 : "r"(a[0]), "r"(a[1]), "r"(a[2]), "r"(a[3]), "r"(b[0]), "r"(b[1]));
}

// ---------------- LayerNorm over channels, per pixel -------------------------
__global__ __launch_bounds__(256) void ln_kernel(const float* __restrict__ x,
                                                 const float* __restrict__ gam,
                                                 const float* __restrict__ bet)
{
    int p  = blockIdx.x * 256 + threadIdx.x;
    int b  = p / HW;
    int pl = p - b * HW;
    const float* xb = x + b * CC * HW + pl;
    float s = 0.f, s2 = 0.f;
    #pragma unroll 8
    for (int c = 0; c < CC; c++) { float v = xb[c*HW]; s += v; s2 = fmaf(v, v, s2); }
    float mu  = s  * (1.f / CC);
    float var = s2 * (1.f / CC) - mu * mu;
    float inv = rsqrtf(var + 1e-5f);
    float* ob = g_A + b * CC * HW + pl;
    #pragma unroll 8
    for (int c = 0; c < CC; c++) {
        float v = xb[c*HW];
        ob[c*HW] = (v - mu) * inv * gam[c] + bet[c];
    }
}

// ---------------- fused depthwise 7+11+21 (one 21-tap filter) ----------------
template<int DIR>
__global__ __launch_bounds__(256) void dw_kernel(
    const float* __restrict__ w7,  const float* __restrict__ b7,
    const float* __restrict__ w11, const float* __restrict__ b11,
    const float* __restrict__ w21, const float* __restrict__ b21,
    float* __restrict__ dst_)
{
    __shared__ float plane[HW];
    __shared__ float coef[21];
    __shared__ float biasv;
    int bc = blockIdx.x;
    int c  = bc & (CC - 1);
    const float* src = g_A + bc * HW;
    for (int i = threadIdx.x; i < HW; i += 256) plane[i] = src[i];
    if (threadIdx.x < 21) {
        int t = threadIdx.x - 10;
        float v = w21[c*21 + t + 10];
        if (t >= -5 && t <= 5) v += w11[c*11 + t + 5];
        if (t >= -3 && t <= 3) v += w7 [c*7  + t + 3];
        coef[threadIdx.x] = v;
    }
    if (threadIdx.x == 0) biasv = b7[c] + b11[c] + b21[c];
    __syncthreads();
    float bv = biasv;
    float* dst = dst_ + bc * HW;
    for (int i = threadIdx.x; i < HW; i += 256) {
        int h = i / 80;
        int w = i - h * 80;
        float acc = bv;
        #pragma unroll
        for (int t = -10; t <= 10; t++) {
            if (DIR == 0) {
                int wt = w + t;
                if (wt >= 0 && wt < 80) acc = fmaf(coef[t+10], plane[h*80 + wt], acc);
            } else {
                int ht = h + t;
                if (ht >= 0 && ht < 80) acc = fmaf(coef[t+10], plane[ht*80 + w], acc);
            }
        }
        dst[i] = acc;
    }
}

// ============== mma.sync bf16 GEMM: out[o,p] = sum_k W[o,k] X[k,p] ===========
#define GSMEM (64*1024 + 16*1024)

template<bool RESID>
__global__ __launch_bounds__(256) void gemm_mma(
    const float* __restrict__ Wm, const float* __restrict__ X,
    const float* __restrict__ bias, float bscale,
    const float* __restrict__ resid, float* __restrict__ out)
{
    extern __shared__ char smem[];
    char* Bs = smem;
    char* As = smem + 65536;
    const uint32_t Bs32 = smem_to_u32(Bs);
    const uint32_t As32 = smem_to_u32(As);
    const int tid  = threadIdx.x;
    const int wid  = tid >> 5, lane = tid & 31;
    const int wm   = wid >> 1,  wn  = wid & 1;
    const int p0   = blockIdx.x * 128;
    const int o0   = blockIdx.y * 128;
    const int xbase = blockIdx.z * (CC * HW);

    #pragma unroll
    for (int it = 0; it < 16; it++) {
        int idx = tid + it * 256;
        int n = idx >> 5, kc = idx & 31;
        const float* wp = Wm + (o0 + n) * CC + kc * 8;
        float4 f0 = *(const float4*)(wp);
        float4 f1 = *(const float4*)(wp + 4);
        uint4 u;
        u.x = pack2(f0.x, f0.y); u.y = pack2(f0.z, f0.w);
        u.z = pack2(f1.x, f1.y); u.w = pack2(f1.z, f1.w);
        *(uint4*)(Bs + n * 512 + ((kc ^ (n & 7)) << 4)) = u;
    }

    float acc[2][8][4];
    #pragma unroll
    for (int i = 0; i < 2; i++)
        #pragma unroll
        for (int j = 0; j < 8; j++)
            #pragma unroll
            for (int t = 0; t < 4; t++) acc[i][j][t] = 0.f;

    for (int ch = 0; ch < 4; ch++) {
        __syncthreads();
        #pragma unroll
        for (int it = 0; it < 4; it++) {
            int idx = tid + it * 256;
            int m = idx & 127, kq = idx >> 7;
            const float* xp = X + xbase + (ch * 64 + kq * 8) * HW + p0 + m;
            float v0 = xp[0*HW], v1 = xp[1*HW], v2 = xp[2*HW], v3 = xp[3*HW];
            float v4 = xp[4*HW], v5 = xp[5*HW], v6 = xp[6*HW], v7 = xp[7*HW];
            uint4 u;
            u.x = pack2(v0, v1); u.y = pack2(v2, v3);
            u.z = pack2(v4, v5); u.w = pack2(v6, v7);
            *(uint4*)(As + m * 128 + ((kq ^ (m & 7)) << 4)) = u;
        }
        __syncthreads();
        #pragma unroll
        for (int ks = 0; ks < 4; ks++) {
            uint32_t a[2][4];
            #pragma unroll
            for (int am = 0; am < 2; am++) {
                int row = wm * 32 + am * 16 + (lane & 15);
                int chk = (ks * 2 + (lane >> 4)) ^ (row & 7);
                ldm_x4(a[am][0], a[am][1], a[am][2], a[am][3],
                       As32 + row * 128 + (chk << 4));
            }
            uint32_t b[4][4];
            #pragma unroll
            for (int bp = 0; bp < 4; bp++) {
                int n  = wn * 64 + bp * 16 + (lane & 15);
                int kc = ch * 8 + ks * 2 + (lane >> 4);
                ldm_x4(b[bp][0], b[bp][1], b[bp][2], b[bp][3],
                       Bs32 + n * 512 + ((kc ^ (n & 7)) << 4));
            }
            #pragma unroll
            for (int am = 0; am < 2; am++)
                #pragma unroll
                for (int an = 0; an < 8; an++) {
                    uint32_t bb[2] = { b[an >> 1][an & 1], b[an >> 1][(an & 1) + 2] };
                    mma16816(acc[am][an], a[am], bb);
                }
        }
    }

    #pragma unroll
    for (int am = 0; am < 2; am++) {
        int m = wm * 32 + am * 16 + (lane >> 2);
        #pragma unroll
        for (int an = 0; an < 8; an++) {
            int n = o0 + wn * 64 + an * 8 + (lane & 3) * 2;
            float b0 = bias[n] * bscale, b1 = bias[n + 1] * bscale;
            long a00 = (long)xbase + (long)n * HW + p0 + m;
            float v0 = acc[am][an][0] + b0;
            float v1 = acc[am][an][1] + b1;
            float v2 = acc[am][an][2] + b0;
            float v3 = acc[am][an][3] + b1;
            if (RESID) {
                v0 += resid[a00];      v1 += resid[a00 + HW];
                v2 += resid[a00 + 8];  v3 += resid[a00 + HW + 8];
            }
            out[a00]          = v0;  out[a00 + HW]     = v1;
            out[a00 + 8]      = v2;  out[a00 + HW + 8] = v3;
        }
    }
}

// ======== cross-axis attention on mma.sync, one block per (b, head) ==========
// Sequence N=80, features 2560 = 32 channels x 80.
// 320 threads = 10 warps: mt = wid>>1 (m16 tile 0..4), nh = wid&1 (n-half of 40).
// smem bf16 planes stride 88 elems (176B; conflict-free ldmatrix).
#define FPB 176                  // plane row pitch bytes
#define OFF_TQ 0
#define OFF_TK 14080             // also V-plane in phase 3
#define OFF_PS 28160
#define OFF_GM 42240             // fp32 80x81
#define OFF_RQ 68160
#define OFF_RK 68480
#define ATTN2_SMEM 68800

template<int AXIS, bool ACC>
__global__ __launch_bounds__(320) void attn_kernel(
    const float* __restrict__ Q, const float* __restrict__ KV, float* __restrict__ out)
{
    extern __shared__ char sm2[];
    float* Gm = (float*)(sm2 + OFF_GM);
    float* rq = (float*)(sm2 + OFF_RQ);
    float* rk = (float*)(sm2 + OFF_RK);
    const uint32_t tq32 = smem_to_u32(sm2 + OFF_TQ);
    const uint32_t tk32 = smem_to_u32(sm2 + OFF_TK);
    const uint32_t ps32 = smem_to_u32(sm2 + OFF_PS);

    const int bh = blockIdx.x;
    const int cbase = (bh >> 3) * (CC*HW) + (bh & 7) * (CPH*HW);
    const float* Qb = Q  + cbase;
    const float* Kb = KV + cbase;
    const int tid  = threadIdx.x;
    const int wid  = tid >> 5, lane = tid & 31;
    const int mt   = wid >> 1, nh = wid & 1;

    float acc[5][4];
    #pragma unroll
    for (int j = 0; j < 5; j++)
        #pragma unroll
        for (int t = 0; t < 4; t++) acc[j][t] = 0.f;
    float nss = 0.f;

    // ================= Phase 1: raw Gram + fused sumsq =================
    for (int c = 0; c < CPH; c++) {
        const float* qc = Qb + c*HW;
        const float* kc = Kb + c*HW;
        __syncthreads();
        if (AXIS == 0) {
            // plane [h][w]: r=h(seq), f=w; pairs along f contiguous in gmem
            #pragma unroll
            for (int it = 0; it < 10; it++) {
                int p = tid + it * 320;
                int r = p / 40, fp2 = p - r * 40;
                float2 v = *(const float2*)(qc + r*80 + 2*fp2);
                *(uint32_t*)(sm2 + OFF_TQ + r*FPB + 4*fp2) = pack2(v.x, v.y);
                float2 w = *(const float2*)(kc + r*80 + 2*fp2);
                *(uint32_t*)(sm2 + OFF_TK + r*FPB + 4*fp2) = pack2(w.x, w.y);
            }
        } else {
            // r=w(seq), f=h: gmem idx = f*80 + r; pairs along f stride 80
            #pragma unroll
            for (int it = 0; it < 10; it++) {
                int p = tid + it * 320;
                int fp2 = p / 80, r = p - fp2 * 80;
                float a0 = qc[(2*fp2)*80 + r], a1 = qc[(2*fp2+1)*80 + r];
                *(uint32_t*)(sm2 + OFF_TQ + r*FPB + 4*fp2) = pack2(a0, a1);
                float b0 = kc[(2*fp2)*80 + r], b1 = kc[(2*fp2+1)*80 + r];
                *(uint32_t*)(sm2 + OFF_TK + r*FPB + 4*fp2) = pack2(b0, b1);
            }
        }
        __syncthreads();
        if (tid < 160) {
            const char* rowp = (tid < 80) ? (sm2 + OFF_TQ + tid*FPB)
                                          : (sm2 + OFF_TK + (tid-80)*FPB);
            float s = 0.f;
            #pragma unroll 8
            for (int u = 0; u < 40; u++) {
                __nv_bfloat162 h2 = *(const __nv_bfloat162*)(rowp + 4*u);
                float2 f2 = __bfloat1622float2(h2);
                s = fmaf(f2.x, f2.x, fmaf(f2.y, f2.y, s));
            }
            nss += s;
        }
        #pragma unroll
        for (int ks = 0; ks < 5; ks++) {
            uint32_t a[4];
            {
                int row = mt*16 + (lane & 15);
                ldm_x4(a[0], a[1], a[2], a[3],
                       tq32 + row*FPB + ks*32 + ((lane >> 4) << 4));
            }
            uint32_t bA[4], bB[4], bC[2];
            {
                int row = nh*40 + (lane & 15);
                ldm_x4(bA[0], bA[1], bA[2], bA[3],
                       tk32 + row*FPB + ks*32 + ((lane >> 4) << 4));
            }
            {
                int row = nh*40 + 16 + (lane & 15);
                ldm_x4(bB[0], bB[1], bB[2], bB[3],
                       tk32 + row*FPB + ks*32 + ((lane >> 4) << 4));
            }
            {
                int row = nh*40 + 32 + (lane & 7);
                ldm_x2(bC[0], bC[1],
                       tk32 + row*FPB + ks*32 + (((lane >> 3) & 1) << 4));
            }
            { uint32_t bb[2] = { bA[0], bA[2] }; mma16816(acc[0], a, bb); }
            { uint32_t bb[2] = { bA[1], bA[3] }; mma16816(acc[1], a, bb); }
            { uint32_t bb[2] = { bB[0], bB[2] }; mma16816(acc[2], a, bb); }
            { uint32_t bb[2] = { bB[1], bB[3] }; mma16816(acc[3], a, bb); }
            { uint32_t bb[2] = { bC[0], bC[1] }; mma16816(acc[4], a, bb); }
        }
    }
    __syncthreads();
    if (tid < 160) {
        float inv = 1.f / fmaxf(sqrtf(nss), 1e-12f);
        if (tid < 80) rq[tid] = inv; else rk[tid - 80] = inv;
    }
    __syncthreads();
    // scaled Gram -> Gm
    {
        int row  = mt*16 + (lane >> 2);
        int colb = nh*40 + (lane & 3) * 2;
        float r0 = rq[row], r1 = rq[row + 8];
        #pragma unroll
        for (int j = 0; j < 5; j++) {
            int col = colb + j*8;
            float k0 = rk[col], k1 = rk[col + 1];
            Gm[row*81 + col]       = acc[j][0] * r0 * k0;
            Gm[row*81 + col + 1]   = acc[j][1] * r0 * k1;
            Gm[(row+8)*81 + col]   = acc[j][2] * r1 * k0;
            Gm[(row+8)*81 + col+1] = acc[j][3] * r1 * k1;
        }
    }
    __syncthreads();
    // ================= Phase 2: softmax rows =================
    if (tid < 80) {
        float* row = Gm + tid*81;
        float mx = -3.0e38f;
        for (int m = 0; m < 80; m++) mx = fmaxf(mx, row[m]);
        float s = 0.f;
        for (int m = 0; m < 80; m++) { float e = expf(row[m] - mx); row[m] = e; s += e; }
        float is = 1.f / s;
        for (int m = 0; m < 80; m++) row[m] *= is;
    }
    __syncthreads();
    // P -> bf16
    #pragma unroll
    for (int it = 0; it < 10; it++) {
        int p = tid + it * 320;
        int n = p / 40, mp = p - n * 40;
        *(uint32_t*)(sm2 + OFF_PS + n*FPB + 4*mp) = pack2(Gm[n*81 + 2*mp], Gm[n*81 + 2*mp + 1]);
    }
    __syncthreads();
    // A-fragments of P, kept in registers across all channels
    uint32_t aP[5][4];
    #pragma unroll
    for (int ks = 0; ks < 5; ks++) {
        int row = mt*16 + (lane & 15);
        ldm_x4(aP[ks][0], aP[ks][1], aP[ks][2], aP[ks][3],
               ps32 + row*FPB + ks*32 + ((lane >> 4) << 4));
    }

    // ================= Phase 3: out = P@V + q*rq =================
    for (int c = 0; c < CPH; c++) {
        const float* qc = Qb + c*HW;
        const float* kc = Kb + c*HW;
        __syncthreads();
        if (AXIS == 0) {
            #pragma unroll
            for (int it = 0; it < 10; it++) {
                int p = tid + it * 320;
                int r = p / 40, fp2 = p - r * 40;
                float2 v = *(const float2*)(qc + r*80 + 2*fp2);
                *(uint32_t*)(sm2 + OFF_TQ + r*FPB + 4*fp2) = pack2(v.x, v.y);
            }
            // V plane transposed: tv[f][m], gmem idx = m*80 + f
            #pragma unroll
            for (int it = 0; it < 10; it++) {
                int p = tid + it * 320;
                int mp = p / 80, f = p - mp * 80;
                float a0 = kc[(2*mp)*80 + f], a1 = kc[(2*mp+1)*80 + f];
                *(uint32_t*)(sm2 + OFF_TK + f*FPB + 4*mp) = pack2(a0, a1);
            }
        } else {
            #pragma unroll
            for (int it = 0; it < 10; it++) {
                int p = tid + it * 320;
                int fp2 = p / 80, r = p - fp2 * 80;
                float a0 = qc[(2*fp2)*80 + r], a1 = qc[(2*fp2+1)*80 + r];
                *(uint32_t*)(sm2 + OFF_TQ + r*FPB + 4*fp2) = pack2(a0, a1);
            }
            // V plane: gmem idx = f*80 + m; pairs along m contiguous
            #pragma unroll
            for (int it = 0; it < 10; it++) {
                int p = tid + it * 320;
                int f = p / 40, mp = p - f * 40;
                float2 v = *(const float2*)(kc + f*80 + 2*mp);
                *(uint32_t*)(sm2 + OFF_TK + f*FPB + 4*mp) = pack2(v.x, v.y);
            }
        }
        __syncthreads();
        float o[5][4];
        #pragma unroll
        for (int j = 0; j < 5; j++)
            #pragma unroll
            for (int t = 0; t < 4; t++) o[j][t] = 0.f;
        #pragma unroll
        for (int ks = 0; ks < 5; ks++) {
            uint32_t bA[4], bB[4], bC[2];
            {
                int row = nh*40 + (lane & 15);
                ldm_x4(bA[0], bA[1], bA[2], bA[3],
                       tk32 + row*FPB + ks*32 + ((lane >> 4) << 4));
            }
            {
                int row = nh*40 + 16 + (lane & 15);
                ldm_x4(bB[0], bB[1], bB[2], bB[3],
                       tk32 + row*FPB + ks*32 + ((lane >> 4) << 4));
            }
            {
                int row = nh*40 + 32 + (lane & 7);
                ldm_x2(bC[0], bC[1],
                       tk32 + row*FPB + ks*32 + (((lane >> 3) & 1) << 4));
            }
            { uint32_t bb[2] = { bA[0], bA[2] }; mma16816(o[0], aP[ks], bb); }
            { uint32_t bb[2] = { bA[1], bA[3] }; mma16816(o[1], aP[ks], bb); }
            { uint32_t bb[2] = { bB[0], bB[2] }; mma16816(o[2], aP[ks], bb); }
            { uint32_t bb[2] = { bB[1], bB[3] }; mma16816(o[3], aP[ks], bb); }
            { uint32_t bb[2] = { bC[0], bC[1] }; mma16816(o[4], aP[ks], bb); }
        }
        // epilogue: + q*rq, write/accumulate gmem
        float* ob = out + cbase + c*HW;
        int row  = mt*16 + (lane >> 2);
        int colb = nh*40 + (lane & 3) * 2;
        #pragma unroll
        for (int j = 0; j < 5; j++) {
            int col = colb + j*8;
            #pragma unroll
            for (int half = 0; half < 2; half++) {
                int rr = row + 8*half;
                float rqi = rq[rr];
                __nv_bfloat162 q2 = *(const __nv_bfloat162*)(sm2 + OFF_TQ + rr*FPB + col*2);
                float2 qf = __bfloat1622float2(q2);
                float v0 = o[j][2*half]     + qf.x * rqi;
                float v1 = o[j][2*half + 1] + qf.y * rqi;
                if (AXIS == 0) {
                    float* dst = ob + rr*80 + col;
                    if (ACC) { v0 += dst[0]; v1 += dst[1]; }
                    dst[0] = v0; dst[1] = v1;
                } else {
                    float* d0 = ob + col*80 + rr;
                    float* d1 = ob + (col+1)*80 + rr;
                    if (ACC) { v0 += *d0; v1 += *d1; }
                    *d0 = v0; *d1 = v1;
                }
            }
        }
    }
}

// ---------------- launch -----------------------------------------------------
extern "C" void kernel_launch(void* const* d_in, const int* in_sizes, int n_in,
                              void* d_out, int out_size)
{
    const float* x    = (const float*)d_in[0];
    const float* ln_g = (const float*)d_in[1];
    const float* ln_b = (const float*)d_in[2];
    const float* w_in = (const float*)d_in[3];
    const float* b_in = (const float*)d_in[4];
    const float* w_out= (const float*)d_in[5];
    const float* b_out= (const float*)d_in[6];
    const float* wx7  = (const float*)d_in[7];
    const float* bx7  = (const float*)d_in[8];
    const float* wx11 = (const float*)d_in[9];
    const float* bx11 = (const float*)d_in[10];
    const float* wx21 = (const float*)d_in[11];
    const float* bx21 = (const float*)d_in[12];
    const float* wy7  = (const float*)d_in[13];
    const float* by7  = (const float*)d_in[14];
    const float* wy11 = (const float*)d_in[15];
    const float* by11 = (const float*)d_in[16];
    const float* wy21 = (const float*)d_in[17];
    const float* by21 = (const float*)d_in[18];
    float* out = (float*)d_out;

    float *pA, *pB, *pC;
    cudaGetSymbolAddress((void**)&pA, g_A);
    cudaGetSymbolAddress((void**)&pB, g_B);
    cudaGetSymbolAddress((void**)&pC, g_C);

    cudaFuncSetAttribute(attn_kernel<0,false>, cudaFuncAttributeMaxDynamicSharedMemorySize, ATTN2_SMEM);
    cudaFuncSetAttribute(attn_kernel<1,true >, cudaFuncAttributeMaxDynamicSharedMemorySize, ATTN2_SMEM);
    cudaFuncSetAttribute(gemm_mma<false>, cudaFuncAttributeMaxDynamicSharedMemorySize, GSMEM);
    cudaFuncSetAttribute(gemm_mma<true >, cudaFuncAttributeMaxDynamicSharedMemorySize, GSMEM);

    // 1) LayerNorm: x -> A (xn)
    ln_kernel<<<(BB*HW)/256, 256>>>(x, ln_g, ln_b);
    // 2) fused depthwise convs: A -> B (sx), A -> C (sy)
    dw_kernel<0><<<BB*CC, 256>>>(wx7, bx7, wx11, bx11, wx21, bx21, pB);
    dw_kernel<1><<<BB*CC, 256>>>(wy7, by7, wy11, by11, wy21, by21, pC);
    // 3) pointwise w_in: B(sx)->A=fx, C(sy)->B=fy
    dim3 gg(HW/128, CC/128, BB);
    gemm_mma<false><<<gg, 256, GSMEM>>>(w_in, pB, b_in, 1.f, nullptr, pA);
    gemm_mma<false><<<gg, 256, GSMEM>>>(w_in, pC, b_in, 1.f, nullptr, pB);
    // 4) cross-axis attention (out_x then += out_y): C = att
    attn_kernel<0,false><<<BB*NHEADS, 320, ATTN2_SMEM>>>(pB, pA, pC); // q=fy,k=v=fx
    attn_kernel<1,true ><<<BB*NHEADS, 320, ATTN2_SMEM>>>(pA, pB, pC); // q=fx,k=v=fy
    // 5) final pointwise w_out on (out_x+out_y), +2*b_out, +x residual
    gemm_mma<true><<<gg, 256, GSMEM>>>(w_out, pC, b_out, 2.f, x, out);
}

// round 9
// speedup vs baseline: 3.2463x; 1.0158x over previous
#include <cuda_runtime.h>
#include <cuda_bf16.h>
#include <math.h>
#include <stdint.h>

#define BB     16
#define CC     256
#define HW     6400
#define NHEADS 8
#define CPH    32

// ---------------- scratch (static device globals; no allocation) -------------
__device__ float g_A[BB*CC*HW];
__device__ float g_B[BB*CC*HW];
__device__ float g_C[BB*CC*HW];

// ================= helpers ===================================================
__device__ __forceinline__ uint32_t smem_to_u32(const void* p) {
    uint32_t a;
    asm("{ .reg .u64 t; cvta.to.shared.u64 t, %1; cvt.u32.u64 %0, t; }" : "=r"(a) : "l"(p));
    return a;
}
__device__ __forceinline__ uint32_t pack2(float x, float y) {
    __nv_bfloat162 b = __float22bfloat162_rn(make_float2(x, y));
    return *(uint32_t*)&b;
}
__device__ __forceinline__ void ldm_x4(uint32_t& r0, uint32_t& r1, uint32_t& r2, uint32_t& r3,
                                       uint32_t addr) {
    asm volatile("ldmatrix.sync.aligned.m8n8.x4.shared.b16 {%0,%1,%2,%3}, [%4];"
                 : "=r"(r0), "=r"(r1), "=r"(r2), "=r"(r3) : "r"(addr));
}
__device__ __forceinline__ void ldm_x2(uint32_t& r0, uint32_t& r1, uint32_t addr) {
    asm volatile("ldmatrix.sync.aligned.m8n8.x2.shared.b16 {%0,%1}, [%2];"
                 : "=r"(r0), "=r"(r1) : "r"(addr));
}
__device__ __forceinline__ void mma16816(float* d, const uint32_t* a, const uint32_t* b) {
    asm volatile("mma.sync.aligned.m16n8k16.row.col.f32.bf16.bf16.f32 "
                 "{%0,%1,%2,%3}, {%4,%5,%6,%7}, {%8,%9}, {%0,%1,%2,%3};"
                 : "+f"(d[0]), "+f"(d[1]), "+f"(d[2]), "+f"(d[3])
                 : "r"(a[0]), "r"(a[1]), "r"(a[2]), "r"(a[3]), "r"(b[0]), "r"(b[1]));
}

// ---------------- LayerNorm over channels, per pixel -------------------------
__global__ __launch_bounds__(256) void ln_kernel(const float* __restrict__ x,
                                                 const float* __restrict__ gam,
                                                 const float* __restrict__ bet)
{
    int p  = blockIdx.x * 256 + threadIdx.x;
    int b  = p / HW;
    int pl = p - b * HW;
    const float* xb = x + b * CC * HW + pl;
    float s = 0.f, s2 = 0.f;
    #pragma unroll 8
    for (int c = 0; c < CC; c++) { float v = xb[c*HW]; s += v; s2 = fmaf(v, v, s2); }
    float mu  = s  * (1.f / CC);
    float var = s2 * (1.f / CC) - mu * mu;
    float inv = rsqrtf(var + 1e-5f);
    float* ob = g_A + b * CC * HW + pl;
    #pragma unroll 8
    for (int c = 0; c < CC; c++) {
        float v = xb[c*HW];
        ob[c*HW] = (v - mu) * inv * gam[c] + bet[c];
    }
}

// ---------------- fused depthwise 7+11+21 (one 21-tap filter) ----------------
// Zero-padded smem plane: no bounds checks in inner loop.
// DIR=0: rows padded to 100 (10 halo each side). DIR=1: 10 halo rows each side.
template<int DIR>
__global__ __launch_bounds__(256) void dw_kernel(
    const float* __restrict__ w7,  const float* __restrict__ b7,
    const float* __restrict__ w11, const float* __restrict__ b11,
    const float* __restrict__ w21, const float* __restrict__ b21,
    float* __restrict__ dst_)
{
    __shared__ float pad[8000];       // DIR0: [80][100]; DIR1: [100][80]
    __shared__ float coef[21];
    __shared__ float biasv;
    int bc = blockIdx.x;
    int c  = bc & (CC - 1);
    for (int i = threadIdx.x; i < 8000; i += 256) pad[i] = 0.f;
    if (threadIdx.x < 21) {
        int t = threadIdx.x - 10;
        float v = w21[c*21 + t + 10];
        if (t >= -5 && t <= 5) v += w11[c*11 + t + 5];
        if (t >= -3 && t <= 3) v += w7 [c*7  + t + 3];
        coef[threadIdx.x] = v;
    }
    if (threadIdx.x == 0) biasv = b7[c] + b11[c] + b21[c];
    __syncthreads();
    const float* src = g_A + bc * HW;
    for (int i = threadIdx.x; i < HW; i += 256) {
        int h = i / 80;
        int w = i - h * 80;
        if (DIR == 0) pad[h*100 + 10 + w] = src[i];
        else          pad[(h + 10)*80 + w] = src[i];
    }
    __syncthreads();
    float bv = biasv;
    float* dst = dst_ + bc * HW;
    for (int i = threadIdx.x; i < HW; i += 256) {
        int h = i / 80;
        int w = i - h * 80;
        const float* base = (DIR == 0) ? (pad + h*100 + w) : (pad + h*80 + w);
        const int stride  = (DIR == 0) ? 1 : 80;
        float acc = bv;
        #pragma unroll
        for (int t = 0; t < 21; t++)
            acc = fmaf(coef[t], base[t*stride], acc);
        dst[i] = acc;
    }
}

// ============== mma.sync bf16 GEMM: out[o,p] = sum_k W[o,k] X[k,p] ===========
#define GSMEM (64*1024 + 16*1024)

template<bool RESID>
__global__ __launch_bounds__(256) void gemm_mma(
    const float* __restrict__ Wm, const float* __restrict__ X,
    const float* __restrict__ bias, float bscale,
    const float* __restrict__ resid, float* __restrict__ out)
{
    extern __shared__ char smem[];
    char* Bs = smem;
    char* As = smem + 65536;
    const uint32_t Bs32 = smem_to_u32(Bs);
    const uint32_t As32 = smem_to_u32(As);
    const int tid  = threadIdx.x;
    const int wid  = tid >> 5, lane = tid & 31;
    const int wm   = wid >> 1,  wn  = wid & 1;
    const int p0   = blockIdx.x * 128;
    const int o0   = blockIdx.y * 128;
    const int xbase = blockIdx.z * (CC * HW);

    #pragma unroll
    for (int it = 0; it < 16; it++) {
        int idx = tid + it * 256;
        int n = idx >> 5, kc = idx & 31;
        const float* wp = Wm + (o0 + n) * CC + kc * 8;
        float4 f0 = *(const float4*)(wp);
        float4 f1 = *(const float4*)(wp + 4);
        uint4 u;
        u.x = pack2(f0.x, f0.y); u.y = pack2(f0.z, f0.w);
        u.z = pack2(f1.x, f1.y); u.w = pack2(f1.z, f1.w);
        *(uint4*)(Bs + n * 512 + ((kc ^ (n & 7)) << 4)) = u;
    }

    float acc[2][8][4];
    #pragma unroll
    for (int i = 0; i < 2; i++)
        #pragma unroll
        for (int j = 0; j < 8; j++)
            #pragma unroll
            for (int t = 0; t < 4; t++) acc[i][j][t] = 0.f;

    for (int ch = 0; ch < 4; ch++) {
        __syncthreads();
        #pragma unroll
        for (int it = 0; it < 4; it++) {
            int idx = tid + it * 256;
            int m = idx & 127, kq = idx >> 7;
            const float* xp = X + xbase + (ch * 64 + kq * 8) * HW + p0 + m;
            float v0 = xp[0*HW], v1 = xp[1*HW], v2 = xp[2*HW], v3 = xp[3*HW];
            float v4 = xp[4*HW], v5 = xp[5*HW], v6 = xp[6*HW], v7 = xp[7*HW];
            uint4 u;
            u.x = pack2(v0, v1); u.y = pack2(v2, v3);
            u.z = pack2(v4, v5); u.w = pack2(v6, v7);
            *(uint4*)(As + m * 128 + ((kq ^ (m & 7)) << 4)) = u;
        }
        __syncthreads();
        #pragma unroll
        for (int ks = 0; ks < 4; ks++) {
            uint32_t a[2][4];
            #pragma unroll
            for (int am = 0; am < 2; am++) {
                int row = wm * 32 + am * 16 + (lane & 15);
                int chk = (ks * 2 + (lane >> 4)) ^ (row & 7);
                ldm_x4(a[am][0], a[am][1], a[am][2], a[am][3],
                       As32 + row * 128 + (chk << 4));
            }
            uint32_t b[4][4];
            #pragma unroll
            for (int bp = 0; bp < 4; bp++) {
                int n  = wn * 64 + bp * 16 + (lane & 15);
                int kc = ch * 8 + ks * 2 + (lane >> 4);
                ldm_x4(b[bp][0], b[bp][1], b[bp][2], b[bp][3],
                       Bs32 + n * 512 + ((kc ^ (n & 7)) << 4));
            }
            #pragma unroll
            for (int am = 0; am < 2; am++)
                #pragma unroll
                for (int an = 0; an < 8; an++) {
                    uint32_t bb[2] = { b[an >> 1][an & 1], b[an >> 1][(an & 1) + 2] };
                    mma16816(acc[am][an], a[am], bb);
                }
        }
    }

    #pragma unroll
    for (int am = 0; am < 2; am++) {
        int m = wm * 32 + am * 16 + (lane >> 2);
        #pragma unroll
        for (int an = 0; an < 8; an++) {
            int n = o0 + wn * 64 + an * 8 + (lane & 3) * 2;
            float b0 = bias[n] * bscale, b1 = bias[n + 1] * bscale;
            long a00 = (long)xbase + (long)n * HW + p0 + m;
            float v0 = acc[am][an][0] + b0;
            float v1 = acc[am][an][1] + b1;
            float v2 = acc[am][an][2] + b0;
            float v3 = acc[am][an][3] + b1;
            if (RESID) {
                v0 += resid[a00];      v1 += resid[a00 + HW];
                v2 += resid[a00 + 8];  v3 += resid[a00 + HW + 8];
            }
            out[a00]          = v0;  out[a00 + HW]     = v1;
            out[a00 + 8]      = v2;  out[a00 + HW + 8] = v3;
        }
    }
}

// ======== cross-axis attention on mma.sync, one block per (b, head) ==========
// 320 threads = 10 warps: mt = wid>>1 (m16 tile 0..4), nh = wid&1 (n-half of 40).
// Software-pipelined: next channel's planes prefetched into registers during MMA.
#define FPB 176
#define OFF_TQ 0
#define OFF_TK 14080
#define OFF_PS 28160
#define OFF_GM 42240
#define OFF_RQ 68160
#define OFF_RK 68480
#define ATTN2_SMEM 68800

template<int AXIS, bool ACC>
__global__ __launch_bounds__(320) void attn_kernel(
    const float* __restrict__ Q, const float* __restrict__ KV, float* __restrict__ out)
{
    extern __shared__ char sm2[];
    float* Gm = (float*)(sm2 + OFF_GM);
    float* rq = (float*)(sm2 + OFF_RQ);
    float* rk = (float*)(sm2 + OFF_RK);
    const uint32_t tq32 = smem_to_u32(sm2 + OFF_TQ);
    const uint32_t tk32 = smem_to_u32(sm2 + OFF_TK);
    const uint32_t ps32 = smem_to_u32(sm2 + OFF_PS);

    const int bh = blockIdx.x;
    const int cbase = (bh >> 3) * (CC*HW) + (bh & 7) * (CPH*HW);
    const float* Qb = Q  + cbase;
    const float* Kb = KV + cbase;
    const int tid  = threadIdx.x;
    const int wid  = tid >> 5, lane = tid & 31;
    const int mt   = wid >> 1, nh = wid & 1;

    uint32_t pf[20];     // prefetched q(10)+k/v(10) packed bf16x2

    // ---- prefetch lambdas (phase 1: q plane + k plane, both seq-major) ----
    auto load_qk = [&](int c) {
        const float* qc = Qb + c*HW;
        const float* kc = Kb + c*HW;
        if (AXIS == 0) {
            #pragma unroll
            for (int it = 0; it < 10; it++) {
                int p = tid + it * 320;
                int r = p / 40, fp2 = p - r * 40;
                float2 v = *(const float2*)(qc + r*80 + 2*fp2);
                pf[it] = pack2(v.x, v.y);
                float2 w = *(const float2*)(kc + r*80 + 2*fp2);
                pf[10 + it] = pack2(w.x, w.y);
            }
        } else {
            #pragma unroll
            for (int it = 0; it < 10; it++) {
                int p = tid + it * 320;
                int fp2 = p / 80, r = p - fp2 * 80;
                float a0 = qc[(2*fp2)*80 + r], a1 = qc[(2*fp2+1)*80 + r];
                pf[it] = pack2(a0, a1);
                float b0 = kc[(2*fp2)*80 + r], b1 = kc[(2*fp2+1)*80 + r];
                pf[10 + it] = pack2(b0, b1);
            }
        }
    };
    auto store_qk = [&]() {
        #pragma unroll
        for (int it = 0; it < 10; it++) {
            int p = tid + it * 320;
            int r, fp2;
            if (AXIS == 0) { r = p / 40; fp2 = p - r * 40; }
            else           { fp2 = p / 80; r = p - fp2 * 80; }
            *(uint32_t*)(sm2 + OFF_TQ + r*FPB + 4*fp2) = pf[it];
            *(uint32_t*)(sm2 + OFF_TK + r*FPB + 4*fp2) = pf[10 + it];
        }
    };
    // ---- phase 3: q plane (seq-major) + V plane (feat-major / transposed) ----
    auto load_qv = [&](int c) {
        const float* qc = Qb + c*HW;
        const float* kc = Kb + c*HW;
        if (AXIS == 0) {
            #pragma unroll
            for (int it = 0; it < 10; it++) {
                int p = tid + it * 320;
                int r = p / 40, fp2 = p - r * 40;
                float2 v = *(const float2*)(qc + r*80 + 2*fp2);
                pf[it] = pack2(v.x, v.y);
            }
            #pragma unroll
            for (int it = 0; it < 10; it++) {
                int p = tid + it * 320;
                int mp = p / 80, f = p - mp * 80;
                float a0 = kc[(2*mp)*80 + f], a1 = kc[(2*mp+1)*80 + f];
                pf[10 + it] = pack2(a0, a1);
            }
        } else {
            #pragma unroll
            for (int it = 0; it < 10; it++) {
                int p = tid + it * 320;
                int fp2 = p / 80, r = p - fp2 * 80;
                float a0 = qc[(2*fp2)*80 + r], a1 = qc[(2*fp2+1)*80 + r];
                pf[it] = pack2(a0, a1);
            }
            #pragma unroll
            for (int it = 0; it < 10; it++) {
                int p = tid + it * 320;
                int f = p / 40, mp = p - f * 40;
                float2 v = *(const float2*)(kc + f*80 + 2*mp);
                pf[10 + it] = pack2(v.x, v.y);
            }
        }
    };
    auto store_qv = [&]() {
        #pragma unroll
        for (int it = 0; it < 10; it++) {
            int p = tid + it * 320;
            int r, fp2;
            if (AXIS == 0) { r = p / 40; fp2 = p - r * 40; }
            else           { fp2 = p / 80; r = p - fp2 * 80; }
            *(uint32_t*)(sm2 + OFF_TQ + r*FPB + 4*fp2) = pf[it];
        }
        #pragma unroll
        for (int it = 0; it < 10; it++) {
            int p = tid + it * 320;
            int f, mp;
            if (AXIS == 0) { mp = p / 80; f = p - mp * 80; }
            else           { f = p / 40; mp = p - f * 40; }
            *(uint32_t*)(sm2 + OFF_TK + f*FPB + 4*mp) = pf[10 + it];
        }
    };

    float acc[5][4];
    #pragma unroll
    for (int j = 0; j < 5; j++)
        #pragma unroll
        for (int t = 0; t < 4; t++) acc[j][t] = 0.f;
    float nss = 0.f;

    // ================= Phase 1: raw Gram + fused sumsq =================
    load_qk(0);
    for (int c = 0; c < CPH; c++) {
        __syncthreads();               // prev MMA done reading smem
        store_qk();
        __syncthreads();
        if (c < CPH-1) load_qk(c + 1); // overlap gmem with MMA below
        if (tid < 160) {
            const char* rowp = (tid < 80) ? (sm2 + OFF_TQ + tid*FPB)
                                          : (sm2 + OFF_TK + (tid-80)*FPB);
            float s = 0.f;
            #pragma unroll 8
            for (int u = 0; u < 40; u++) {
                __nv_bfloat162 h2 = *(const __nv_bfloat162*)(rowp + 4*u);
                float2 f2 = __bfloat1622float2(h2);
                s = fmaf(f2.x, f2.x, fmaf(f2.y, f2.y, s));
            }
            nss += s;
        }
        #pragma unroll
        for (int ks = 0; ks < 5; ks++) {
            uint32_t a[4];
            {
                int row = mt*16 + (lane & 15);
                ldm_x4(a[0], a[1], a[2], a[3],
                       tq32 + row*FPB + ks*32 + ((lane >> 4) << 4));
            }
            uint32_t bA[4], bB[4], bC[2];
            {
                int row = nh*40 + (lane & 15);
                ldm_x4(bA[0], bA[1], bA[2], bA[3],
                       tk32 + row*FPB + ks*32 + ((lane >> 4) << 4));
            }
            {
                int row = nh*40 + 16 + (lane & 15);
                ldm_x4(bB[0], bB[1], bB[2], bB[3],
                       tk32 + row*FPB + ks*32 + ((lane >> 4) << 4));
            }
            {
                int row = nh*40 + 32 + (lane & 7);
                ldm_x2(bC[0], bC[1],
                       tk32 + row*FPB + ks*32 + (((lane >> 3) & 1) << 4));
            }
            { uint32_t bb[2] = { bA[0], bA[2] }; mma16816(acc[0], a, bb); }
            { uint32_t bb[2] = { bA[1], bA[3] }; mma16816(acc[1], a, bb); }
            { uint32_t bb[2] = { bB[0], bB[2] }; mma16816(acc[2], a, bb); }
            { uint32_t bb[2] = { bB[1], bB[3] }; mma16816(acc[3], a, bb); }
            { uint32_t bb[2] = { bC[0], bC[1] }; mma16816(acc[4], a, bb); }
        }
    }
    __syncthreads();
    if (tid < 160) {
        float inv = 1.f / fmaxf(sqrtf(nss), 1e-12f);
        if (tid < 80) rq[tid] = inv; else rk[tid - 80] = inv;
    }
    __syncthreads();
    {
        int row  = mt*16 + (lane >> 2);
        int colb = nh*40 + (lane & 3) * 2;
        float r0 = rq[row], r1 = rq[row + 8];
        #pragma unroll
        for (int j = 0; j < 5; j++) {
            int col = colb + j*8;
            float k0 = rk[col], k1 = rk[col + 1];
            Gm[row*81 + col]       = acc[j][0] * r0 * k0;
            Gm[row*81 + col + 1]   = acc[j][1] * r0 * k1;
            Gm[(row+8)*81 + col]   = acc[j][2] * r1 * k0;
            Gm[(row+8)*81 + col+1] = acc[j][3] * r1 * k1;
        }
    }
    __syncthreads();
    // ================= Phase 2: softmax rows =================
    if (tid < 80) {
        float* row = Gm + tid*81;
        float mx = -3.0e38f;
        for (int m = 0; m < 80; m++) mx = fmaxf(mx, row[m]);
        float s = 0.f;
        for (int m = 0; m < 80; m++) { float e = expf(row[m] - mx); row[m] = e; s += e; }
        float is = 1.f / s;
        for (int m = 0; m < 80; m++) row[m] *= is;
    }
    __syncthreads();
    #pragma unroll
    for (int it = 0; it < 10; it++) {
        int p = tid + it * 320;
        int n = p / 40, mp = p - n * 40;
        *(uint32_t*)(sm2 + OFF_PS + n*FPB + 4*mp) = pack2(Gm[n*81 + 2*mp], Gm[n*81 + 2*mp + 1]);
    }
    __syncthreads();
    uint32_t aP[5][4];
    #pragma unroll
    for (int ks = 0; ks < 5; ks++) {
        int row = mt*16 + (lane & 15);
        ldm_x4(aP[ks][0], aP[ks][1], aP[ks][2], aP[ks][3],
               ps32 + row*FPB + ks*32 + ((lane >> 4) << 4));
    }

    // ================= Phase 3: out = P@V + q*rq =================
    load_qv(0);
    for (int c = 0; c < CPH; c++) {
        __syncthreads();
        store_qv();
        __syncthreads();
        if (c < CPH-1) load_qv(c + 1);
        float o[5][4];
        #pragma unroll
        for (int j = 0; j < 5; j++)
            #pragma unroll
            for (int t = 0; t < 4; t++) o[j][t] = 0.f;
        #pragma unroll
        for (int ks = 0; ks < 5; ks++) {
            uint32_t bA[4], bB[4], bC[2];
            {
                int row = nh*40 + (lane & 15);
                ldm_x4(bA[0], bA[1], bA[2], bA[3],
                       tk32 + row*FPB + ks*32 + ((lane >> 4) << 4));
            }
            {
                int row = nh*40 + 16 + (lane & 15);
                ldm_x4(bB[0], bB[1], bB[2], bB[3],
                       tk32 + row*FPB + ks*32 + ((lane >> 4) << 4));
            }
            {
                int row = nh*40 + 32 + (lane & 7);
                ldm_x2(bC[0], bC[1],
                       tk32 + row*FPB + ks*32 + (((lane >> 3) & 1) << 4));
            }
            { uint32_t bb[2] = { bA[0], bA[2] }; mma16816(o[0], aP[ks], bb); }
            { uint32_t bb[2] = { bA[1], bA[3] }; mma16816(o[1], aP[ks], bb); }
            { uint32_t bb[2] = { bB[0], bB[2] }; mma16816(o[2], aP[ks], bb); }
            { uint32_t bb[2] = { bB[1], bB[3] }; mma16816(o[3], aP[ks], bb); }
            { uint32_t bb[2] = { bC[0], bC[1] }; mma16816(o[4], aP[ks], bb); }
        }
        float* ob = out + cbase + c*HW;
        int row  = mt*16 + (lane >> 2);
        int colb = nh*40 + (lane & 3) * 2;
        #pragma unroll
        for (int j = 0; j < 5; j++) {
            int col = colb + j*8;
            #pragma unroll
            for (int half = 0; half < 2; half++) {
                int rr = row + 8*half;
                float rqi = rq[rr];
                __nv_bfloat162 q2 = *(const __nv_bfloat162*)(sm2 + OFF_TQ + rr*FPB + col*2);
                float2 qf = __bfloat1622float2(q2);
                float v0 = o[j][2*half]     + qf.x * rqi;
                float v1 = o[j][2*half + 1] + qf.y * rqi;
                if (AXIS == 0) {
                    float* dst = ob + rr*80 + col;
                    if (ACC) { v0 += dst[0]; v1 += dst[1]; }
                    dst[0] = v0; dst[1] = v1;
                } else {
                    float* d0 = ob + col*80 + rr;
                    float* d1 = ob + (col+1)*80 + rr;
                    if (ACC) { v0 += *d0; v1 += *d1; }
                    *d0 = v0; *d1 = v1;
                }
            }
        }
    }
}

// ---------------- launch -----------------------------------------------------
extern "C" void kernel_launch(void* const* d_in, const int* in_sizes, int n_in,
                              void* d_out, int out_size)
{
    const float* x    = (const float*)d_in[0];
    const float* ln_g = (const float*)d_in[1];
    const float* ln_b = (const float*)d_in[2];
    const float* w_in = (const float*)d_in[3];
    const float* b_in = (const float*)d_in[4];
    const float* w_out= (const float*)d_in[5];
    const float* b_out= (const float*)d_in[6];
    const float* wx7  = (const float*)d_in[7];
    const float* bx7  = (const float*)d_in[8];
    const float* wx11 = (const float*)d_in[9];
    const float* bx11 = (const float*)d_in[10];
    const float* wx21 = (const float*)d_in[11];
    const float* bx21 = (const float*)d_in[12];
    const float* wy7  = (const float*)d_in[13];
    const float* by7  = (const float*)d_in[14];
    const float* wy11 = (const float*)d_in[15];
    const float* by11 = (const float*)d_in[16];
    const float* wy21 = (const float*)d_in[17];
    const float* by21 = (const float*)d_in[18];
    float* out = (float*)d_out;

    float *pA, *pB, *pC;
    cudaGetSymbolAddress((void**)&pA, g_A);
    cudaGetSymbolAddress((void**)&pB, g_B);
    cudaGetSymbolAddress((void**)&pC, g_C);

    cudaFuncSetAttribute(attn_kernel<0,false>, cudaFuncAttributeMaxDynamicSharedMemorySize, ATTN2_SMEM);
    cudaFuncSetAttribute(attn_kernel<1,true >, cudaFuncAttributeMaxDynamicSharedMemorySize, ATTN2_SMEM);
    cudaFuncSetAttribute(gemm_mma<false>, cudaFuncAttributeMaxDynamicSharedMemorySize, GSMEM);
    cudaFuncSetAttribute(gemm_mma<true >, cudaFuncAttributeMaxDynamicSharedMemorySize, GSMEM);

    // 1) LayerNorm: x -> A (xn)
    ln_kernel<<<(BB*HW)/256, 256>>>(x, ln_g, ln_b);
    // 2) fused depthwise convs: A -> B (sx), A -> C (sy)
    dw_kernel<0><<<BB*CC, 256>>>(wx7, bx7, wx11, bx11, wx21, bx21, pB);
    dw_kernel<1><<<BB*CC, 256>>>(wy7, by7, wy11, by11, wy21, by21, pC);
    // 3) pointwise w_in: B(sx)->A=fx, C(sy)->B=fy
    dim3 gg(HW/128, CC/128, BB);
    gemm_mma<false><<<gg, 256, GSMEM>>>(w_in, pB, b_in, 1.f, nullptr, pA);
    gemm_mma<false><<<gg, 256, GSMEM>>>(w_in, pC, b_in, 1.f, nullptr, pB);
    // 4) cross-axis attention (out_x then += out_y): C = att
    attn_kernel<0,false><<<BB*NHEADS, 320, ATTN2_SMEM>>>(pB, pA, pC); // q=fy,k=v=fx
    attn_kernel<1,true ><<<BB*NHEADS, 320, ATTN2_SMEM>>>(pA, pB, pC); // q=fx,k=v=fy
    // 5) final pointwise w_out on (out_x+out_y), +2*b_out, +x residual
    gemm_mma<true><<<gg, 256, GSMEM>>>(w_out, pC, b_out, 2.f, x, out);
}

// round 10
// speedup vs baseline: 4.0119x; 1.2358x over previous
#include <cuda_runtime.h>
#include <cuda_bf16.h>
#include <math.h>
#include <stdint.h>

#define BB     16
#define CC     256
#define HW     6400
#define NHEADS 8
#define CPH    32

// ---------------- scratch (static device globals; no allocation) -------------
// ln: x->A | dw: A->B(sx), A->C(sy) | gemm: B->D(fx), C->B(fy)
// attn(merged): (D,B) -> C(att_x), A(att_y) | gemm: W@(C+A)+2b+x -> out
__device__ float g_A[BB*CC*HW];
__device__ float g_B[BB*CC*HW];
__device__ float g_C[BB*CC*HW];
__device__ float g_D[BB*CC*HW];

// ================= helpers ===================================================
__device__ __forceinline__ uint32_t smem_to_u32(const void* p) {
    uint32_t a;
    asm("{ .reg .u64 t; cvta.to.shared.u64 t, %1; cvt.u32.u64 %0, t; }" : "=r"(a) : "l"(p));
    return a;
}
__device__ __forceinline__ uint32_t pack2(float x, float y) {
    __nv_bfloat162 b = __float22bfloat162_rn(make_float2(x, y));
    return *(uint32_t*)&b;
}
__device__ __forceinline__ void ldm_x4(uint32_t& r0, uint32_t& r1, uint32_t& r2, uint32_t& r3,
                                       uint32_t addr) {
    asm volatile("ldmatrix.sync.aligned.m8n8.x4.shared.b16 {%0,%1,%2,%3}, [%4];"
                 : "=r"(r0), "=r"(r1), "=r"(r2), "=r"(r3) : "r"(addr));
}
__device__ __forceinline__ void ldm_x2(uint32_t& r0, uint32_t& r1, uint32_t addr) {
    asm volatile("ldmatrix.sync.aligned.m8n8.x2.shared.b16 {%0,%1}, [%2];"
                 : "=r"(r0), "=r"(r1) : "r"(addr));
}
__device__ __forceinline__ void mma16816(float* d, const uint32_t* a, const uint32_t* b) {
    asm volatile("mma.sync.aligned.m16n8k16.row.col.f32.bf16.bf16.f32 "
                 "{%0,%1,%2,%3}, {%4,%5,%6,%7}, {%8,%9}, {%0,%1,%2,%3};"
                 : "+f"(d[0]), "+f"(d[1]), "+f"(d[2]), "+f"(d[3])
                 : "r"(a[0]), "r"(a[1]), "r"(a[2]), "r"(a[3]), "r"(b[0]), "r"(b[1]));
}

// ---------------- LayerNorm over channels, per pixel -------------------------
__global__ __launch_bounds__(256) void ln_kernel(const float* __restrict__ x,
                                                 const float* __restrict__ gam,
                                                 const float* __restrict__ bet)
{
    int p  = blockIdx.x * 256 + threadIdx.x;
    int b  = p / HW;
    int pl = p - b * HW;
    const float* xb = x + b * CC * HW + pl;
    float s = 0.f, s2 = 0.f;
    #pragma unroll 8
    for (int c = 0; c < CC; c++) { float v = xb[c*HW]; s += v; s2 = fmaf(v, v, s2); }
    float mu  = s  * (1.f / CC);
    float var = s2 * (1.f / CC) - mu * mu;
    float inv = rsqrtf(var + 1e-5f);
    float* ob = g_A + b * CC * HW + pl;
    #pragma unroll 8
    for (int c = 0; c < CC; c++) {
        float v = xb[c*HW];
        ob[c*HW] = (v - mu) * inv * gam[c] + bet[c];
    }
}

// ---------------- fused depthwise, both dirs in one launch -------------------
// blockIdx.x < BB*CC: dir 0 (along W) -> dstX;  else dir 1 (along H) -> dstY
__global__ __launch_bounds__(256) void dw_kernel(
    const float* __restrict__ wx7,  const float* __restrict__ bx7,
    const float* __restrict__ wx11, const float* __restrict__ bx11,
    const float* __restrict__ wx21, const float* __restrict__ bx21,
    const float* __restrict__ wy7,  const float* __restrict__ by7,
    const float* __restrict__ wy11, const float* __restrict__ by11,
    const float* __restrict__ wy21, const float* __restrict__ by21,
    float* __restrict__ dstX, float* __restrict__ dstY)
{
    __shared__ float pad[8000];       // dir0: [80][100]; dir1: [100][80]
    __shared__ float coef[21];
    __shared__ float biasv;
    const int dir = (blockIdx.x >= BB*CC) ? 1 : 0;
    const int bc  = blockIdx.x - dir * BB * CC;
    const int c   = bc & (CC - 1);
    const float* w7  = dir ? wy7  : wx7;
    const float* w11 = dir ? wy11 : wx11;
    const float* w21 = dir ? wy21 : wx21;
    for (int i = threadIdx.x; i < 8000; i += 256) pad[i] = 0.f;
    if (threadIdx.x < 21) {
        int t = threadIdx.x - 10;
        float v = w21[c*21 + t + 10];
        if (t >= -5 && t <= 5) v += w11[c*11 + t + 5];
        if (t >= -3 && t <= 3) v += w7 [c*7  + t + 3];
        coef[threadIdx.x] = v;
    }
    if (threadIdx.x == 0) {
        biasv = (dir ? (by7[c] + by11[c] + by21[c])
                     : (bx7[c] + bx11[c] + bx21[c]));
    }
    __syncthreads();
    const float* src = g_A + bc * HW;
    for (int i = threadIdx.x; i < HW; i += 256) {
        int h = i / 80;
        int w = i - h * 80;
        if (dir == 0) pad[h*100 + 10 + w] = src[i];
        else          pad[(h + 10)*80 + w] = src[i];
    }
    __syncthreads();
    float bv = biasv;
    float* dst = (dir ? dstY : dstX) + bc * HW;
    const int stride = dir ? 80 : 1;
    for (int i = threadIdx.x; i < HW; i += 256) {
        int h = i / 80;
        int w = i - h * 80;
        const float* base = dir ? (pad + h*80 + w) : (pad + h*100 + w);
        float acc = bv;
        #pragma unroll
        for (int t = 0; t < 21; t++)
            acc = fmaf(coef[t], base[t*stride], acc);
        dst[i] = acc;
    }
}

// ============== mma.sync bf16 GEMM: out[o,p] = sum_k W[o,k] (X[+X2])[k,p] ====
#define GSMEM (64*1024 + 16*1024)

template<bool RESID>
__global__ __launch_bounds__(256) void gemm_mma(
    const float* __restrict__ Wm, const float* __restrict__ X,
    const float* __restrict__ X2,
    const float* __restrict__ bias, float bscale,
    const float* __restrict__ resid, float* __restrict__ out)
{
    extern __shared__ char smem[];
    char* Bs = smem;
    char* As = smem + 65536;
    const uint32_t Bs32 = smem_to_u32(Bs);
    const uint32_t As32 = smem_to_u32(As);
    const int tid  = threadIdx.x;
    const int wid  = tid >> 5, lane = tid & 31;
    const int wm   = wid >> 1,  wn  = wid & 1;
    const int p0   = blockIdx.x * 128;
    const int o0   = blockIdx.y * 128;
    const int xbase = blockIdx.z * (CC * HW);

    #pragma unroll
    for (int it = 0; it < 16; it++) {
        int idx = tid + it * 256;
        int n = idx >> 5, kc = idx & 31;
        const float* wp = Wm + (o0 + n) * CC + kc * 8;
        float4 f0 = *(const float4*)(wp);
        float4 f1 = *(const float4*)(wp + 4);
        uint4 u;
        u.x = pack2(f0.x, f0.y); u.y = pack2(f0.z, f0.w);
        u.z = pack2(f1.x, f1.y); u.w = pack2(f1.z, f1.w);
        *(uint4*)(Bs + n * 512 + ((kc ^ (n & 7)) << 4)) = u;
    }

    float acc[2][8][4];
    #pragma unroll
    for (int i = 0; i < 2; i++)
        #pragma unroll
        for (int j = 0; j < 8; j++)
            #pragma unroll
            for (int t = 0; t < 4; t++) acc[i][j][t] = 0.f;

    for (int ch = 0; ch < 4; ch++) {
        __syncthreads();
        #pragma unroll
        for (int it = 0; it < 4; it++) {
            int idx = tid + it * 256;
            int m = idx & 127, kq = idx >> 7;
            long off = (long)xbase + (long)(ch * 64 + kq * 8) * HW + p0 + m;
            const float* xp = X + off;
            float v[8];
            #pragma unroll
            for (int u2 = 0; u2 < 8; u2++) v[u2] = xp[u2*HW];
            if (RESID) {  // final gemm: X2 = second attention buffer
                const float* yp = X2 + off;
                #pragma unroll
                for (int u2 = 0; u2 < 8; u2++) v[u2] += yp[u2*HW];
            }
            uint4 u;
            u.x = pack2(v[0], v[1]); u.y = pack2(v[2], v[3]);
            u.z = pack2(v[4], v[5]); u.w = pack2(v[6], v[7]);
            *(uint4*)(As + m * 128 + ((kq ^ (m & 7)) << 4)) = u;
        }
        __syncthreads();
        #pragma unroll
        for (int ks = 0; ks < 4; ks++) {
            uint32_t a[2][4];
            #pragma unroll
            for (int am = 0; am < 2; am++) {
                int row = wm * 32 + am * 16 + (lane & 15);
                int chk = (ks * 2 + (lane >> 4)) ^ (row & 7);
                ldm_x4(a[am][0], a[am][1], a[am][2], a[am][3],
                       As32 + row * 128 + (chk << 4));
            }
            uint32_t b[4][4];
            #pragma unroll
            for (int bp = 0; bp < 4; bp++) {
                int n  = wn * 64 + bp * 16 + (lane & 15);
                int kc = ch * 8 + ks * 2 + (lane >> 4);
                ldm_x4(b[bp][0], b[bp][1], b[bp][2], b[bp][3],
                       Bs32 + n * 512 + ((kc ^ (n & 7)) << 4));
            }
            #pragma unroll
            for (int am = 0; am < 2; am++)
                #pragma unroll
                for (int an = 0; an < 8; an++) {
                    uint32_t bb[2] = { b[an >> 1][an & 1], b[an >> 1][(an & 1) + 2] };
                    mma16816(acc[am][an], a[am], bb);
                }
        }
    }

    #pragma unroll
    for (int am = 0; am < 2; am++) {
        int m = wm * 32 + am * 16 + (lane >> 2);
        #pragma unroll
        for (int an = 0; an < 8; an++) {
            int n = o0 + wn * 64 + an * 8 + (lane & 3) * 2;
            float b0 = bias[n] * bscale, b1 = bias[n + 1] * bscale;
            long a00 = (long)xbase + (long)n * HW + p0 + m;
            float v0 = acc[am][an][0] + b0;
            float v1 = acc[am][an][1] + b1;
            float v2 = acc[am][an][2] + b0;
            float v3 = acc[am][an][3] + b1;
            if (RESID) {
                v0 += resid[a00];      v1 += resid[a00 + HW];
                v2 += resid[a00 + 8];  v3 += resid[a00 + HW + 8];
            }
            out[a00]          = v0;  out[a00 + HW]     = v1;
            out[a00 + 8]      = v2;  out[a00 + HW + 8] = v3;
        }
    }
}

// ======== cross-axis attention, both axes in ONE launch (grid 256) ===========
// blockIdx.x < 128: axis0 (q=fy,k=v=fx -> outx); else axis1 (q=fx,k=v=fy -> outy)
// 320 threads = 10 warps: mt = wid>>1 (m16 tile 0..4), nh = wid&1 (n-half of 40).
#define FPB 176
#define OFF_TQ 0
#define OFF_TK 14080
#define OFF_PS 28160
#define OFF_GM 42240
#define OFF_RQ 68160
#define OFF_RK 68480
#define ATTN2_SMEM 68800

__global__ __launch_bounds__(320, 2) void attn_kernel(
    const float* __restrict__ fx, const float* __restrict__ fy,
    float* __restrict__ outx, float* __restrict__ outy)
{
    extern __shared__ char sm2[];
    float* Gm = (float*)(sm2 + OFF_GM);
    float* rq = (float*)(sm2 + OFF_RQ);
    float* rk = (float*)(sm2 + OFF_RK);
    const uint32_t tq32 = smem_to_u32(sm2 + OFF_TQ);
    const uint32_t tk32 = smem_to_u32(sm2 + OFF_TK);
    const uint32_t ps32 = smem_to_u32(sm2 + OFF_PS);

    const int axis = blockIdx.x >> 7;
    const int bh   = blockIdx.x & 127;
    const int cbase = (bh >> 3) * (CC*HW) + (bh & 7) * (CPH*HW);
    const float* Qb = (axis ? fx : fy) + cbase;
    const float* Kb = (axis ? fy : fx) + cbase;
    float* outb     = (axis ? outy : outx) + cbase;
    const int tid  = threadIdx.x;
    const int wid  = tid >> 5, lane = tid & 31;
    const int mt   = wid >> 1, nh = wid & 1;

    float acc[5][4];
    #pragma unroll
    for (int j = 0; j < 5; j++)
        #pragma unroll
        for (int t = 0; t < 4; t++) acc[j][t] = 0.f;
    float nss = 0.f;

    // ================= Phase 1: raw Gram + fused sumsq =================
    for (int c = 0; c < CPH; c++) {
        const float* qc = Qb + c*HW;
        const float* kc = Kb + c*HW;
        __syncthreads();
        if (axis == 0) {
            #pragma unroll
            for (int it = 0; it < 10; it++) {
                int p = tid + it * 320;
                int r = p / 40, fp2 = p - r * 40;
                float2 v = *(const float2*)(qc + r*80 + 2*fp2);
                *(uint32_t*)(sm2 + OFF_TQ + r*FPB + 4*fp2) = pack2(v.x, v.y);
                float2 w = *(const float2*)(kc + r*80 + 2*fp2);
                *(uint32_t*)(sm2 + OFF_TK + r*FPB + 4*fp2) = pack2(w.x, w.y);
            }
        } else {
            #pragma unroll
            for (int it = 0; it < 10; it++) {
                int p = tid + it * 320;
                int fp2 = p / 80, r = p - fp2 * 80;
                float a0 = qc[(2*fp2)*80 + r], a1 = qc[(2*fp2+1)*80 + r];
                *(uint32_t*)(sm2 + OFF_TQ + r*FPB + 4*fp2) = pack2(a0, a1);
                float b0 = kc[(2*fp2)*80 + r], b1 = kc[(2*fp2+1)*80 + r];
                *(uint32_t*)(sm2 + OFF_TK + r*FPB + 4*fp2) = pack2(b0, b1);
            }
        }
        __syncthreads();
        if (tid < 160) {
            const char* rowp = (tid < 80) ? (sm2 + OFF_TQ + tid*FPB)
                                          : (sm2 + OFF_TK + (tid-80)*FPB);
            float s = 0.f;
            #pragma unroll 8
            for (int u = 0; u < 40; u++) {
                __nv_bfloat162 h2 = *(const __nv_bfloat162*)(rowp + 4*u);
                float2 f2 = __bfloat1622float2(h2);
                s = fmaf(f2.x, f2.x, fmaf(f2.y, f2.y, s));
            }
            nss += s;
        }
        #pragma unroll
        for (int ks = 0; ks < 5; ks++) {
            uint32_t a[4];
            {
                int row = mt*16 + (lane & 15);
                ldm_x4(a[0], a[1], a[2], a[3],
                       tq32 + row*FPB + ks*32 + ((lane >> 4) << 4));
            }
            uint32_t bA[4], bB[4], bC[2];
            {
                int row = nh*40 + (lane & 15);
                ldm_x4(bA[0], bA[1], bA[2], bA[3],
                       tk32 + row*FPB + ks*32 + ((lane >> 4) << 4));
            }
            {
                int row = nh*40 + 16 + (lane & 15);
                ldm_x4(bB[0], bB[1], bB[2], bB[3],
                       tk32 + row*FPB + ks*32 + ((lane >> 4) << 4));
            }
            {
                int row = nh*40 + 32 + (lane & 7);
                ldm_x2(bC[0], bC[1],
                       tk32 + row*FPB + ks*32 + (((lane >> 3) & 1) << 4));
            }
            { uint32_t bb[2] = { bA[0], bA[2] }; mma16816(acc[0], a, bb); }
            { uint32_t bb[2] = { bA[1], bA[3] }; mma16816(acc[1], a, bb); }
            { uint32_t bb[2] = { bB[0], bB[2] }; mma16816(acc[2], a, bb); }
            { uint32_t bb[2] = { bB[1], bB[3] }; mma16816(acc[3], a, bb); }
            { uint32_t bb[2] = { bC[0], bC[1] }; mma16816(acc[4], a, bb); }
        }
    }
    __syncthreads();
    if (tid < 160) {
        float inv = 1.f / fmaxf(sqrtf(nss), 1e-12f);
        if (tid < 80) rq[tid] = inv; else rk[tid - 80] = inv;
    }
    __syncthreads();
    {
        int row  = mt*16 + (lane >> 2);
        int colb = nh*40 + (lane & 3) * 2;
        float r0 = rq[row], r1 = rq[row + 8];
        #pragma unroll
        for (int j = 0; j < 5; j++) {
            int col = colb + j*8;
            float k0 = rk[col], k1 = rk[col + 1];
            Gm[row*81 + col]       = acc[j][0] * r0 * k0;
            Gm[row*81 + col + 1]   = acc[j][1] * r0 * k1;
            Gm[(row+8)*81 + col]   = acc[j][2] * r1 * k0;
            Gm[(row+8)*81 + col+1] = acc[j][3] * r1 * k1;
        }
    }
    __syncthreads();
    // ================= Phase 2: softmax rows =================
    if (tid < 80) {
        float* row = Gm + tid*81;
        float mx = -3.0e38f;
        for (int m = 0; m < 80; m++) mx = fmaxf(mx, row[m]);
        float s = 0.f;
        for (int m = 0; m < 80; m++) { float e = expf(row[m] - mx); row[m] = e; s += e; }
        float is = 1.f / s;
        for (int m = 0; m < 80; m++) row[m] *= is;
    }
    __syncthreads();
    #pragma unroll
    for (int it = 0; it < 10; it++) {
        int p = tid + it * 320;
        int n = p / 40, mp = p - n * 40;
        *(uint32_t*)(sm2 + OFF_PS + n*FPB + 4*mp) = pack2(Gm[n*81 + 2*mp], Gm[n*81 + 2*mp + 1]);
    }
    __syncthreads();
    uint32_t aP[5][4];
    #pragma unroll
    for (int ks = 0; ks < 5; ks++) {
        int row = mt*16 + (lane & 15);
        ldm_x4(aP[ks][0], aP[ks][1], aP[ks][2], aP[ks][3],
               ps32 + row*FPB + ks*32 + ((lane >> 4) << 4));
    }

    // ================= Phase 3: out = P@V + q*rq =================
    for (int c = 0; c < CPH; c++) {
        const float* qc = Qb + c*HW;
        const float* kc = Kb + c*HW;
        __syncthreads();
        if (axis == 0) {
            #pragma unroll
            for (int it = 0; it < 10; it++) {
                int p = tid + it * 320;
                int r = p / 40, fp2 = p - r * 40;
                float2 v = *(const float2*)(qc + r*80 + 2*fp2);
                *(uint32_t*)(sm2 + OFF_TQ + r*FPB + 4*fp2) = pack2(v.x, v.y);
            }
            #pragma unroll
            for (int it = 0; it < 10; it++) {
                int p = tid + it * 320;
                int mp = p / 80, f = p - mp * 80;
                float a0 = kc[(2*mp)*80 + f], a1 = kc[(2*mp+1)*80 + f];
                *(uint32_t*)(sm2 + OFF_TK + f*FPB + 4*mp) = pack2(a0, a1);
            }
        } else {
            #pragma unroll
            for (int it = 0; it < 10; it++) {
                int p = tid + it * 320;
                int fp2 = p / 80, r = p - fp2 * 80;
                float a0 = qc[(2*fp2)*80 + r], a1 = qc[(2*fp2+1)*80 + r];
                *(uint32_t*)(sm2 + OFF_TQ + r*FPB + 4*fp2) = pack2(a0, a1);
            }
            #pragma unroll
            for (int it = 0; it < 10; it++) {
                int p = tid + it * 320;
                int f = p / 40, mp = p - f * 40;
                float2 v = *(const float2*)(kc + f*80 + 2*mp);
                *(uint32_t*)(sm2 + OFF_TK + f*FPB + 4*mp) = pack2(v.x, v.y);
            }
        }
        __syncthreads();
        float o[5][4];
        #pragma unroll
        for (int j = 0; j < 5; j++)
            #pragma unroll
            for (int t = 0; t < 4; t++) o[j][t] = 0.f;
        #pragma unroll
        for (int ks = 0; ks < 5; ks++) {
            uint32_t bA[4], bB[4], bC[2];
            {
                int row = nh*40 + (lane & 15);
                ldm_x4(bA[0], bA[1], bA[2], bA[3],
                       tk32 + row*FPB + ks*32 + ((lane >> 4) << 4));
            }
            {
                int row = nh*40 + 16 + (lane & 15);
                ldm_x4(bB[0], bB[1], bB[2], bB[3],
                       tk32 + row*FPB + ks*32 + ((lane >> 4) << 4));
            }
            {
                int row = nh*40 + 32 + (lane & 7);
                ldm_x2(bC[0], bC[1],
                       tk32 + row*FPB + ks*32 + (((lane >> 3) & 1) << 4));
            }
            { uint32_t bb[2] = { bA[0], bA[2] }; mma16816(o[0], aP[ks], bb); }
            { uint32_t bb[2] = { bA[1], bA[3] }; mma16816(o[1], aP[ks], bb); }
            { uint32_t bb[2] = { bB[0], bB[2] }; mma16816(o[2], aP[ks], bb); }
            { uint32_t bb[2] = { bB[1], bB[3] }; mma16816(o[3], aP[ks], bb); }
            { uint32_t bb[2] = { bC[0], bC[1] }; mma16816(o[4], aP[ks], bb); }
        }
        float* ob = outb + c*HW;
        int row  = mt*16 + (lane >> 2);
        int colb = nh*40 + (lane & 3) * 2;
        #pragma unroll
        for (int j = 0; j < 5; j++) {
            int col = colb + j*8;
            #pragma unroll
            for (int half = 0; half < 2; half++) {
                int rr = row + 8*half;
                float rqi = rq[rr];
                __nv_bfloat162 q2 = *(const __nv_bfloat162*)(sm2 + OFF_TQ + rr*FPB + col*2);
                float2 qf = __bfloat1622float2(q2);
                float v0 = o[j][2*half]     + qf.x * rqi;
                float v1 = o[j][2*half + 1] + qf.y * rqi;
                if (axis == 0) {
                    float* dst = ob + rr*80 + col;
                    dst[0] = v0; dst[1] = v1;
                } else {
                    *(ob + col*80 + rr)     = v0;
                    *(ob + (col+1)*80 + rr) = v1;
                }
            }
        }
    }
}

// ---------------- launch -----------------------------------------------------
extern "C" void kernel_launch(void* const* d_in, const int* in_sizes, int n_in,
                              void* d_out, int out_size)
{
    const float* x    = (const float*)d_in[0];
    const float* ln_g = (const float*)d_in[1];
    const float* ln_b = (const float*)d_in[2];
    const float* w_in = (const float*)d_in[3];
    const float* b_in = (const float*)d_in[4];
    const float* w_out= (const float*)d_in[5];
    const float* b_out= (const float*)d_in[6];
    const float* wx7  = (const float*)d_in[7];
    const float* bx7  = (const float*)d_in[8];
    const float* wx11 = (const float*)d_in[9];
    const float* bx11 = (const float*)d_in[10];
    const float* wx21 = (const float*)d_in[11];
    const float* bx21 = (const float*)d_in[12];
    const float* wy7  = (const float*)d_in[13];
    const float* by7  = (const float*)d_in[14];
    const float* wy11 = (const float*)d_in[15];
    const float* by11 = (const float*)d_in[16];
    const float* wy21 = (const float*)d_in[17];
    const float* by21 = (const float*)d_in[18];
    float* out = (float*)d_out;

    float *pA, *pB, *pC, *pD;
    cudaGetSymbolAddress((void**)&pA, g_A);
    cudaGetSymbolAddress((void**)&pB, g_B);
    cudaGetSymbolAddress((void**)&pC, g_C);
    cudaGetSymbolAddress((void**)&pD, g_D);

    cudaFuncSetAttribute(attn_kernel, cudaFuncAttributeMaxDynamicSharedMemorySize, ATTN2_SMEM);
    cudaFuncSetAttribute(gemm_mma<false>, cudaFuncAttributeMaxDynamicSharedMemorySize, GSMEM);
    cudaFuncSetAttribute(gemm_mma<true >, cudaFuncAttributeMaxDynamicSharedMemorySize, GSMEM);

    // 1) LayerNorm: x -> A (xn)
    ln_kernel<<<(BB*HW)/256, 256>>>(x, ln_g, ln_b);
    // 2) fused depthwise convs (both dirs, one launch): A -> B (sx), A -> C (sy)
    dw_kernel<<<2*BB*CC, 256>>>(wx7, bx7, wx11, bx11, wx21, bx21,
                                wy7, by7, wy11, by11, wy21, by21, pB, pC);
    // 3) pointwise w_in: B(sx)->D=fx, C(sy)->B=fy
    dim3 gg(HW/128, CC/128, BB);
    gemm_mma<false><<<gg, 256, GSMEM>>>(w_in, pB, nullptr, b_in, 1.f, nullptr, pD);
    gemm_mma<false><<<gg, 256, GSMEM>>>(w_in, pC, nullptr, b_in, 1.f, nullptr, pB);
    // 4) cross-axis attention, both axes in one launch: -> C (att_x), A (att_y)
    attn_kernel<<<2*BB*NHEADS, 320, ATTN2_SMEM>>>(pD, pB, pC, pA);
    // 5) final pointwise: W_out@(C+A), +2*b_out, +x residual
    gemm_mma<true><<<gg, 256, GSMEM>>>(w_out, pC, pA, b_out, 2.f, x, out);
}

// round 11
// speedup vs baseline: 4.3701x; 1.0893x over previous
#include <cuda_runtime.h>
#include <cuda_bf16.h>
#include <math.h>
#include <stdint.h>

#define BB     16
#define CC     256
#define HW     6400
#define NHEADS 8
#define CPH    32

// ---------------- scratch (static device globals; no allocation) -------------
// ln: x->A(f32) | dw: A->B(bf16 sx), C(bf16 sy) | gemm_bf: B->D(bf16 fx), C->B(bf16 fy)
// attn: (D,B) -> C(f32 attx), A(f32 atty) | gemm_mma: W@(C+A)+2b+x -> out
__device__ float g_A[BB*CC*HW];
__device__ float g_B[BB*CC*HW];
__device__ float g_C[BB*CC*HW];
__device__ float g_D[BB*CC*HW];

// ================= helpers ===================================================
__device__ __forceinline__ uint32_t smem_to_u32(const void* p) {
    uint32_t a;
    asm("{ .reg .u64 t; cvta.to.shared.u64 t, %1; cvt.u32.u64 %0, t; }" : "=r"(a) : "l"(p));
    return a;
}
__device__ __forceinline__ uint32_t pack2(float x, float y) {
    __nv_bfloat162 b = __float22bfloat162_rn(make_float2(x, y));
    return *(uint32_t*)&b;
}
__device__ __forceinline__ uint32_t pk(__nv_bfloat16 a, __nv_bfloat16 b) {
    __nv_bfloat162 t(a, b); return *(uint32_t*)&t;
}
__device__ __forceinline__ void ldm_x4(uint32_t& r0, uint32_t& r1, uint32_t& r2, uint32_t& r3,
                                       uint32_t addr) {
    asm volatile("ldmatrix.sync.aligned.m8n8.x4.shared.b16 {%0,%1,%2,%3}, [%4];"
                 : "=r"(r0), "=r"(r1), "=r"(r2), "=r"(r3) : "r"(addr));
}
__device__ __forceinline__ void ldm_x4_t(uint32_t& r0, uint32_t& r1, uint32_t& r2, uint32_t& r3,
                                         uint32_t addr) {
    asm volatile("ldmatrix.sync.aligned.m8n8.x4.trans.shared.b16 {%0,%1,%2,%3}, [%4];"
                 : "=r"(r0), "=r"(r1), "=r"(r2), "=r"(r3) : "r"(addr));
}
__device__ __forceinline__ void ldm_x2(uint32_t& r0, uint32_t& r1, uint32_t addr) {
    asm volatile("ldmatrix.sync.aligned.m8n8.x2.shared.b16 {%0,%1}, [%2];"
                 : "=r"(r0), "=r"(r1) : "r"(addr));
}
__device__ __forceinline__ void mma16816(float* d, const uint32_t* a, const uint32_t* b) {
    asm volatile("mma.sync.aligned.m16n8k16.row.col.f32.bf16.bf16.f32 "
                 "{%0,%1,%2,%3}, {%4,%5,%6,%7}, {%8,%9}, {%0,%1,%2,%3};"
                 : "+f"(d[0]), "+f"(d[1]), "+f"(d[2]), "+f"(d[3])
                 : "r"(a[0]), "r"(a[1]), "r"(a[2]), "r"(a[3]), "r"(b[0]), "r"(b[1]));
}

// ---------------- LayerNorm over channels, per pixel -------------------------
__global__ __launch_bounds__(256) void ln_kernel(const float* __restrict__ x,
                                                 const float* __restrict__ gam,
                                                 const float* __restrict__ bet)
{
    int p  = blockIdx.x * 256 + threadIdx.x;
    int b  = p / HW;
    int pl = p - b * HW;
    const float* xb = x + b * CC * HW + pl;
    float s = 0.f, s2 = 0.f;
    #pragma unroll 8
    for (int c = 0; c < CC; c++) { float v = xb[c*HW]; s += v; s2 = fmaf(v, v, s2); }
    float mu  = s  * (1.f / CC);
    float var = s2 * (1.f / CC) - mu * mu;
    float inv = rsqrtf(var + 1e-5f);
    float* ob = g_A + b * CC * HW + pl;
    #pragma unroll 8
    for (int c = 0; c < CC; c++) {
        float v = xb[c*HW];
        ob[c*HW] = (v - mu) * inv * gam[c] + bet[c];
    }
}

// ---------------- fused depthwise, both dirs, bf16 output --------------------
__global__ __launch_bounds__(256) void dw_kernel(
    const float* __restrict__ wx7,  const float* __restrict__ bx7,
    const float* __restrict__ wx11, const float* __restrict__ bx11,
    const float* __restrict__ wx21, const float* __restrict__ bx21,
    const float* __restrict__ wy7,  const float* __restrict__ by7,
    const float* __restrict__ wy11, const float* __restrict__ by11,
    const float* __restrict__ wy21, const float* __restrict__ by21,
    __nv_bfloat16* __restrict__ dstX, __nv_bfloat16* __restrict__ dstY)
{
    __shared__ float pad[8000];
    __shared__ float coef[21];
    __shared__ float biasv;
    const int dir = (blockIdx.x >= BB*CC) ? 1 : 0;
    const int bc  = blockIdx.x - dir * BB * CC;
    const int c   = bc & (CC - 1);
    const float* w7  = dir ? wy7  : wx7;
    const float* w11 = dir ? wy11 : wx11;
    const float* w21 = dir ? wy21 : wx21;
    for (int i = threadIdx.x; i < 8000; i += 256) pad[i] = 0.f;
    if (threadIdx.x < 21) {
        int t = threadIdx.x - 10;
        float v = w21[c*21 + t + 10];
        if (t >= -5 && t <= 5) v += w11[c*11 + t + 5];
        if (t >= -3 && t <= 3) v += w7 [c*7  + t + 3];
        coef[threadIdx.x] = v;
    }
    if (threadIdx.x == 0) {
        biasv = (dir ? (by7[c] + by11[c] + by21[c])
                     : (bx7[c] + bx11[c] + bx21[c]));
    }
    __syncthreads();
    const float* src = g_A + bc * HW;
    for (int i = threadIdx.x; i < HW; i += 256) {
        int h = i / 80;
        int w = i - h * 80;
        if (dir == 0) pad[h*100 + 10 + w] = src[i];
        else          pad[(h + 10)*80 + w] = src[i];
    }
    __syncthreads();
    float bv = biasv;
    __nv_bfloat16* dst = (dir ? dstY : dstX) + bc * HW;
    const int stride = dir ? 80 : 1;
    for (int i = threadIdx.x; i < HW; i += 256) {
        int h = i / 80;
        int w = i - h * 80;
        const float* base = dir ? (pad + h*80 + w) : (pad + h*100 + w);
        float acc = bv;
        #pragma unroll
        for (int t = 0; t < 21; t++)
            acc = fmaf(coef[t], base[t*stride], acc);
        dst[i] = __float2bfloat16(acc);
    }
}

// ====== bf16-in / bf16-out GEMM, cp.async double-buffered A ==================
// out[o,p] = sum_k W[o,k] X[k,p] + bias[o].  X bf16 [k][HW], out bf16 [o][HW].
#define GSMEM_BF (64*1024 + 2*16*1024)

__global__ __launch_bounds__(256) void gemm_bf(
    const float* __restrict__ Wm, const __nv_bfloat16* __restrict__ X,
    const float* __restrict__ bias, __nv_bfloat16* __restrict__ out)
{
    extern __shared__ char smem[];
    char* Bs = smem;                   // 64KB weights [n][256k] bf16 swizzled
    const uint32_t Bs32 = smem_to_u32(Bs);
    const uint32_t As32 = smem_to_u32(smem + 65536);   // 2 x 16KB A chunk [k][128m]
    const int tid = threadIdx.x, wid = tid >> 5, lane = tid & 31;
    const int wm = wid >> 1, wn = wid & 1;
    const int p0 = blockIdx.x * 128, o0 = blockIdx.y * 128;
    const long xbase = (long)blockIdx.z * (CC * HW);

    // B fill (once): fp32 W -> bf16, [n][k] 16B-chunk swizzled
    #pragma unroll
    for (int it = 0; it < 16; it++) {
        int idx = tid + it * 256;
        int n = idx >> 5, kc = idx & 31;
        const float* wp = Wm + (o0 + n) * CC + kc * 8;
        float4 f0 = *(const float4*)(wp);
        float4 f1 = *(const float4*)(wp + 4);
        uint4 u;
        u.x = pack2(f0.x, f0.y); u.y = pack2(f0.z, f0.w);
        u.z = pack2(f1.x, f1.y); u.w = pack2(f1.z, f1.w);
        *(uint4*)(Bs + n * 512 + ((kc ^ (n & 7)) << 4)) = u;
    }

    float acc[2][8][4];
    #pragma unroll
    for (int i = 0; i < 2; i++)
        #pragma unroll
        for (int j = 0; j < 8; j++)
            #pragma unroll
            for (int t = 0; t < 4; t++) acc[i][j][t] = 0.f;

    // A chunk fill via cp.async: [k][m] 64x128 bf16, chunk-swizzled
    auto fillA = [&](int ch, int buf) {
        #pragma unroll
        for (int it = 0; it < 4; it++) {
            int idx = tid + it * 256;
            int k = idx >> 4, cm = idx & 15;
            const __nv_bfloat16* src = X + xbase + (long)(ch * 64 + k) * HW + p0 + cm * 8;
            uint32_t dst = As32 + buf * 16384 + k * 256 + ((cm ^ (k & 7)) << 4);
            asm volatile("cp.async.cg.shared.global [%0], [%1], 16;" :: "r"(dst), "l"(src));
        }
        asm volatile("cp.async.commit_group;" ::: "memory");
    };

    fillA(0, 0);
    for (int ch = 0; ch < 4; ch++) {
        asm volatile("cp.async.wait_group 0;" ::: "memory");
        __syncthreads();                       // A(ch) visible; MMA(ch-1) done everywhere
        if (ch < 3) fillA(ch + 1, (ch + 1) & 1);
        const uint32_t Ab = As32 + (ch & 1) * 16384;
        #pragma unroll
        for (int ks = 0; ks < 4; ks++) {
            uint32_t a[2][4];
            #pragma unroll
            for (int am = 0; am < 2; am++) {
                int krow = ks * 16 + (lane & 7) + ((lane >> 4) << 3);
                int cm   = (wm * 32 + am * 16) / 8 + ((lane >> 3) & 1);
                ldm_x4_t(a[am][0], a[am][1], a[am][2], a[am][3],
                         Ab + krow * 256 + ((cm ^ (krow & 7)) << 4));
            }
            uint32_t b[4][4];
            #pragma unroll
            for (int bp = 0; bp < 4; bp++) {
                int n  = wn * 64 + bp * 16 + (lane & 15);
                int kc = ch * 8 + ks * 2 + (lane >> 4);
                ldm_x4(b[bp][0], b[bp][1], b[bp][2], b[bp][3],
                       Bs32 + n * 512 + ((kc ^ (n & 7)) << 4));
            }
            #pragma unroll
            for (int am = 0; am < 2; am++)
                #pragma unroll
                for (int an = 0; an < 8; an++) {
                    uint32_t bb[2] = { b[an >> 1][an & 1], b[an >> 1][(an & 1) + 2] };
                    mma16816(acc[am][an], a[am], bb);
                }
        }
    }

    // epilogue: +bias, bf16, smem transpose for coalesced u32 stores
    __syncthreads();
    #pragma unroll
    for (int am = 0; am < 2; am++) {
        int m = wm * 32 + am * 16 + (lane >> 2);
        #pragma unroll
        for (int an = 0; an < 8; an++) {
            int nl = wn * 64 + an * 8 + (lane & 3) * 2;
            float b0 = bias[o0 + nl], b1 = bias[o0 + nl + 1];
            *(__nv_bfloat16*)(Bs + nl * 256 + m * 2)           = __float2bfloat16(acc[am][an][0] + b0);
            *(__nv_bfloat16*)(Bs + (nl + 1) * 256 + m * 2)     = __float2bfloat16(acc[am][an][1] + b1);
            *(__nv_bfloat16*)(Bs + nl * 256 + (m + 8) * 2)     = __float2bfloat16(acc[am][an][2] + b0);
            *(__nv_bfloat16*)(Bs + (nl + 1) * 256 + (m + 8) * 2) = __float2bfloat16(acc[am][an][3] + b1);
        }
    }
    __syncthreads();
    #pragma unroll
    for (int it = 0; it < 32; it++) {
        int idx = tid + it * 256;
        int n = idx >> 6, mu = idx & 63;
        uint32_t u = *(uint32_t*)(Bs + n * 256 + mu * 4);
        *(uint32_t*)(out + xbase + (long)(o0 + n) * HW + p0 + 2 * mu) = u;
    }
}

// ============== fp32-in GEMM (final): out = W@(X+X2) + 2b + resid ============
#define GSMEM (64*1024 + 16*1024)

template<bool RESID>
__global__ __launch_bounds__(256) void gemm_mma(
    const float* __restrict__ Wm, const float* __restrict__ X,
    const float* __restrict__ X2,
    const float* __restrict__ bias, float bscale,
    const float* __restrict__ resid, float* __restrict__ out)
{
    extern __shared__ char smem[];
    char* Bs = smem;
    char* As = smem + 65536;
    const uint32_t Bs32 = smem_to_u32(Bs);
    const uint32_t As32 = smem_to_u32(As);
    const int tid  = threadIdx.x;
    const int wid  = tid >> 5, lane = tid & 31;
    const int wm   = wid >> 1,  wn  = wid & 1;
    const int p0   = blockIdx.x * 128;
    const int o0   = blockIdx.y * 128;
    const int xbase = blockIdx.z * (CC * HW);

    #pragma unroll
    for (int it = 0; it < 16; it++) {
        int idx = tid + it * 256;
        int n = idx >> 5, kc = idx & 31;
        const float* wp = Wm + (o0 + n) * CC + kc * 8;
        float4 f0 = *(const float4*)(wp);
        float4 f1 = *(const float4*)(wp + 4);
        uint4 u;
        u.x = pack2(f0.x, f0.y); u.y = pack2(f0.z, f0.w);
        u.z = pack2(f1.x, f1.y); u.w = pack2(f1.z, f1.w);
        *(uint4*)(Bs + n * 512 + ((kc ^ (n & 7)) << 4)) = u;
    }

    float acc[2][8][4];
    #pragma unroll
    for (int i = 0; i < 2; i++)
        #pragma unroll
        for (int j = 0; j < 8; j++)
            #pragma unroll
            for (int t = 0; t < 4; t++) acc[i][j][t] = 0.f;

    for (int ch = 0; ch < 4; ch++) {
        __syncthreads();
        #pragma unroll
        for (int it = 0; it < 4; it++) {
            int idx = tid + it * 256;
            int m = idx & 127, kq = idx >> 7;
            long off = (long)xbase + (long)(ch * 64 + kq * 8) * HW + p0 + m;
            const float* xp = X + off;
            float v[8];
            #pragma unroll
            for (int u2 = 0; u2 < 8; u2++) v[u2] = xp[u2*HW];
            if (RESID) {
                const float* yp = X2 + off;
                #pragma unroll
                for (int u2 = 0; u2 < 8; u2++) v[u2] += yp[u2*HW];
            }
            uint4 u;
            u.x = pack2(v[0], v[1]); u.y = pack2(v[2], v[3]);
            u.z = pack2(v[4], v[5]); u.w = pack2(v[6], v[7]);
            *(uint4*)(As + m * 128 + ((kq ^ (m & 7)) << 4)) = u;
        }
        __syncthreads();
        #pragma unroll
        for (int ks = 0; ks < 4; ks++) {
            uint32_t a[2][4];
            #pragma unroll
            for (int am = 0; am < 2; am++) {
                int row = wm * 32 + am * 16 + (lane & 15);
                int chk = (ks * 2 + (lane >> 4)) ^ (row & 7);
                ldm_x4(a[am][0], a[am][1], a[am][2], a[am][3],
                       As32 + row * 128 + (chk << 4));
            }
            uint32_t b[4][4];
            #pragma unroll
            for (int bp = 0; bp < 4; bp++) {
                int n  = wn * 64 + bp * 16 + (lane & 15);
                int kc = ch * 8 + ks * 2 + (lane >> 4);
                ldm_x4(b[bp][0], b[bp][1], b[bp][2], b[bp][3],
                       Bs32 + n * 512 + ((kc ^ (n & 7)) << 4));
            }
            #pragma unroll
            for (int am = 0; am < 2; am++)
                #pragma unroll
                for (int an = 0; an < 8; an++) {
                    uint32_t bb[2] = { b[an >> 1][an & 1], b[an >> 1][(an & 1) + 2] };
                    mma16816(acc[am][an], a[am], bb);
                }
        }
    }

    #pragma unroll
    for (int am = 0; am < 2; am++) {
        int m = wm * 32 + am * 16 + (lane >> 2);
        #pragma unroll
        for (int an = 0; an < 8; an++) {
            int n = o0 + wn * 64 + an * 8 + (lane & 3) * 2;
            float b0 = bias[n] * bscale, b1 = bias[n + 1] * bscale;
            long a00 = (long)xbase + (long)n * HW + p0 + m;
            float v0 = acc[am][an][0] + b0;
            float v1 = acc[am][an][1] + b1;
            float v2 = acc[am][an][2] + b0;
            float v3 = acc[am][an][3] + b1;
            if (RESID) {
                v0 += resid[a00];      v1 += resid[a00 + HW];
                v2 += resid[a00 + 8];  v3 += resid[a00 + HW + 8];
            }
            out[a00]          = v0;  out[a00 + HW]     = v1;
            out[a00 + 8]      = v2;  out[a00 + HW + 8] = v3;
        }
    }
}

// ======== cross-axis attention, both axes in ONE launch, bf16 inputs =========
#define FPB 176
#define OFF_TQ 0
#define OFF_TK 14080
#define OFF_PS 28160
#define OFF_GM 42240
#define OFF_RQ 68160
#define OFF_RK 68480
#define ATTN2_SMEM 68800

__global__ __launch_bounds__(320, 2) void attn_kernel(
    const __nv_bfloat16* __restrict__ fx, const __nv_bfloat16* __restrict__ fy,
    float* __restrict__ outx, float* __restrict__ outy)
{
    extern __shared__ char sm2[];
    float* Gm = (float*)(sm2 + OFF_GM);
    float* rq = (float*)(sm2 + OFF_RQ);
    float* rk = (float*)(sm2 + OFF_RK);
    const uint32_t tq32 = smem_to_u32(sm2 + OFF_TQ);
    const uint32_t tk32 = smem_to_u32(sm2 + OFF_TK);
    const uint32_t ps32 = smem_to_u32(sm2 + OFF_PS);

    const int axis = blockIdx.x >> 7;
    const int bh   = blockIdx.x & 127;
    const int cbase = (bh >> 3) * (CC*HW) + (bh & 7) * (CPH*HW);
    const __nv_bfloat16* Qb = (axis ? fx : fy) + cbase;
    const __nv_bfloat16* Kb = (axis ? fy : fx) + cbase;
    float* outb     = (axis ? outy : outx) + cbase;
    const int tid  = threadIdx.x;
    const int wid  = tid >> 5, lane = tid & 31;
    const int mt   = wid >> 1, nh = wid & 1;

    float acc[5][4];
    #pragma unroll
    for (int j = 0; j < 5; j++)
        #pragma unroll
        for (int t = 0; t < 4; t++) acc[j][t] = 0.f;
    float nss = 0.f;

    // ================= Phase 1: raw Gram + fused sumsq =================
    for (int c = 0; c < CPH; c++) {
        const __nv_bfloat16* qc = Qb + c*HW;
        const __nv_bfloat16* kc = Kb + c*HW;
        __syncthreads();
        if (axis == 0) {
            #pragma unroll
            for (int it = 0; it < 10; it++) {
                int p = tid + it * 320;
                int r = p / 40, fp2 = p - r * 40;
                *(uint32_t*)(sm2 + OFF_TQ + r*FPB + 4*fp2) = *(const uint32_t*)(qc + r*80 + 2*fp2);
                *(uint32_t*)(sm2 + OFF_TK + r*FPB + 4*fp2) = *(const uint32_t*)(kc + r*80 + 2*fp2);
            }
        } else {
            #pragma unroll
            for (int it = 0; it < 10; it++) {
                int p = tid + it * 320;
                int fp2 = p / 80, r = p - fp2 * 80;
                *(uint32_t*)(sm2 + OFF_TQ + r*FPB + 4*fp2) = pk(qc[(2*fp2)*80 + r], qc[(2*fp2+1)*80 + r]);
                *(uint32_t*)(sm2 + OFF_TK + r*FPB + 4*fp2) = pk(kc[(2*fp2)*80 + r], kc[(2*fp2+1)*80 + r]);
            }
        }
        __syncthreads();
        if (tid < 160) {
            const char* rowp = (tid < 80) ? (sm2 + OFF_TQ + tid*FPB)
                                          : (sm2 + OFF_TK + (tid-80)*FPB);
            float s = 0.f;
            #pragma unroll 8
            for (int u = 0; u < 40; u++) {
                __nv_bfloat162 h2 = *(const __nv_bfloat162*)(rowp + 4*u);
                float2 f2 = __bfloat1622float2(h2);
                s = fmaf(f2.x, f2.x, fmaf(f2.y, f2.y, s));
            }
            nss += s;
        }
        #pragma unroll
        for (int ks = 0; ks < 5; ks++) {
            uint32_t a[4];
            {
                int row = mt*16 + (lane & 15);
                ldm_x4(a[0], a[1], a[2], a[3],
                       tq32 + row*FPB + ks*32 + ((lane >> 4) << 4));
            }
            uint32_t bA[4], bB[4], bC[2];
            {
                int row = nh*40 + (lane & 15);
                ldm_x4(bA[0], bA[1], bA[2], bA[3],
                       tk32 + row*FPB + ks*32 + ((lane >> 4) << 4));
            }
            {
                int row = nh*40 + 16 + (lane & 15);
                ldm_x4(bB[0], bB[1], bB[2], bB[3],
                       tk32 + row*FPB + ks*32 + ((lane >> 4) << 4));
            }
            {
                int row = nh*40 + 32 + (lane & 7);
                ldm_x2(bC[0], bC[1],
                       tk32 + row*FPB + ks*32 + (((lane >> 3) & 1) << 4));
            }
            { uint32_t bb[2] = { bA[0], bA[2] }; mma16816(acc[0], a, bb); }
            { uint32_t bb[2] = { bA[1], bA[3] }; mma16816(acc[1], a, bb); }
            { uint32_t bb[2] = { bB[0], bB[2] }; mma16816(acc[2], a, bb); }
            { uint32_t bb[2] = { bB[1], bB[3] }; mma16816(acc[3], a, bb); }
            { uint32_t bb[2] = { bC[0], bC[1] }; mma16816(acc[4], a, bb); }
        }
    }
    __syncthreads();
    if (tid < 160) {
        float inv = 1.f / fmaxf(sqrtf(nss), 1e-12f);
        if (tid < 80) rq[tid] = inv; else rk[tid - 80] = inv;
    }
    __syncthreads();
    {
        int row  = mt*16 + (lane >> 2);
        int colb = nh*40 + (lane & 3) * 2;
        float r0 = rq[row], r1 = rq[row + 8];
        #pragma unroll
        for (int j = 0; j < 5; j++) {
            int col = colb + j*8;
            float k0 = rk[col], k1 = rk[col + 1];
            Gm[row*81 + col]       = acc[j][0] * r0 * k0;
            Gm[row*81 + col + 1]   = acc[j][1] * r0 * k1;
            Gm[(row+8)*81 + col]   = acc[j][2] * r1 * k0;
            Gm[(row+8)*81 + col+1] = acc[j][3] * r1 * k1;
        }
    }
    __syncthreads();
    // ================= Phase 2: softmax rows =================
    if (tid < 80) {
        float* row = Gm + tid*81;
        float mx = -3.0e38f;
        for (int m = 0; m < 80; m++) mx = fmaxf(mx, row[m]);
        float s = 0.f;
        for (int m = 0; m < 80; m++) { float e = expf(row[m] - mx); row[m] = e; s += e; }
        float is = 1.f / s;
        for (int m = 0; m < 80; m++) row[m] *= is;
    }
    __syncthreads();
    #pragma unroll
    for (int it = 0; it < 10; it++) {
        int p = tid + it * 320;
        int n = p / 40, mp = p - n * 40;
        *(uint32_t*)(sm2 + OFF_PS + n*FPB + 4*mp) = pack2(Gm[n*81 + 2*mp], Gm[n*81 + 2*mp + 1]);
    }
    __syncthreads();
    uint32_t aP[5][4];
    #pragma unroll
    for (int ks = 0; ks < 5; ks++) {
        int row = mt*16 + (lane & 15);
        ldm_x4(aP[ks][0], aP[ks][1], aP[ks][2], aP[ks][3],
               ps32 + row*FPB + ks*32 + ((lane >> 4) << 4));
    }

    // ================= Phase 3: out = P@V + q*rq =================
    for (int c = 0; c < CPH; c++) {
        const __nv_bfloat16* qc = Qb + c*HW;
        const __nv_bfloat16* kc = Kb + c*HW;
        __syncthreads();
        if (axis == 0) {
            #pragma unroll
            for (int it = 0; it < 10; it++) {
                int p = tid + it * 320;
                int r = p / 40, fp2 = p - r * 40;
                *(uint32_t*)(sm2 + OFF_TQ + r*FPB + 4*fp2) = *(const uint32_t*)(qc + r*80 + 2*fp2);
            }
            #pragma unroll
            for (int it = 0; it < 10; it++) {
                int p = tid + it * 320;
                int mp = p / 80, f = p - mp * 80;
                *(uint32_t*)(sm2 + OFF_TK + f*FPB + 4*mp) = pk(kc[(2*mp)*80 + f], kc[(2*mp+1)*80 + f]);
            }
        } else {
            #pragma unroll
            for (int it = 0; it < 10; it++) {
                int p = tid + it * 320;
                int fp2 = p / 80, r = p - fp2 * 80;
                *(uint32_t*)(sm2 + OFF_TQ + r*FPB + 4*fp2) = pk(qc[(2*fp2)*80 + r], qc[(2*fp2+1)*80 + r]);
            }
            #pragma unroll
            for (int it = 0; it < 10; it++) {
                int p = tid + it * 320;
                int f = p / 40, mp = p - f * 40;
                *(uint32_t*)(sm2 + OFF_TK + f*FPB + 4*mp) = *(const uint32_t*)(kc + f*80 + 2*mp);
            }
        }
        __syncthreads();
        float o[5][4];
        #pragma unroll
        for (int j = 0; j < 5; j++)
            #pragma unroll
            for (int t = 0; t < 4; t++) o[j][t] = 0.f;
        #pragma unroll
        for (int ks = 0; ks < 5; ks++) {
            uint32_t bA[4], bB[4], bC[2];
            {
                int row = nh*40 + (lane & 15);
                ldm_x4(bA[0], bA[1], bA[2], bA[3],
                       tk32 + row*FPB + ks*32 + ((lane >> 4) << 4));
            }
            {
                int row = nh*40 + 16 + (lane & 15);
                ldm_x4(bB[0], bB[1], bB[2], bB[3],
                       tk32 + row*FPB + ks*32 + ((lane >> 4) << 4));
            }
            {
                int row = nh*40 + 32 + (lane & 7);
                ldm_x2(bC[0], bC[1],
                       tk32 + row*FPB + ks*32 + (((lane >> 3) & 1) << 4));
            }
            { uint32_t bb[2] = { bA[0], bA[2] }; mma16816(o[0], aP[ks], bb); }
            { uint32_t bb[2] = { bA[1], bA[3] }; mma16816(o[1], aP[ks], bb); }
            { uint32_t bb[2] = { bB[0], bB[2] }; mma16816(o[2], aP[ks], bb); }
            { uint32_t bb[2] = { bB[1], bB[3] }; mma16816(o[3], aP[ks], bb); }
            { uint32_t bb[2] = { bC[0], bC[1] }; mma16816(o[4], aP[ks], bb); }
        }
        float* ob = outb + c*HW;
        int row  = mt*16 + (lane >> 2);
        int colb = nh*40 + (lane & 3) * 2;
        #pragma unroll
        for (int j = 0; j < 5; j++) {
            int col = colb + j*8;
            #pragma unroll
            for (int half = 0; half < 2; half++) {
                int rr = row + 8*half;
                float rqi = rq[rr];
                __nv_bfloat162 q2 = *(const __nv_bfloat162*)(sm2 + OFF_TQ + rr*FPB + col*2);
                float2 qf = __bfloat1622float2(q2);
                float v0 = o[j][2*half]     + qf.x * rqi;
                float v1 = o[j][2*half + 1] + qf.y * rqi;
                if (axis == 0) {
                    float* dst = ob + rr*80 + col;
                    dst[0] = v0; dst[1] = v1;
                } else {
                    *(ob + col*80 + rr)     = v0;
                    *(ob + (col+1)*80 + rr) = v1;
                }
            }
        }
    }
}

// ---------------- launch -----------------------------------------------------
extern "C" void kernel_launch(void* const* d_in, const int* in_sizes, int n_in,
                              void* d_out, int out_size)
{
    const float* x    = (const float*)d_in[0];
    const float* ln_g = (const float*)d_in[1];
    const float* ln_b = (const float*)d_in[2];
    const float* w_in = (const float*)d_in[3];
    const float* b_in = (const float*)d_in[4];
    const float* w_out= (const float*)d_in[5];
    const float* b_out= (const float*)d_in[6];
    const float* wx7  = (const float*)d_in[7];
    const float* bx7  = (const float*)d_in[8];
    const float* wx11 = (const float*)d_in[9];
    const float* bx11 = (const float*)d_in[10];
    const float* wx21 = (const float*)d_in[11];
    const float* bx21 = (const float*)d_in[12];
    const float* wy7  = (const float*)d_in[13];
    const float* by7  = (const float*)d_in[14];
    const float* wy11 = (const float*)d_in[15];
    const float* by11 = (const float*)d_in[16];
    const float* wy21 = (const float*)d_in[17];
    const float* by21 = (const float*)d_in[18];
    float* out = (float*)d_out;

    float *pA, *pB, *pC, *pD;
    cudaGetSymbolAddress((void**)&pA, g_A);
    cudaGetSymbolAddress((void**)&pB, g_B);
    cudaGetSymbolAddress((void**)&pC, g_C);
    cudaGetSymbolAddress((void**)&pD, g_D);
    __nv_bfloat16* hB = (__nv_bfloat16*)pB;
    __nv_bfloat16* hC = (__nv_bfloat16*)pC;
    __nv_bfloat16* hD = (__nv_bfloat16*)pD;

    cudaFuncSetAttribute(attn_kernel, cudaFuncAttributeMaxDynamicSharedMemorySize, ATTN2_SMEM);
    cudaFuncSetAttribute(gemm_bf, cudaFuncAttributeMaxDynamicSharedMemorySize, GSMEM_BF);
    cudaFuncSetAttribute(gemm_mma<true>, cudaFuncAttributeMaxDynamicSharedMemorySize, GSMEM);

    // 1) LayerNorm: x -> A (fp32 xn)
    ln_kernel<<<(BB*HW)/256, 256>>>(x, ln_g, ln_b);
    // 2) depthwise (both dirs): A -> B (bf16 sx), C (bf16 sy)
    dw_kernel<<<2*BB*CC, 256>>>(wx7, bx7, wx11, bx11, wx21, bx21,
                                wy7, by7, wy11, by11, wy21, by21, hB, hC);
    // 3) pointwise w_in (bf16 in/out, cp.async pipelined): B->D (fx), C->B (fy)
    dim3 gg(HW/128, CC/128, BB);
    gemm_bf<<<gg, 256, GSMEM_BF>>>(w_in, hB, b_in, hD);
    gemm_bf<<<gg, 256, GSMEM_BF>>>(w_in, hC, b_in, hB);
    // 4) cross-axis attention (both axes, one launch): -> C (attx), A (atty) fp32
    attn_kernel<<<2*BB*NHEADS, 320, ATTN2_SMEM>>>(hD, hB, pC, pA);
    // 5) final pointwise: W_out@(C+A) + 2*b_out + x residual
    gemm_mma<true><<<gg, 256, GSMEM>>>(w_out, pC, pA, b_out, 2.f, x, out);
}

// round 12
// speedup vs baseline: 5.4313x; 1.2428x over previous
#include <cuda_runtime.h>
#include <cuda_bf16.h>
#include <math.h>
#include <stdint.h>

#define BB     16
#define CC     256
#define HW     6400
#define NHEADS 8
#define CPH    32

// ---------------- scratch (static device globals; no allocation) -------------
// ln: x->A(bf16 xn) | dw: A->B(bf16 sx), C(bf16 sy)
// gemm_bf: B->D(bf16 fx), C->B(bf16 fy)
// attn: (D,B) -> C(bf16 attx), A(bf16 atty)
// gemm_out: W@(C+A) + 2b + x -> out (fp32)
__device__ float g_A[BB*CC*HW];
__device__ float g_B[BB*CC*HW];
__device__ float g_C[BB*CC*HW];
__device__ float g_D[BB*CC*HW];

// ================= helpers ===================================================
__device__ __forceinline__ uint32_t smem_to_u32(const void* p) {
    uint32_t a;
    asm("{ .reg .u64 t; cvta.to.shared.u64 t, %1; cvt.u32.u64 %0, t; }" : "=r"(a) : "l"(p));
    return a;
}
__device__ __forceinline__ uint32_t pack2(float x, float y) {
    __nv_bfloat162 b = __float22bfloat162_rn(make_float2(x, y));
    return *(uint32_t*)&b;
}
__device__ __forceinline__ uint32_t pk(__nv_bfloat16 a, __nv_bfloat16 b) {
    __nv_bfloat162 t(a, b); return *(uint32_t*)&t;
}
__device__ __forceinline__ uint32_t hadd2u(uint32_t a, uint32_t b) {
    __nv_bfloat162 x = *(__nv_bfloat162*)&a, y = *(__nv_bfloat162*)&b;
    __nv_bfloat162 r = __hadd2(x, y);
    return *(uint32_t*)&r;
}
__device__ __forceinline__ void ldm_x4(uint32_t& r0, uint32_t& r1, uint32_t& r2, uint32_t& r3,
                                       uint32_t addr) {
    asm volatile("ldmatrix.sync.aligned.m8n8.x4.shared.b16 {%0,%1,%2,%3}, [%4];"
                 : "=r"(r0), "=r"(r1), "=r"(r2), "=r"(r3) : "r"(addr));
}
__device__ __forceinline__ void ldm_x4_t(uint32_t& r0, uint32_t& r1, uint32_t& r2, uint32_t& r3,
                                         uint32_t addr) {
    asm volatile("ldmatrix.sync.aligned.m8n8.x4.trans.shared.b16 {%0,%1,%2,%3}, [%4];"
                 : "=r"(r0), "=r"(r1), "=r"(r2), "=r"(r3) : "r"(addr));
}
__device__ __forceinline__ void ldm_x2(uint32_t& r0, uint32_t& r1, uint32_t addr) {
    asm volatile("ldmatrix.sync.aligned.m8n8.x2.shared.b16 {%0,%1}, [%2];"
                 : "=r"(r0), "=r"(r1) : "r"(addr));
}
__device__ __forceinline__ void mma16816(float* d, const uint32_t* a, const uint32_t* b) {
    asm volatile("mma.sync.aligned.m16n8k16.row.col.f32.bf16.bf16.f32 "
                 "{%0,%1,%2,%3}, {%4,%5,%6,%7}, {%8,%9}, {%0,%1,%2,%3};"
                 : "+f"(d[0]), "+f"(d[1]), "+f"(d[2]), "+f"(d[3])
                 : "r"(a[0]), "r"(a[1]), "r"(a[2]), "r"(a[3]), "r"(b[0]), "r"(b[1]));
}

// ---------------- LayerNorm over channels, per pixel (bf16 out) --------------
__global__ __launch_bounds__(256) void ln_kernel(const float* __restrict__ x,
                                                 const float* __restrict__ gam,
                                                 const float* __restrict__ bet,
                                                 __nv_bfloat16* __restrict__ xn)
{
    int p  = blockIdx.x * 256 + threadIdx.x;
    int b  = p / HW;
    int pl = p - b * HW;
    const float* xb = x + b * CC * HW + pl;
    float s = 0.f, s2 = 0.f;
    #pragma unroll 8
    for (int c = 0; c < CC; c++) { float v = xb[c*HW]; s += v; s2 = fmaf(v, v, s2); }
    float mu  = s  * (1.f / CC);
    float var = s2 * (1.f / CC) - mu * mu;
    float inv = rsqrtf(var + 1e-5f);
    __nv_bfloat16* ob = xn + b * CC * HW + pl;
    #pragma unroll 8
    for (int c = 0; c < CC; c++) {
        float v = xb[c*HW];
        ob[c*HW] = __float2bfloat16((v - mu) * inv * gam[c] + bet[c]);
    }
}

// ---------------- fused depthwise, both dirs, bf16 HFMA2 2-wide --------------
// dir0 (conv along w): pairs packed along h. dir1 (conv along h): pairs along w.
__global__ __launch_bounds__(256) void dw_kernel(
    const __nv_bfloat16* __restrict__ xn,
    const float* __restrict__ wx7,  const float* __restrict__ bx7,
    const float* __restrict__ wx11, const float* __restrict__ bx11,
    const float* __restrict__ wx21, const float* __restrict__ bx21,
    const float* __restrict__ wy7,  const float* __restrict__ by7,
    const float* __restrict__ wy11, const float* __restrict__ by11,
    const float* __restrict__ wy21, const float* __restrict__ by21,
    __nv_bfloat16* __restrict__ dstX, __nv_bfloat16* __restrict__ dstY)
{
    __shared__ uint32_t pad[4000];       // dir0: [40 h2][100 wp]; dir1: [100 hp][40 w2]
    __shared__ __nv_bfloat162 coef2[21];
    __shared__ float biasv;
    const int tid = threadIdx.x;
    const int dir = (blockIdx.x >= BB*CC) ? 1 : 0;
    const int bc  = blockIdx.x - dir * BB * CC;
    const int c   = bc & (CC - 1);
    const float* w7  = dir ? wy7  : wx7;
    const float* w11 = dir ? wy11 : wx11;
    const float* w21 = dir ? wy21 : wx21;
    for (int i = tid; i < 4000; i += 256) pad[i] = 0;
    if (tid < 21) {
        int t = tid - 10;
        float v = w21[c*21 + t + 10];
        if (t >= -5 && t <= 5) v += w11[c*11 + t + 5];
        if (t >= -3 && t <= 3) v += w7 [c*7  + t + 3];
        coef2[tid] = __float2bfloat162_rn(v);
    }
    if (tid == 0) {
        biasv = (dir ? (by7[c] + by11[c] + by21[c])
                     : (bx7[c] + bx11[c] + bx21[c]));
    }
    __syncthreads();
    const uint32_t* src32 = (const uint32_t*)(xn + bc * HW);
    if (dir == 0) {
        for (int i = tid; i < 1600; i += 256) {
            int h2 = i / 40, wp2 = i - h2 * 40;
            uint32_t a01 = src32[(2*h2)*40 + wp2];      // x[2h2][2wp2], x[2h2][2wp2+1]
            uint32_t b01 = src32[(2*h2+1)*40 + wp2];
            pad[h2*100 + 10 + 2*wp2] = __byte_perm(a01, b01, 0x5410);  // (row even, row odd) at w=2wp2
            pad[h2*100 + 11 + 2*wp2] = __byte_perm(a01, b01, 0x7632);  // at w=2wp2+1
        }
    } else {
        for (int i = tid; i < 3200; i += 256) {
            int h = i / 40, w2 = i - h * 40;
            pad[(h + 10)*40 + w2] = src32[i];
        }
    }
    __syncthreads();
    const __nv_bfloat162 bias2 = __float2bfloat162_rn(biasv);
    const __nv_bfloat162 z2    = __float2bfloat162_rn(0.f);
    uint32_t* dst32 = (uint32_t*)((dir ? dstY : dstX) + bc * HW);
    for (int i = tid; i < 1600; i += 256) {
        int h2 = i / 40, w2 = i - h2 * 40;
        uint32_t win[22];
        if (dir == 0) {
            #pragma unroll
            for (int t = 0; t < 22; t++) win[t] = pad[h2*100 + 2*w2 + t];
        } else {
            #pragma unroll
            for (int t = 0; t < 22; t++) win[t] = pad[(2*h2 + t)*40 + w2];
        }
        __nv_bfloat162 ae = bias2, ao = z2, be = bias2, bo = z2;
        #pragma unroll
        for (int t = 0; t < 21; t++) {
            __nv_bfloat162 w0 = *(__nv_bfloat162*)&win[t];
            __nv_bfloat162 w1 = *(__nv_bfloat162*)&win[t + 1];
            if (t & 1) { ao = __hfma2(coef2[t], w0, ao); bo = __hfma2(coef2[t], w1, bo); }
            else       { ae = __hfma2(coef2[t], w0, ae); be = __hfma2(coef2[t], w1, be); }
        }
        __nv_bfloat162 A2 = __hadd2(ae, ao);
        __nv_bfloat162 B2 = __hadd2(be, bo);
        uint32_t uA = *(uint32_t*)&A2, uB = *(uint32_t*)&B2;
        if (dir == 0) {
            // A2 = outputs at w=2w2 for rows (2h2, 2h2+1); B2 at w=2w2+1
            dst32[(2*h2)*40 + w2]   = __byte_perm(uA, uB, 0x5410);
            dst32[(2*h2+1)*40 + w2] = __byte_perm(uA, uB, 0x7632);
        } else {
            // A2 = row 2h2 (w pair), B2 = row 2h2+1
            dst32[(2*h2)*40 + w2]   = uA;
            dst32[(2*h2+1)*40 + w2] = uB;
        }
    }
}

// ====== bf16-in / bf16-out GEMM, cp.async double-buffered A ==================
#define GSMEM_BF (64*1024 + 2*16*1024)

__global__ __launch_bounds__(256) void gemm_bf(
    const float* __restrict__ Wm, const __nv_bfloat16* __restrict__ X,
    const float* __restrict__ bias, __nv_bfloat16* __restrict__ out)
{
    extern __shared__ char smem[];
    char* Bs = smem;
    const uint32_t Bs32 = smem_to_u32(Bs);
    const uint32_t As32 = smem_to_u32(smem + 65536);
    const int tid = threadIdx.x, wid = tid >> 5, lane = tid & 31;
    const int wm = wid >> 1, wn = wid & 1;
    const int p0 = blockIdx.x * 128, o0 = blockIdx.y * 128;
    const long xbase = (long)blockIdx.z * (CC * HW);

    #pragma unroll
    for (int it = 0; it < 16; it++) {
        int idx = tid + it * 256;
        int n = idx >> 5, kc = idx & 31;
        const float* wp = Wm + (o0 + n) * CC + kc * 8;
        float4 f0 = *(const float4*)(wp);
        float4 f1 = *(const float4*)(wp + 4);
        uint4 u;
        u.x = pack2(f0.x, f0.y); u.y = pack2(f0.z, f0.w);
        u.z = pack2(f1.x, f1.y); u.w = pack2(f1.z, f1.w);
        *(uint4*)(Bs + n * 512 + ((kc ^ (n & 7)) << 4)) = u;
    }

    float acc[2][8][4];
    #pragma unroll
    for (int i = 0; i < 2; i++)
        #pragma unroll
        for (int j = 0; j < 8; j++)
            #pragma unroll
            for (int t = 0; t < 4; t++) acc[i][j][t] = 0.f;

    auto fillA = [&](int ch, int buf) {
        #pragma unroll
        for (int it = 0; it < 4; it++) {
            int idx = tid + it * 256;
            int k = idx >> 4, cm = idx & 15;
            const __nv_bfloat16* src = X + xbase + (long)(ch * 64 + k) * HW + p0 + cm * 8;
            uint32_t dst = As32 + buf * 16384 + k * 256 + ((cm ^ (k & 7)) << 4);
            asm volatile("cp.async.cg.shared.global [%0], [%1], 16;" :: "r"(dst), "l"(src));
        }
        asm volatile("cp.async.commit_group;" ::: "memory");
    };

    fillA(0, 0);
    for (int ch = 0; ch < 4; ch++) {
        asm volatile("cp.async.wait_group 0;" ::: "memory");
        __syncthreads();
        if (ch < 3) fillA(ch + 1, (ch + 1) & 1);
        const uint32_t Ab = As32 + (ch & 1) * 16384;
        #pragma unroll
        for (int ks = 0; ks < 4; ks++) {
            uint32_t a[2][4];
            #pragma unroll
            for (int am = 0; am < 2; am++) {
                int krow = ks * 16 + (lane & 7) + ((lane >> 4) << 3);
                int cm   = (wm * 32 + am * 16) / 8 + ((lane >> 3) & 1);
                ldm_x4_t(a[am][0], a[am][1], a[am][2], a[am][3],
                         Ab + krow * 256 + ((cm ^ (krow & 7)) << 4));
            }
            uint32_t b[4][4];
            #pragma unroll
            for (int bp = 0; bp < 4; bp++) {
                int n  = wn * 64 + bp * 16 + (lane & 15);
                int kc = ch * 8 + ks * 2 + (lane >> 4);
                ldm_x4(b[bp][0], b[bp][1], b[bp][2], b[bp][3],
                       Bs32 + n * 512 + ((kc ^ (n & 7)) << 4));
            }
            #pragma unroll
            for (int am = 0; am < 2; am++)
                #pragma unroll
                for (int an = 0; an < 8; an++) {
                    uint32_t bb[2] = { b[an >> 1][an & 1], b[an >> 1][(an & 1) + 2] };
                    mma16816(acc[am][an], a[am], bb);
                }
        }
    }

    __syncthreads();
    #pragma unroll
    for (int am = 0; am < 2; am++) {
        int m = wm * 32 + am * 16 + (lane >> 2);
        #pragma unroll
        for (int an = 0; an < 8; an++) {
            int nl = wn * 64 + an * 8 + (lane & 3) * 2;
            float b0 = bias[o0 + nl], b1 = bias[o0 + nl + 1];
            *(__nv_bfloat16*)(Bs + nl * 256 + m * 2)             = __float2bfloat16(acc[am][an][0] + b0);
            *(__nv_bfloat16*)(Bs + (nl + 1) * 256 + m * 2)       = __float2bfloat16(acc[am][an][1] + b1);
            *(__nv_bfloat16*)(Bs + nl * 256 + (m + 8) * 2)       = __float2bfloat16(acc[am][an][2] + b0);
            *(__nv_bfloat16*)(Bs + (nl + 1) * 256 + (m + 8) * 2) = __float2bfloat16(acc[am][an][3] + b1);
        }
    }
    __syncthreads();
    #pragma unroll
    for (int it = 0; it < 32; it++) {
        int idx = tid + it * 256;
        int n = idx >> 6, mu = idx & 63;
        uint32_t u = *(uint32_t*)(Bs + n * 256 + mu * 4);
        *(uint32_t*)(out + xbase + (long)(o0 + n) * HW + p0 + 2 * mu) = u;
    }
}

// ====== final GEMM: out = W@(X+X2) + 2b + resid, bf16 in, cp.async ==========
#define GSMEM_OUT (64*1024 + 32*1024)

__global__ __launch_bounds__(256) void gemm_out(
    const float* __restrict__ Wm, const __nv_bfloat16* __restrict__ X,
    const __nv_bfloat16* __restrict__ X2,
    const float* __restrict__ bias, const float* __restrict__ resid,
    float* __restrict__ out)
{
    extern __shared__ char smem[];
    char* Bs = smem;
    const uint32_t Bs32 = smem_to_u32(Bs);
    const uint32_t As32 = smem_to_u32(smem + 65536);  // 2 buf x (X 8KB + X2 8KB)
    const int tid = threadIdx.x, wid = tid >> 5, lane = tid & 31;
    const int wm = wid >> 1, wn = wid & 1;
    const int p0 = blockIdx.x * 128, o0 = blockIdx.y * 128;
    const long xbase = (long)blockIdx.z * (CC * HW);

    #pragma unroll
    for (int it = 0; it < 16; it++) {
        int idx = tid + it * 256;
        int n = idx >> 5, kc = idx & 31;
        const float* wp = Wm + (o0 + n) * CC + kc * 8;
        float4 f0 = *(const float4*)(wp);
        float4 f1 = *(const float4*)(wp + 4);
        uint4 u;
        u.x = pack2(f0.x, f0.y); u.y = pack2(f0.z, f0.w);
        u.z = pack2(f1.x, f1.y); u.w = pack2(f1.z, f1.w);
        *(uint4*)(Bs + n * 512 + ((kc ^ (n & 7)) << 4)) = u;
    }

    float acc[2][8][4];
    #pragma unroll
    for (int i = 0; i < 2; i++)
        #pragma unroll
        for (int j = 0; j < 8; j++)
            #pragma unroll
            for (int t = 0; t < 4; t++) acc[i][j][t] = 0.f;

    auto fillA = [&](int ch, int buf) {
        #pragma unroll
        for (int it = 0; it < 2; it++) {
            int idx = tid + it * 256;
            int k = idx >> 4, cm = idx & 15;     // k in [0,32)
            long off = xbase + (long)(ch * 32 + k) * HW + p0 + cm * 8;
            uint32_t dst = As32 + buf * 16384 + k * 256 + ((cm ^ (k & 7)) << 4);
            const __nv_bfloat16* s1 = X  + off;
            const __nv_bfloat16* s2 = X2 + off;
            asm volatile("cp.async.cg.shared.global [%0], [%1], 16;" :: "r"(dst), "l"(s1));
            asm volatile("cp.async.cg.shared.global [%0], [%1], 16;" :: "r"(dst + 8192), "l"(s2));
        }
        asm volatile("cp.async.commit_group;" ::: "memory");
    };

    fillA(0, 0);
    for (int ch = 0; ch < 8; ch++) {
        asm volatile("cp.async.wait_group 0;" ::: "memory");
        __syncthreads();
        if (ch < 7) fillA(ch + 1, (ch + 1) & 1);
        const uint32_t Ab = As32 + (ch & 1) * 16384;
        #pragma unroll
        for (int ks = 0; ks < 2; ks++) {
            uint32_t a[2][4];
            #pragma unroll
            for (int am = 0; am < 2; am++) {
                int krow = ks * 16 + (lane & 7) + ((lane >> 4) << 3);
                int cm   = (wm * 32 + am * 16) / 8 + ((lane >> 3) & 1);
                uint32_t addr = Ab + krow * 256 + ((cm ^ (krow & 7)) << 4);
                uint32_t p0r, p1r, p2r, p3r, q0r, q1r, q2r, q3r;
                ldm_x4_t(p0r, p1r, p2r, p3r, addr);
                ldm_x4_t(q0r, q1r, q2r, q3r, addr + 8192);
                a[am][0] = hadd2u(p0r, q0r);
                a[am][1] = hadd2u(p1r, q1r);
                a[am][2] = hadd2u(p2r, q2r);
                a[am][3] = hadd2u(p3r, q3r);
            }
            uint32_t b[4][4];
            #pragma unroll
            for (int bp = 0; bp < 4; bp++) {
                int n  = wn * 64 + bp * 16 + (lane & 15);
                int kc = ch * 4 + ks * 2 + (lane >> 4);
                ldm_x4(b[bp][0], b[bp][1], b[bp][2], b[bp][3],
                       Bs32 + n * 512 + ((kc ^ (n & 7)) << 4));
            }
            #pragma unroll
            for (int am = 0; am < 2; am++)
                #pragma unroll
                for (int an = 0; an < 8; an++) {
                    uint32_t bb[2] = { b[an >> 1][an & 1], b[an >> 1][(an & 1) + 2] };
                    mma16816(acc[am][an], a[am], bb);
                }
        }
    }

    #pragma unroll
    for (int am = 0; am < 2; am++) {
        int m = wm * 32 + am * 16 + (lane >> 2);
        #pragma unroll
        for (int an = 0; an < 8; an++) {
            int n = o0 + wn * 64 + an * 8 + (lane & 3) * 2;
            float b0 = bias[n] * 2.f, b1 = bias[n + 1] * 2.f;
            long a00 = xbase + (long)n * HW + p0 + m;
            out[a00]          = acc[am][an][0] + b0 + resid[a00];
            out[a00 + HW]     = acc[am][an][1] + b1 + resid[a00 + HW];
            out[a00 + 8]      = acc[am][an][2] + b0 + resid[a00 + 8];
            out[a00 + HW + 8] = acc[am][an][3] + b1 + resid[a00 + HW + 8];
        }
    }
}

// ======== cross-axis attention, both axes in ONE launch, bf16 in/out =========
#define FPB 176
#define OFF_TQ 0
#define OFF_TK 14080
#define OFF_PS 28160
#define OFF_GM 42240
#define OFF_RQ 68160
#define OFF_RK 68480
#define ATTN2_SMEM 68800

__global__ __launch_bounds__(320, 2) void attn_kernel(
    const __nv_bfloat16* __restrict__ fx, const __nv_bfloat16* __restrict__ fy,
    __nv_bfloat16* __restrict__ outx, __nv_bfloat16* __restrict__ outy)
{
    extern __shared__ char sm2[];
    float* Gm = (float*)(sm2 + OFF_GM);
    float* rq = (float*)(sm2 + OFF_RQ);
    float* rk = (float*)(sm2 + OFF_RK);
    const uint32_t tq32 = smem_to_u32(sm2 + OFF_TQ);
    const uint32_t tk32 = smem_to_u32(sm2 + OFF_TK);
    const uint32_t ps32 = smem_to_u32(sm2 + OFF_PS);

    const int axis = blockIdx.x >> 7;
    const int bh   = blockIdx.x & 127;
    const int cbase = (bh >> 3) * (CC*HW) + (bh & 7) * (CPH*HW);
    const __nv_bfloat16* Qb = (axis ? fx : fy) + cbase;
    const __nv_bfloat16* Kb = (axis ? fy : fx) + cbase;
    __nv_bfloat16* outb     = (axis ? outy : outx) + cbase;
    const int tid  = threadIdx.x;
    const int wid  = tid >> 5, lane = tid & 31;
    const int mt   = wid >> 1, nh = wid & 1;

    float acc[5][4];
    #pragma unroll
    for (int j = 0; j < 5; j++)
        #pragma unroll
        for (int t = 0; t < 4; t++) acc[j][t] = 0.f;
    float nss = 0.f;

    // ================= Phase 1: raw Gram + fused sumsq =================
    for (int c = 0; c < CPH; c++) {
        const __nv_bfloat16* qc = Qb + c*HW;
        const __nv_bfloat16* kc = Kb + c*HW;
        __syncthreads();
        if (axis == 0) {
            #pragma unroll
            for (int it = 0; it < 10; it++) {
                int p = tid + it * 320;
                int r = p / 40, fp2 = p - r * 40;
                *(uint32_t*)(sm2 + OFF_TQ + r*FPB + 4*fp2) = *(const uint32_t*)(qc + r*80 + 2*fp2);
                *(uint32_t*)(sm2 + OFF_TK + r*FPB + 4*fp2) = *(const uint32_t*)(kc + r*80 + 2*fp2);
            }
        } else {
            #pragma unroll
            for (int it = 0; it < 10; it++) {
                int p = tid + it * 320;
                int fp2 = p / 80, r = p - fp2 * 80;
                *(uint32_t*)(sm2 + OFF_TQ + r*FPB + 4*fp2) = pk(qc[(2*fp2)*80 + r], qc[(2*fp2+1)*80 + r]);
                *(uint32_t*)(sm2 + OFF_TK + r*FPB + 4*fp2) = pk(kc[(2*fp2)*80 + r], kc[(2*fp2+1)*80 + r]);
            }
        }
        __syncthreads();
        if (tid < 160) {
            const char* rowp = (tid < 80) ? (sm2 + OFF_TQ + tid*FPB)
                                          : (sm2 + OFF_TK + (tid-80)*FPB);
            float s = 0.f;
            #pragma unroll 8
            for (int u = 0; u < 40; u++) {
                __nv_bfloat162 h2 = *(const __nv_bfloat162*)(rowp + 4*u);
                float2 f2 = __bfloat1622float2(h2);
                s = fmaf(f2.x, f2.x, fmaf(f2.y, f2.y, s));
            }
            nss += s;
        }
        #pragma unroll
        for (int ks = 0; ks < 5; ks++) {
            uint32_t a[4];
            {
                int row = mt*16 + (lane & 15);
                ldm_x4(a[0], a[1], a[2], a[3],
                       tq32 + row*FPB + ks*32 + ((lane >> 4) << 4));
            }
            uint32_t bA[4], bB[4], bC[2];
            {
                int row = nh*40 + (lane & 15);
                ldm_x4(bA[0], bA[1], bA[2], bA[3],
                       tk32 + row*FPB + ks*32 + ((lane >> 4) << 4));
            }
            {
                int row = nh*40 + 16 + (lane & 15);
                ldm_x4(bB[0], bB[1], bB[2], bB[3],
                       tk32 + row*FPB + ks*32 + ((lane >> 4) << 4));
            }
            {
                int row = nh*40 + 32 + (lane & 7);
                ldm_x2(bC[0], bC[1],
                       tk32 + row*FPB + ks*32 + (((lane >> 3) & 1) << 4));
            }
            { uint32_t bb[2] = { bA[0], bA[2] }; mma16816(acc[0], a, bb); }
            { uint32_t bb[2] = { bA[1], bA[3] }; mma16816(acc[1], a, bb); }
            { uint32_t bb[2] = { bB[0], bB[2] }; mma16816(acc[2], a, bb); }
            { uint32_t bb[2] = { bB[1], bB[3] }; mma16816(acc[3], a, bb); }
            { uint32_t bb[2] = { bC[0], bC[1] }; mma16816(acc[4], a, bb); }
        }
    }
    __syncthreads();
    if (tid < 160) {
        float inv = 1.f / fmaxf(sqrtf(nss), 1e-12f);
        if (tid < 80) rq[tid] = inv; else rk[tid - 80] = inv;
    }
    __syncthreads();
    {
        int row  = mt*16 + (lane >> 2);
        int colb = nh*40 + (lane & 3) * 2;
        float r0 = rq[row], r1 = rq[row + 8];
        #pragma unroll
        for (int j = 0; j < 5; j++) {
            int col = colb + j*8;
            float k0 = rk[col], k1 = rk[col + 1];
            Gm[row*81 + col]       = acc[j][0] * r0 * k0;
            Gm[row*81 + col + 1]   = acc[j][1] * r0 * k1;
            Gm[(row+8)*81 + col]   = acc[j][2] * r1 * k0;
            Gm[(row+8)*81 + col+1] = acc[j][3] * r1 * k1;
        }
    }
    __syncthreads();
    // ================= Phase 2: softmax rows =================
    if (tid < 80) {
        float* row = Gm + tid*81;
        float mx = -3.0e38f;
        for (int m = 0; m < 80; m++) mx = fmaxf(mx, row[m]);
        float s = 0.f;
        for (int m = 0; m < 80; m++) { float e = expf(row[m] - mx); row[m] = e; s += e; }
        float is = 1.f / s;
        for (int m = 0; m < 80; m++) row[m] *= is;
    }
    __syncthreads();
    #pragma unroll
    for (int it = 0; it < 10; it++) {
        int p = tid + it * 320;
        int n = p / 40, mp = p - n * 40;
        *(uint32_t*)(sm2 + OFF_PS + n*FPB + 4*mp) = pack2(Gm[n*81 + 2*mp], Gm[n*81 + 2*mp + 1]);
    }
    __syncthreads();
    uint32_t aP[5][4];
    #pragma unroll
    for (int ks = 0; ks < 5; ks++) {
        int row = mt*16 + (lane & 15);
        ldm_x4(aP[ks][0], aP[ks][1], aP[ks][2], aP[ks][3],
               ps32 + row*FPB + ks*32 + ((lane >> 4) << 4));
    }

    // ================= Phase 3: out = P@V + q*rq =================
    for (int c = 0; c < CPH; c++) {
        const __nv_bfloat16* qc = Qb + c*HW;
        const __nv_bfloat16* kc = Kb + c*HW;
        __syncthreads();
        if (axis == 0) {
            #pragma unroll
            for (int it = 0; it < 10; it++) {
                int p = tid + it * 320;
                int r = p / 40, fp2 = p - r * 40;
                *(uint32_t*)(sm2 + OFF_TQ + r*FPB + 4*fp2) = *(const uint32_t*)(qc + r*80 + 2*fp2);
            }
            #pragma unroll
            for (int it = 0; it < 10; it++) {
                int p = tid + it * 320;
                int mp = p / 80, f = p - mp * 80;
                *(uint32_t*)(sm2 + OFF_TK + f*FPB + 4*mp) = pk(kc[(2*mp)*80 + f], kc[(2*mp+1)*80 + f]);
            }
        } else {
            #pragma unroll
            for (int it = 0; it < 10; it++) {
                int p = tid + it * 320;
                int fp2 = p / 80, r = p - fp2 * 80;
                *(uint32_t*)(sm2 + OFF_TQ + r*FPB + 4*fp2) = pk(qc[(2*fp2)*80 + r], qc[(2*fp2+1)*80 + r]);
            }
            #pragma unroll
            for (int it = 0; it < 10; it++) {
                int p = tid + it * 320;
                int f = p / 40, mp = p - f * 40;
                *(uint32_t*)(sm2 + OFF_TK + f*FPB + 4*mp) = *(const uint32_t*)(kc + f*80 + 2*mp);
            }
        }
        __syncthreads();
        float o[5][4];
        #pragma unroll
        for (int j = 0; j < 5; j++)
            #pragma unroll
            for (int t = 0; t < 4; t++) o[j][t] = 0.f;
        #pragma unroll
        for (int ks = 0; ks < 5; ks++) {
            uint32_t bA[4], bB[4], bC[2];
            {
                int row = nh*40 + (lane & 15);
                ldm_x4(bA[0], bA[1], bA[2], bA[3],
                       tk32 + row*FPB + ks*32 + ((lane >> 4) << 4));
            }
            {
                int row = nh*40 + 16 + (lane & 15);
                ldm_x4(bB[0], bB[1], bB[2], bB[3],
                       tk32 + row*FPB + ks*32 + ((lane >> 4) << 4));
            }
            {
                int row = nh*40 + 32 + (lane & 7);
                ldm_x2(bC[0], bC[1],
                       tk32 + row*FPB + ks*32 + (((lane >> 3) & 1) << 4));
            }
            { uint32_t bb[2] = { bA[0], bA[2] }; mma16816(o[0], aP[ks], bb); }
            { uint32_t bb[2] = { bA[1], bA[3] }; mma16816(o[1], aP[ks], bb); }
            { uint32_t bb[2] = { bB[0], bB[2] }; mma16816(o[2], aP[ks], bb); }
            { uint32_t bb[2] = { bB[1], bB[3] }; mma16816(o[3], aP[ks], bb); }
            { uint32_t bb[2] = { bC[0], bC[1] }; mma16816(o[4], aP[ks], bb); }
        }
        __nv_bfloat16* ob = outb + c*HW;
        int row  = mt*16 + (lane >> 2);
        int colb = nh*40 + (lane & 3) * 2;
        #pragma unroll
        for (int j = 0; j < 5; j++) {
            int col = colb + j*8;
            #pragma unroll
            for (int half = 0; half < 2; half++) {
                int rr = row + 8*half;
                float rqi = rq[rr];
                __nv_bfloat162 q2 = *(const __nv_bfloat162*)(sm2 + OFF_TQ + rr*FPB + col*2);
                float2 qf = __bfloat1622float2(q2);
                float v0 = o[j][2*half]     + qf.x * rqi;
                float v1 = o[j][2*half + 1] + qf.y * rqi;
                if (axis == 0) {
                    *(uint32_t*)(ob + rr*80 + col) = pack2(v0, v1);
                } else {
                    ob[col*80 + rr]       = __float2bfloat16(v0);
                    ob[(col+1)*80 + rr]   = __float2bfloat16(v1);
                }
            }
        }
    }
}

// ---------------- launch -----------------------------------------------------
extern "C" void kernel_launch(void* const* d_in, const int* in_sizes, int n_in,
                              void* d_out, int out_size)
{
    const float* x    = (const float*)d_in[0];
    const float* ln_g = (const float*)d_in[1];
    const float* ln_b = (const float*)d_in[2];
    const float* w_in = (const float*)d_in[3];
    const float* b_in = (const float*)d_in[4];
    const float* w_out= (const float*)d_in[5];
    const float* b_out= (const float*)d_in[6];
    const float* wx7  = (const float*)d_in[7];
    const float* bx7  = (const float*)d_in[8];
    const float* wx11 = (const float*)d_in[9];
    const float* bx11 = (const float*)d_in[10];
    const float* wx21 = (const float*)d_in[11];
    const float* bx21 = (const float*)d_in[12];
    const float* wy7  = (const float*)d_in[13];
    const float* by7  = (const float*)d_in[14];
    const float* wy11 = (const float*)d_in[15];
    const float* by11 = (const float*)d_in[16];
    const float* wy21 = (const float*)d_in[17];
    const float* by21 = (const float*)d_in[18];
    float* out = (float*)d_out;

    float *pA, *pB, *pC, *pD;
    cudaGetSymbolAddress((void**)&pA, g_A);
    cudaGetSymbolAddress((void**)&pB, g_B);
    cudaGetSymbolAddress((void**)&pC, g_C);
    cudaGetSymbolAddress((void**)&pD, g_D);
    __nv_bfloat16* hA = (__nv_bfloat16*)pA;
    __nv_bfloat16* hB = (__nv_bfloat16*)pB;
    __nv_bfloat16* hC = (__nv_bfloat16*)pC;
    __nv_bfloat16* hD = (__nv_bfloat16*)pD;

    cudaFuncSetAttribute(attn_kernel, cudaFuncAttributeMaxDynamicSharedMemorySize, ATTN2_SMEM);
    cudaFuncSetAttribute(gemm_bf,  cudaFuncAttributeMaxDynamicSharedMemorySize, GSMEM_BF);
    cudaFuncSetAttribute(gemm_out, cudaFuncAttributeMaxDynamicSharedMemorySize, GSMEM_OUT);

    // 1) LayerNorm: x -> A (bf16 xn)
    ln_kernel<<<(BB*HW)/256, 256>>>(x, ln_g, ln_b, hA);
    // 2) depthwise (both dirs, HFMA2): A -> B (bf16 sx), C (bf16 sy)
    dw_kernel<<<2*BB*CC, 256>>>(hA, wx7, bx7, wx11, bx11, wx21, bx21,
                                wy7, by7, wy11, by11, wy21, by21, hB, hC);
    // 3) pointwise w_in (bf16, cp.async): B->D (fx), C->B (fy)
    dim3 gg(HW/128, CC/128, BB);
    gemm_bf<<<gg, 256, GSMEM_BF>>>(w_in, hB, b_in, hD);
    gemm_bf<<<gg, 256, GSMEM_BF>>>(w_in, hC, b_in, hB);
    // 4) cross-axis attention (both axes): -> C (bf16 attx), A (bf16 atty)
    attn_kernel<<<2*BB*NHEADS, 320, ATTN2_SMEM>>>(hD, hB, hC, hA);
    // 5) final pointwise: W_out@(C+A) + 2*b_out + x residual
    gemm_out<<<gg, 256, GSMEM_OUT>>>(w_out, hC, hA, b_out, x, out);
}

// round 13
// speedup vs baseline: 6.4032x; 1.1789x over previous
#include <cuda_runtime.h>
#include <cuda_bf16.h>
#include <math.h>
#include <stdint.h>

#define BB     16
#define CC     256
#define HW     6400
#define NHEADS 8
#define CPH    32

// ---------------- scratch (static device globals; no allocation) -------------
// ln: x->A(bf16 xn) | dw: A->B(bf16 sx), C(bf16 sy)
// gemm_bf merged: B->D(bf16 fx), C->E(bf16 fy)
// attn: (D,E) -> C(bf16 attx), A(bf16 atty)
// gemm_out: W@(C+A) + 2b + x -> out (fp32)
__device__ float g_A[BB*CC*HW];
__device__ float g_B[BB*CC*HW];
__device__ float g_C[BB*CC*HW];
__device__ float g_D[BB*CC*HW];
__device__ float g_E[BB*CC*HW];

// ================= helpers ===================================================
__device__ __forceinline__ uint32_t smem_to_u32(const void* p) {
    uint32_t a;
    asm("{ .reg .u64 t; cvta.to.shared.u64 t, %1; cvt.u32.u64 %0, t; }" : "=r"(a) : "l"(p));
    return a;
}
__device__ __forceinline__ uint32_t pack2(float x, float y) {
    __nv_bfloat162 b = __float22bfloat162_rn(make_float2(x, y));
    return *(uint32_t*)&b;
}
__device__ __forceinline__ uint32_t hadd2u(uint32_t a, uint32_t b) {
    __nv_bfloat162 x = *(__nv_bfloat162*)&a, y = *(__nv_bfloat162*)&b;
    __nv_bfloat162 r = __hadd2(x, y);
    return *(uint32_t*)&r;
}
__device__ __forceinline__ void ldm_x4(uint32_t& r0, uint32_t& r1, uint32_t& r2, uint32_t& r3,
                                       uint32_t addr) {
    asm volatile("ldmatrix.sync.aligned.m8n8.x4.shared.b16 {%0,%1,%2,%3}, [%4];"
                 : "=r"(r0), "=r"(r1), "=r"(r2), "=r"(r3) : "r"(addr));
}
__device__ __forceinline__ void ldm_x4_t(uint32_t& r0, uint32_t& r1, uint32_t& r2, uint32_t& r3,
                                         uint32_t addr) {
    asm volatile("ldmatrix.sync.aligned.m8n8.x4.trans.shared.b16 {%0,%1,%2,%3}, [%4];"
                 : "=r"(r0), "=r"(r1), "=r"(r2), "=r"(r3) : "r"(addr));
}
__device__ __forceinline__ void ldm_x2(uint32_t& r0, uint32_t& r1, uint32_t addr) {
    asm volatile("ldmatrix.sync.aligned.m8n8.x2.shared.b16 {%0,%1}, [%2];"
                 : "=r"(r0), "=r"(r1) : "r"(addr));
}
__device__ __forceinline__ void ldm_x2_t(uint32_t& r0, uint32_t& r1, uint32_t addr) {
    asm volatile("ldmatrix.sync.aligned.m8n8.x2.trans.shared.b16 {%0,%1}, [%2];"
                 : "=r"(r0), "=r"(r1) : "r"(addr));
}
__device__ __forceinline__ void mma16816(float* d, const uint32_t* a, const uint32_t* b) {
    asm volatile("mma.sync.aligned.m16n8k16.row.col.f32.bf16.bf16.f32 "
                 "{%0,%1,%2,%3}, {%4,%5,%6,%7}, {%8,%9}, {%0,%1,%2,%3};"
                 : "+f"(d[0]), "+f"(d[1]), "+f"(d[2]), "+f"(d[3])
                 : "r"(a[0]), "r"(a[1]), "r"(a[2]), "r"(a[3]), "r"(b[0]), "r"(b[1]));
}
#define CP16(dst, src) asm volatile("cp.async.cg.shared.global [%0], [%1], 16;" :: "r"(dst), "l"(src))
#define CPCOMMIT()     asm volatile("cp.async.commit_group;" ::: "memory")
#define CPWAIT0()      asm volatile("cp.async.wait_group 0;" ::: "memory")

// ---------------- LayerNorm over channels, per pixel (bf16 out) --------------
__global__ __launch_bounds__(256) void ln_kernel(const float* __restrict__ x,
                                                 const float* __restrict__ gam,
                                                 const float* __restrict__ bet,
                                                 __nv_bfloat16* __restrict__ xn)
{
    int p  = blockIdx.x * 256 + threadIdx.x;
    int b  = p / HW;
    int pl = p - b * HW;
    const float* xb = x + b * CC * HW + pl;
    float s = 0.f, s2 = 0.f;
    #pragma unroll 8
    for (int c = 0; c < CC; c++) { float v = xb[c*HW]; s += v; s2 = fmaf(v, v, s2); }
    float mu  = s  * (1.f / CC);
    float var = s2 * (1.f / CC) - mu * mu;
    float inv = rsqrtf(var + 1e-5f);
    __nv_bfloat16* ob = xn + b * CC * HW + pl;
    #pragma unroll 8
    for (int c = 0; c < CC; c++) {
        float v = xb[c*HW];
        ob[c*HW] = __float2bfloat16((v - mu) * inv * gam[c] + bet[c]);
    }
}

// ---------------- fused depthwise, both dirs, bf16 HFMA2 2-wide --------------
__global__ __launch_bounds__(256) void dw_kernel(
    const __nv_bfloat16* __restrict__ xn,
    const float* __restrict__ wx7,  const float* __restrict__ bx7,
    const float* __restrict__ wx11, const float* __restrict__ bx11,
    const float* __restrict__ wx21, const float* __restrict__ bx21,
    const float* __restrict__ wy7,  const float* __restrict__ by7,
    const float* __restrict__ wy11, const float* __restrict__ by11,
    const float* __restrict__ wy21, const float* __restrict__ by21,
    __nv_bfloat16* __restrict__ dstX, __nv_bfloat16* __restrict__ dstY)
{
    __shared__ uint32_t pad[4000];
    __shared__ __nv_bfloat162 coef2[21];
    __shared__ float biasv;
    const int tid = threadIdx.x;
    const int dir = (blockIdx.x >= BB*CC) ? 1 : 0;
    const int bc  = blockIdx.x - dir * BB * CC;
    const int c   = bc & (CC - 1);
    const float* w7  = dir ? wy7  : wx7;
    const float* w11 = dir ? wy11 : wx11;
    const float* w21 = dir ? wy21 : wx21;
    for (int i = tid; i < 4000; i += 256) pad[i] = 0;
    if (tid < 21) {
        int t = tid - 10;
        float v = w21[c*21 + t + 10];
        if (t >= -5 && t <= 5) v += w11[c*11 + t + 5];
        if (t >= -3 && t <= 3) v += w7 [c*7  + t + 3];
        coef2[tid] = __float2bfloat162_rn(v);
    }
    if (tid == 0) {
        biasv = (dir ? (by7[c] + by11[c] + by21[c])
                     : (bx7[c] + bx11[c] + bx21[c]));
    }
    __syncthreads();
    const uint32_t* src32 = (const uint32_t*)(xn + bc * HW);
    if (dir == 0) {
        for (int i = tid; i < 1600; i += 256) {
            int h2 = i / 40, wp2 = i - h2 * 40;
            uint32_t a01 = src32[(2*h2)*40 + wp2];
            uint32_t b01 = src32[(2*h2+1)*40 + wp2];
            pad[h2*100 + 10 + 2*wp2] = __byte_perm(a01, b01, 0x5410);
            pad[h2*100 + 11 + 2*wp2] = __byte_perm(a01, b01, 0x7632);
        }
    } else {
        for (int i = tid; i < 3200; i += 256) {
            int h = i / 40, w2 = i - h * 40;
            pad[(h + 10)*40 + w2] = src32[i];
        }
    }
    __syncthreads();
    const __nv_bfloat162 bias2 = __float2bfloat162_rn(biasv);
    const __nv_bfloat162 z2    = __float2bfloat162_rn(0.f);
    uint32_t* dst32 = (uint32_t*)((dir ? dstY : dstX) + bc * HW);
    for (int i = tid; i < 1600; i += 256) {
        int h2 = i / 40, w2 = i - h2 * 40;
        uint32_t win[22];
        if (dir == 0) {
            #pragma unroll
            for (int t = 0; t < 22; t++) win[t] = pad[h2*100 + 2*w2 + t];
        } else {
            #pragma unroll
            for (int t = 0; t < 22; t++) win[t] = pad[(2*h2 + t)*40 + w2];
        }
        __nv_bfloat162 ae = bias2, ao = z2, be = bias2, bo = z2;
        #pragma unroll
        for (int t = 0; t < 21; t++) {
            __nv_bfloat162 w0 = *(__nv_bfloat162*)&win[t];
            __nv_bfloat162 w1 = *(__nv_bfloat162*)&win[t + 1];
            if (t & 1) { ao = __hfma2(coef2[t], w0, ao); bo = __hfma2(coef2[t], w1, bo); }
            else       { ae = __hfma2(coef2[t], w0, ae); be = __hfma2(coef2[t], w1, be); }
        }
        __nv_bfloat162 A2 = __hadd2(ae, ao);
        __nv_bfloat162 B2 = __hadd2(be, bo);
        uint32_t uA = *(uint32_t*)&A2, uB = *(uint32_t*)&B2;
        if (dir == 0) {
            dst32[(2*h2)*40 + w2]   = __byte_perm(uA, uB, 0x5410);
            dst32[(2*h2+1)*40 + w2] = __byte_perm(uA, uB, 0x7632);
        } else {
            dst32[(2*h2)*40 + w2]   = uA;
            dst32[(2*h2+1)*40 + w2] = uB;
        }
    }
}

// ====== bf16-in / bf16-out GEMM, cp.async, MERGED two inputs via grid.z ======
#define GSMEM_BF (64*1024 + 2*16*1024)

__global__ __launch_bounds__(256) void gemm_bf(
    const float* __restrict__ Wm,
    const __nv_bfloat16* __restrict__ Xa, const __nv_bfloat16* __restrict__ Xb,
    const float* __restrict__ bias,
    __nv_bfloat16* __restrict__ Oa, __nv_bfloat16* __restrict__ Ob)
{
    extern __shared__ char smem[];
    char* Bs = smem;
    const uint32_t Bs32 = smem_to_u32(Bs);
    const uint32_t As32 = smem_to_u32(smem + 65536);
    const int tid = threadIdx.x, wid = tid >> 5, lane = tid & 31;
    const int wm = wid >> 1, wn = wid & 1;
    const int p0 = blockIdx.x * 128, o0 = blockIdx.y * 128;
    const int sel = blockIdx.z >> 4;
    const long xbase = (long)(blockIdx.z & 15) * (CC * HW);
    const __nv_bfloat16* X = sel ? Xb : Xa;
    __nv_bfloat16* out     = sel ? Ob : Oa;

    #pragma unroll
    for (int it = 0; it < 16; it++) {
        int idx = tid + it * 256;
        int n = idx >> 5, kc = idx & 31;
        const float* wp = Wm + (o0 + n) * CC + kc * 8;
        float4 f0 = *(const float4*)(wp);
        float4 f1 = *(const float4*)(wp + 4);
        uint4 u;
        u.x = pack2(f0.x, f0.y); u.y = pack2(f0.z, f0.w);
        u.z = pack2(f1.x, f1.y); u.w = pack2(f1.z, f1.w);
        *(uint4*)(Bs + n * 512 + ((kc ^ (n & 7)) << 4)) = u;
    }

    float acc[2][8][4];
    #pragma unroll
    for (int i = 0; i < 2; i++)
        #pragma unroll
        for (int j = 0; j < 8; j++)
            #pragma unroll
            for (int t = 0; t < 4; t++) acc[i][j][t] = 0.f;

    auto fillA = [&](int ch, int buf) {
        #pragma unroll
        for (int it = 0; it < 4; it++) {
            int idx = tid + it * 256;
            int k = idx >> 4, cm = idx & 15;
            const __nv_bfloat16* src = X + xbase + (long)(ch * 64 + k) * HW + p0 + cm * 8;
            uint32_t dst = As32 + buf * 16384 + k * 256 + ((cm ^ (k & 7)) << 4);
            CP16(dst, src);
        }
        CPCOMMIT();
    };

    fillA(0, 0);
    for (int ch = 0; ch < 4; ch++) {
        CPWAIT0();
        __syncthreads();
        if (ch < 3) fillA(ch + 1, (ch + 1) & 1);
        const uint32_t Ab = As32 + (ch & 1) * 16384;
        #pragma unroll
        for (int ks = 0; ks < 4; ks++) {
            uint32_t a[2][4];
            #pragma unroll
            for (int am = 0; am < 2; am++) {
                int krow = ks * 16 + (lane & 7) + ((lane >> 4) << 3);
                int cm   = (wm * 32 + am * 16) / 8 + ((lane >> 3) & 1);
                ldm_x4_t(a[am][0], a[am][1], a[am][2], a[am][3],
                         Ab + krow * 256 + ((cm ^ (krow & 7)) << 4));
            }
            uint32_t b[4][4];
            #pragma unroll
            for (int bp = 0; bp < 4; bp++) {
                int n  = wn * 64 + bp * 16 + (lane & 15);
                int kc = ch * 8 + ks * 2 + (lane >> 4);
                ldm_x4(b[bp][0], b[bp][1], b[bp][2], b[bp][3],
                       Bs32 + n * 512 + ((kc ^ (n & 7)) << 4));
            }
            #pragma unroll
            for (int am = 0; am < 2; am++)
                #pragma unroll
                for (int an = 0; an < 8; an++) {
                    uint32_t bb[2] = { b[an >> 1][an & 1], b[an >> 1][(an & 1) + 2] };
                    mma16816(acc[am][an], a[am], bb);
                }
        }
    }

    __syncthreads();
    #pragma unroll
    for (int am = 0; am < 2; am++) {
        int m = wm * 32 + am * 16 + (lane >> 2);
        #pragma unroll
        for (int an = 0; an < 8; an++) {
            int nl = wn * 64 + an * 8 + (lane & 3) * 2;
            float b0 = bias[o0 + nl], b1 = bias[o0 + nl + 1];
            *(__nv_bfloat16*)(Bs + nl * 256 + m * 2)             = __float2bfloat16(acc[am][an][0] + b0);
            *(__nv_bfloat16*)(Bs + (nl + 1) * 256 + m * 2)       = __float2bfloat16(acc[am][an][1] + b1);
            *(__nv_bfloat16*)(Bs + nl * 256 + (m + 8) * 2)       = __float2bfloat16(acc[am][an][2] + b0);
            *(__nv_bfloat16*)(Bs + (nl + 1) * 256 + (m + 8) * 2) = __float2bfloat16(acc[am][an][3] + b1);
        }
    }
    __syncthreads();
    #pragma unroll
    for (int it = 0; it < 32; it++) {
        int idx = tid + it * 256;
        int n = idx >> 6, mu = idx & 63;
        uint32_t u = *(uint32_t*)(Bs + n * 256 + mu * 4);
        *(uint32_t*)(out + xbase + (long)(o0 + n) * HW + p0 + 2 * mu) = u;
    }
}

// ====== final GEMM: out = W@(X+X2) + 2b + resid, bf16 in, cp.async ==========
#define GSMEM_OUT (64*1024 + 32*1024)

__global__ __launch_bounds__(256) void gemm_out(
    const float* __restrict__ Wm, const __nv_bfloat16* __restrict__ X,
    const __nv_bfloat16* __restrict__ X2,
    const float* __restrict__ bias, const float* __restrict__ resid,
    float* __restrict__ out)
{
    extern __shared__ char smem[];
    char* Bs = smem;
    const uint32_t Bs32 = smem_to_u32(Bs);
    const uint32_t As32 = smem_to_u32(smem + 65536);
    const int tid = threadIdx.x, wid = tid >> 5, lane = tid & 31;
    const int wm = wid >> 1, wn = wid & 1;
    const int p0 = blockIdx.x * 128, o0 = blockIdx.y * 128;
    const long xbase = (long)blockIdx.z * (CC * HW);

    #pragma unroll
    for (int it = 0; it < 16; it++) {
        int idx = tid + it * 256;
        int n = idx >> 5, kc = idx & 31;
        const float* wp = Wm + (o0 + n) * CC + kc * 8;
        float4 f0 = *(const float4*)(wp);
        float4 f1 = *(const float4*)(wp + 4);
        uint4 u;
        u.x = pack2(f0.x, f0.y); u.y = pack2(f0.z, f0.w);
        u.z = pack2(f1.x, f1.y); u.w = pack2(f1.z, f1.w);
        *(uint4*)(Bs + n * 512 + ((kc ^ (n & 7)) << 4)) = u;
    }

    float acc[2][8][4];
    #pragma unroll
    for (int i = 0; i < 2; i++)
        #pragma unroll
        for (int j = 0; j < 8; j++)
            #pragma unroll
            for (int t = 0; t < 4; t++) acc[i][j][t] = 0.f;

    auto fillA = [&](int ch, int buf) {
        #pragma unroll
        for (int it = 0; it < 2; it++) {
            int idx = tid + it * 256;
            int k = idx >> 4, cm = idx & 15;
            long off = xbase + (long)(ch * 32 + k) * HW + p0 + cm * 8;
            uint32_t dst = As32 + buf * 16384 + k * 256 + ((cm ^ (k & 7)) << 4);
            CP16(dst, X + off);
            CP16(dst + 8192, X2 + off);
        }
        CPCOMMIT();
    };

    fillA(0, 0);
    for (int ch = 0; ch < 8; ch++) {
        CPWAIT0();
        __syncthreads();
        if (ch < 7) fillA(ch + 1, (ch + 1) & 1);
        const uint32_t Ab = As32 + (ch & 1) * 16384;
        #pragma unroll
        for (int ks = 0; ks < 2; ks++) {
            uint32_t a[2][4];
            #pragma unroll
            for (int am = 0; am < 2; am++) {
                int krow = ks * 16 + (lane & 7) + ((lane >> 4) << 3);
                int cm   = (wm * 32 + am * 16) / 8 + ((lane >> 3) & 1);
                uint32_t addr = Ab + krow * 256 + ((cm ^ (krow & 7)) << 4);
                uint32_t p0r, p1r, p2r, p3r, q0r, q1r, q2r, q3r;
                ldm_x4_t(p0r, p1r, p2r, p3r, addr);
                ldm_x4_t(q0r, q1r, q2r, q3r, addr + 8192);
                a[am][0] = hadd2u(p0r, q0r);
                a[am][1] = hadd2u(p1r, q1r);
                a[am][2] = hadd2u(p2r, q2r);
                a[am][3] = hadd2u(p3r, q3r);
            }
            uint32_t b[4][4];
            #pragma unroll
            for (int bp = 0; bp < 4; bp++) {
                int n  = wn * 64 + bp * 16 + (lane & 15);
                int kc = ch * 4 + ks * 2 + (lane >> 4);
                ldm_x4(b[bp][0], b[bp][1], b[bp][2], b[bp][3],
                       Bs32 + n * 512 + ((kc ^ (n & 7)) << 4));
            }
            #pragma unroll
            for (int am = 0; am < 2; am++)
                #pragma unroll
                for (int an = 0; an < 8; an++) {
                    uint32_t bb[2] = { b[an >> 1][an & 1], b[an >> 1][(an & 1) + 2] };
                    mma16816(acc[am][an], a[am], bb);
                }
        }
    }

    #pragma unroll
    for (int am = 0; am < 2; am++) {
        int m = wm * 32 + am * 16 + (lane >> 2);
        #pragma unroll
        for (int an = 0; an < 8; an++) {
            int n = o0 + wn * 64 + an * 8 + (lane & 3) * 2;
            float b0 = bias[n] * 2.f, b1 = bias[n + 1] * 2.f;
            long a00 = xbase + (long)n * HW + p0 + m;
            out[a00]          = acc[am][an][0] + b0 + resid[a00];
            out[a00 + HW]     = acc[am][an][1] + b1 + resid[a00 + HW];
            out[a00 + 8]      = acc[am][an][2] + b0 + resid[a00 + 8];
            out[a00 + HW + 8] = acc[am][an][3] + b1 + resid[a00 + HW + 8];
        }
    }
}

// ======== cross-axis attention: native-layout cp.async staging ===============
// Planes staged ALWAYS as native [h][w], pitch 176B, double-buffered cp.async.
// Transposed MMA operands via ldmatrix.trans.
// smem: TQ[2] @0/14080, TK[2] @28160/42240, PS @56320, GM @70400(fp32 80x81),
//       RQ @96320, RK @96640. total 96960.
#define FPB 176
#define OFF_TK 28160
#define OFF_PS 56320
#define OFF_GM 70400
#define OFF_RQ 96320
#define OFF_RK 96640
#define ATTN2_SMEM 96960

__global__ __launch_bounds__(320, 2) void attn_kernel(
    const __nv_bfloat16* __restrict__ fx, const __nv_bfloat16* __restrict__ fy,
    __nv_bfloat16* __restrict__ outx, __nv_bfloat16* __restrict__ outy)
{
    extern __shared__ char sm2[];
    float* Gm = (float*)(sm2 + OFF_GM);
    float* rq = (float*)(sm2 + OFF_RQ);
    float* rk = (float*)(sm2 + OFF_RK);
    const uint32_t tq32 = smem_to_u32(sm2);
    const uint32_t tk32 = tq32 + OFF_TK;
    const uint32_t ps32 = tq32 + OFF_PS;

    const int axis = blockIdx.x >> 7;
    const int bh   = blockIdx.x & 127;
    const int cbase = (bh >> 3) * (CC*HW) + (bh & 7) * (CPH*HW);
    const __nv_bfloat16* Qb = (axis ? fx : fy) + cbase;
    const __nv_bfloat16* Kb = (axis ? fy : fx) + cbase;
    __nv_bfloat16* outb     = (axis ? outy : outx) + cbase;
    const int tid  = threadIdx.x;
    const int wid  = tid >> 5, lane = tid & 31;
    const int mt   = wid >> 1, nh = wid & 1;

    // cp.async fill of q+k planes (native [h][w], 10 x 16B chunks per row)
    auto fill = [&](int c, int b) {
        const __nv_bfloat16* qc = Qb + c*HW;
        const __nv_bfloat16* kc = Kb + c*HW;
        uint32_t dq = tq32 + b * 14080;
        uint32_t dk = tk32 + b * 14080;
        #pragma unroll
        for (int it = 0; it < 5; it++) {
            int idx = tid + it * 320;          // 0..1599
            int pl  = (idx >= 800);
            int j   = idx - pl * 800;          // 0..799
            int r = j / 10, cj = j - r * 10;
            const __nv_bfloat16* s = (pl ? kc : qc) + r * 80 + cj * 8;
            uint32_t d = (pl ? dk : dq) + r * FPB + cj * 16;
            CP16(d, s);
        }
        CPCOMMIT();
    };

    // B-operand fragment load (n-range = nh*40..+40, k-chunk ks), from buffer base tb.
    // normal: rows are n (native h), cols are k (w).  trans: rows are k (h), cols n (w).
    auto loadB = [&](uint32_t tb, int ks, bool tr, uint32_t* bA, uint32_t* bB, uint32_t* bC) {
        if (!tr) {
            {
                int row = nh*40 + (lane & 15);
                ldm_x4(bA[0], bA[1], bA[2], bA[3], tb + row*FPB + ks*32 + ((lane >> 4) << 4));
            }
            {
                int row = nh*40 + 16 + (lane & 15);
                ldm_x4(bB[0], bB[1], bB[2], bB[3], tb + row*FPB + ks*32 + ((lane >> 4) << 4));
            }
            {
                int row = nh*40 + 32 + (lane & 7);
                ldm_x2(bC[0], bC[1], tb + row*FPB + ks*32 + (((lane >> 3) & 1) << 4));
            }
        } else {
            int krow = ks*16 + (lane & 7) + ((lane >> 4) << 3);
            {
                int nc = nh*5 + ((lane >> 3) & 1);
                ldm_x4_t(bA[0], bA[1], bA[2], bA[3], tb + krow*FPB + (nc << 4));
            }
            {
                int nc = nh*5 + 2 + ((lane >> 3) & 1);
                ldm_x4_t(bB[0], bB[1], bB[2], bB[3], tb + krow*FPB + (nc << 4));
            }
            {
                int kr2 = ks*16 + (lane & 7) + (((lane >> 3) & 1) << 3);
                int nc = nh*5 + 4;
                ldm_x2_t(bC[0], bC[1], tb + kr2*FPB + (nc << 4));
            }
        }
    };

    float acc[5][4];
    #pragma unroll
    for (int j = 0; j < 5; j++)
        #pragma unroll
        for (int t = 0; t < 4; t++) acc[j][t] = 0.f;
    float nss = 0.f;

    // ================= Phase 1: raw Gram + fused sumsq =================
    fill(0, 0);
    for (int c = 0; c < CPH; c++) {
        const int b = c & 1;
        CPWAIT0();
        __syncthreads();
        if (c < CPH-1) fill(c + 1, b ^ 1);
        const uint32_t qb = tq32 + b * 14080;
        const uint32_t kb = tk32 + b * 14080;
        // fused sumsq: norms are per SEQ position (rows if axis0, cols if axis1)
        if (tid < 160) {
            const char* pb = (char*)sm2 + ((tid < 80) ? b*14080 : OFF_TK + b*14080);
            int sp = (tid < 80) ? tid : tid - 80;
            float s = 0.f;
            if (axis == 0) {
                const char* rowp = pb + sp * FPB;
                #pragma unroll 8
                for (int u = 0; u < 40; u++) {
                    __nv_bfloat162 h2 = *(const __nv_bfloat162*)(rowp + 4*u);
                    float2 f2 = __bfloat1622float2(h2);
                    s = fmaf(f2.x, f2.x, fmaf(f2.y, f2.y, s));
                }
            } else {
                #pragma unroll 8
                for (int r = 0; r < 80; r++) {
                    float v = __bfloat162float(*(const __nv_bfloat16*)(pb + r*FPB + sp*2));
                    s = fmaf(v, v, s);
                }
            }
            nss += s;
        }
        #pragma unroll
        for (int ks = 0; ks < 5; ks++) {
            uint32_t a[4];
            if (axis == 0) {
                int row = mt*16 + (lane & 15);
                ldm_x4(a[0], a[1], a[2], a[3], qb + row*FPB + ks*32 + ((lane >> 4) << 4));
            } else {
                int krow = ks*16 + (lane & 7) + ((lane >> 4) << 3);
                int mc   = mt*2 + ((lane >> 3) & 1);
                ldm_x4_t(a[0], a[1], a[2], a[3], qb + krow*FPB + (mc << 4));
            }
            uint32_t bA[4], bB[4], bC[2];
            loadB(kb, ks, axis == 1, bA, bB, bC);
            { uint32_t bb[2] = { bA[0], bA[2] }; mma16816(acc[0], a, bb); }
            { uint32_t bb[2] = { bA[1], bA[3] }; mma16816(acc[1], a, bb); }
            { uint32_t bb[2] = { bB[0], bB[2] }; mma16816(acc[2], a, bb); }
            { uint32_t bb[2] = { bB[1], bB[3] }; mma16816(acc[3], a, bb); }
            { uint32_t bb[2] = { bC[0], bC[1] }; mma16816(acc[4], a, bb); }
        }
    }
    __syncthreads();
    if (tid < 160) {
        float inv = 1.f / fmaxf(sqrtf(nss), 1e-12f);
        if (tid < 80) rq[tid] = inv; else rk[tid - 80] = inv;
    }
    __syncthreads();
    {
        int row  = mt*16 + (lane >> 2);
        int colb = nh*40 + (lane & 3) * 2;
        float r0 = rq[row], r1 = rq[row + 8];
        #pragma unroll
        for (int j = 0; j < 5; j++) {
            int col = colb + j*8;
            float k0 = rk[col], k1 = rk[col + 1];
            Gm[row*81 + col]       = acc[j][0] * r0 * k0;
            Gm[row*81 + col + 1]   = acc[j][1] * r0 * k1;
            Gm[(row+8)*81 + col]   = acc[j][2] * r1 * k0;
            Gm[(row+8)*81 + col+1] = acc[j][3] * r1 * k1;
        }
    }
    __syncthreads();
    // ================= Phase 2: softmax rows =================
    if (tid < 80) {
        float* row = Gm + tid*81;
        float mx = -3.0e38f;
        for (int m = 0; m < 80; m++) mx = fmaxf(mx, row[m]);
        float s = 0.f;
        for (int m = 0; m < 80; m++) { float e = expf(row[m] - mx); row[m] = e; s += e; }
        float is = 1.f / s;
        for (int m = 0; m < 80; m++) row[m] *= is;
    }
    __syncthreads();
    #pragma unroll
    for (int it = 0; it < 10; it++) {
        int p = tid + it * 320;
        int n = p / 40, mp = p - n * 40;
        *(uint32_t*)(sm2 + OFF_PS + n*FPB + 4*mp) = pack2(Gm[n*81 + 2*mp], Gm[n*81 + 2*mp + 1]);
    }
    __syncthreads();
    uint32_t aP[5][4];
    #pragma unroll
    for (int ks = 0; ks < 5; ks++) {
        int row = mt*16 + (lane & 15);
        ldm_x4(aP[ks][0], aP[ks][1], aP[ks][2], aP[ks][3],
               ps32 + row*FPB + ks*32 + ((lane >> 4) << 4));
    }

    // ================= Phase 3: out = P@V + q*rq =================
    fill(0, 0);
    for (int c = 0; c < CPH; c++) {
        const int b = c & 1;
        CPWAIT0();
        __syncthreads();
        if (c < CPH-1) fill(c + 1, b ^ 1);
        const uint32_t qb = tq32 + b * 14080;
        const uint32_t kb = tk32 + b * 14080;
        const char* qsm = sm2 + b * 14080;
        float o[5][4];
        #pragma unroll
        for (int j = 0; j < 5; j++)
            #pragma unroll
            for (int t = 0; t < 4; t++) o[j][t] = 0.f;
        #pragma unroll
        for (int ks = 0; ks < 5; ks++) {
            uint32_t bA[4], bB[4], bC[2];
            // axis0: V operand = (n=w, k=h) -> trans; axis1: (n=h, k=w) -> normal
            loadB(kb, ks, axis == 0, bA, bB, bC);
            { uint32_t bb[2] = { bA[0], bA[2] }; mma16816(o[0], aP[ks], bb); }
            { uint32_t bb[2] = { bA[1], bA[3] }; mma16816(o[1], aP[ks], bb); }
            { uint32_t bb[2] = { bB[0], bB[2] }; mma16816(o[2], aP[ks], bb); }
            { uint32_t bb[2] = { bB[1], bB[3] }; mma16816(o[3], aP[ks], bb); }
            { uint32_t bb[2] = { bC[0], bC[1] }; mma16816(o[4], aP[ks], bb); }
        }
        __nv_bfloat16* ob = outb + c*HW;
        int row  = mt*16 + (lane >> 2);
        int colb = nh*40 + (lane & 3) * 2;
        #pragma unroll
        for (int j = 0; j < 5; j++) {
            int col = colb + j*8;
            #pragma unroll
            for (int half = 0; half < 2; half++) {
                int rr = row + 8*half;
                float rqi = rq[rr];
                float q0, q1;
                if (axis == 0) {
                    __nv_bfloat162 q2 = *(const __nv_bfloat162*)(qsm + rr*FPB + col*2);
                    float2 qf = __bfloat1622float2(q2);
                    q0 = qf.x; q1 = qf.y;
                } else {
                    q0 = __bfloat162float(*(const __nv_bfloat16*)(qsm + col*FPB + rr*2));
                    q1 = __bfloat162float(*(const __nv_bfloat16*)(qsm + (col+1)*FPB + rr*2));
                }
                float v0 = o[j][2*half]     + q0 * rqi;
                float v1 = o[j][2*half + 1] + q1 * rqi;
                if (axis == 0) {
                    *(uint32_t*)(ob + rr*80 + col) = pack2(v0, v1);
                } else {
                    ob[col*80 + rr]       = __float2bfloat16(v0);
                    ob[(col+1)*80 + rr]   = __float2bfloat16(v1);
                }
            }
        }
    }
}

// ---------------- launch -----------------------------------------------------
extern "C" void kernel_launch(void* const* d_in, const int* in_sizes, int n_in,
                              void* d_out, int out_size)
{
    const float* x    = (const float*)d_in[0];
    const float* ln_g = (const float*)d_in[1];
    const float* ln_b = (const float*)d_in[2];
    const float* w_in = (const float*)d_in[3];
    const float* b_in = (const float*)d_in[4];
    const float* w_out= (const float*)d_in[5];
    const float* b_out= (const float*)d_in[6];
    const float* wx7  = (const float*)d_in[7];
    const float* bx7  = (const float*)d_in[8];
    const float* wx11 = (const float*)d_in[9];
    const float* bx11 = (const float*)d_in[10];
    const float* wx21 = (const float*)d_in[11];
    const float* bx21 = (const float*)d_in[12];
    const float* wy7  = (const float*)d_in[13];
    const float* by7  = (const float*)d_in[14];
    const float* wy11 = (const float*)d_in[15];
    const float* by11 = (const float*)d_in[16];
    const float* wy21 = (const float*)d_in[17];
    const float* by21 = (const float*)d_in[18];
    float* out = (float*)d_out;

    float *pA, *pB, *pC, *pD, *pE;
    cudaGetSymbolAddress((void**)&pA, g_A);
    cudaGetSymbolAddress((void**)&pB, g_B);
    cudaGetSymbolAddress((void**)&pC, g_C);
    cudaGetSymbolAddress((void**)&pD, g_D);
    cudaGetSymbolAddress((void**)&pE, g_E);
    __nv_bfloat16* hA = (__nv_bfloat16*)pA;
    __nv_bfloat16* hB = (__nv_bfloat16*)pB;
    __nv_bfloat16* hC = (__nv_bfloat16*)pC;
    __nv_bfloat16* hD = (__nv_bfloat16*)pD;
    __nv_bfloat16* hE = (__nv_bfloat16*)pE;

    cudaFuncSetAttribute(attn_kernel, cudaFuncAttributeMaxDynamicSharedMemorySize, ATTN2_SMEM);
    cudaFuncSetAttribute(gemm_bf,  cudaFuncAttributeMaxDynamicSharedMemorySize, GSMEM_BF);
    cudaFuncSetAttribute(gemm_out, cudaFuncAttributeMaxDynamicSharedMemorySize, GSMEM_OUT);

    // 1) LayerNorm: x -> A (bf16 xn)
    ln_kernel<<<(BB*HW)/256, 256>>>(x, ln_g, ln_b, hA);
    // 2) depthwise (both dirs): A -> B (bf16 sx), C (bf16 sy)
    dw_kernel<<<2*BB*CC, 256>>>(hA, wx7, bx7, wx11, bx11, wx21, bx21,
                                wy7, by7, wy11, by11, wy21, by21, hB, hC);
    // 3) pointwise w_in merged: B->D (fx), C->E (fy)
    dim3 gg(HW/128, CC/128, 2*BB);
    gemm_bf<<<gg, 256, GSMEM_BF>>>(w_in, hB, hC, b_in, hD, hE);
    // 4) cross-axis attention (both axes): (D,E) -> C (bf16 attx), A (bf16 atty)
    attn_kernel<<<2*BB*NHEADS, 320, ATTN2_SMEM>>>(hD, hE, hC, hA);
    // 5) final pointwise: W_out@(C+A) + 2*b_out + x residual
    dim3 go(HW/128, CC/128, BB);
    gemm_out<<<go, 256, GSMEM_OUT>>>(w_out, hC, hA, b_out, x, out);
}